// round 1
// baseline (speedup 1.0000x reference)
#include <cuda_runtime.h>
#include <math.h>

#define WID 256
#define HGT 256
#define HW  65536
#define BAT 2
#define NF  64
#define DG  8
#define CG  8
#define NK  9

// ---------------- scratch (__device__ globals; no allocation) ----------------
__device__ float d_nbr_t[BAT * DG * HW * CG];   // [b][g][p][c8]   33.5 MB
__device__ float d_nbr_warp[BAT * NF * HW];     // NCHW            33.5 MB
__device__ float d_fea[BAT * NF * HW];          // NCHW            33.5 MB
__device__ float d_om[BAT * 216 * HW];          // NCHW            113 MB

// ---------------- packed f32x2 helpers ----------------
__device__ __forceinline__ unsigned long long pack2(float lo, float hi) {
    unsigned long long r;
    asm("mov.b64 %0, {%1, %2};" : "=l"(r) : "f"(lo), "f"(hi));
    return r;
}
__device__ __forceinline__ unsigned long long fma2(unsigned long long a,
                                                   unsigned long long b,
                                                   unsigned long long c) {
    unsigned long long d;
    asm("fma.rn.f32x2 %0, %1, %2, %3;" : "=l"(d) : "l"(a), "l"(b), "l"(c));
    return d;
}
__device__ __forceinline__ void unpack2(unsigned long long v, float& lo, float& hi) {
    asm("mov.b64 {%0, %1}, %2;" : "=f"(lo), "=f"(hi) : "l"(v));
}

// ---------------- kernel 1: bilinear flow warp of nbr ----------------
__global__ void warp_kernel(const float* __restrict__ nbr,
                            const float* __restrict__ flow) {
    int idx = blockIdx.x * blockDim.x + threadIdx.x;   // b*HW + p
    if (idx >= BAT * HW) return;
    int b = idx >> 16;
    int p = idx & 65535;
    int y = p >> 8, x = p & 255;

    float fx = flow[(b * 2 + 0) * HW + p];
    float fy = flow[(b * 2 + 1) * HW + p];
    float px = (float)x + fx;
    float py = (float)y + fy;
    float x0f = floorf(px), y0f = floorf(py);
    int ix0 = (int)x0f, iy0 = (int)y0f;
    float wx = px - x0f, wy = py - y0f;

    bool vx0 = (unsigned)ix0 < WID;
    bool vx1 = (unsigned)(ix0 + 1) < WID;
    bool vy0 = (unsigned)iy0 < HGT;
    bool vy1 = (unsigned)(iy0 + 1) < HGT;

    float w00 = (vy0 && vx0) ? (1.f - wy) * (1.f - wx) : 0.f;
    float w01 = (vy0 && vx1) ? (1.f - wy) * wx : 0.f;
    float w10 = (vy1 && vx0) ? wy * (1.f - wx) : 0.f;
    float w11 = (vy1 && vx1) ? wy * wx : 0.f;

    int cx0 = min(max(ix0, 0), WID - 1);
    int cx1 = min(max(ix0 + 1, 0), WID - 1);
    int cy0 = min(max(iy0, 0), HGT - 1);
    int cy1 = min(max(iy0 + 1, 0), HGT - 1);
    int i00 = cy0 * WID + cx0;
    int i01 = cy0 * WID + cx1;
    int i10 = cy1 * WID + cx0;
    int i11 = cy1 * WID + cx1;

    const float* base = nbr + (size_t)b * NF * HW;
#pragma unroll 4
    for (int c = 0; c < NF; c++) {
        const float* ch = base + c * HW;
        float v = w00 * ch[i00] + w01 * ch[i01] + w10 * ch[i10] + w11 * ch[i11];
        d_nbr_warp[(b * NF + c) * HW + p] = v;
    }
}

// ---------------- kernel 2: transpose nbr to [b][g][p][c8] ----------------
__global__ void transpose_kernel(const float* __restrict__ nbr) {
    int idx = blockIdx.x * blockDim.x + threadIdx.x;   // (b*8+g)*HW + p
    if (idx >= BAT * DG * HW) return;
    int bg = idx >> 16;                // b*8+g
    int p = idx & 65535;
    int b = bg >> 3;
    int g = bg & 7;
    float v[8];
#pragma unroll
    for (int c = 0; c < 8; c++)
        v[c] = nbr[((b * NF + g * 8 + c) * HW) + p];
    float4* dst = (float4*)&d_nbr_t[(size_t)idx * 8];
    dst[0] = make_float4(v[0], v[1], v[2], v[3]);
    dst[1] = make_float4(v[4], v[5], v[6], v[7]);
}

// ---------------- kernel 3: conv1 (128 -> 64, 3x3, relu) ----------------
// block: 256 threads = 16x16 pixels; 16 output channels per block; IC chunks of 8.
__global__ void conv1_kernel(const float* __restrict__ ref,
                             const float* __restrict__ wgt,
                             const float* __restrict__ bias) {
    __shared__ __align__(16) float sIn[8 * 18 * 18];
    __shared__ __align__(16) float sW[8 * 9 * 16];   // [(c*9+kk)*16 + oc]

    int bz = blockIdx.z;
    int b = bz >> 2;
    int oc0 = (bz & 3) * 16;
    int tx = threadIdx.x & 15, ty = threadIdx.x >> 4;
    int gx0 = blockIdx.x * 16, gy0 = blockIdx.y * 16;

    unsigned long long acc[8];
#pragma unroll
    for (int j = 0; j < 8; j++) acc[j] = 0ull;

    for (int c0 = 0; c0 < 128; c0 += 8) {
        __syncthreads();
        // stage input tile (18x18 x 8ch), zero-padded
        for (int i = threadIdx.x; i < 8 * 324; i += 256) {
            int c = i / 324;
            int pos = i - c * 324;
            int iy = pos / 18, ix = pos - iy * 18;
            int gy = gy0 + iy - 1, gx = gx0 + ix - 1;
            float v = 0.f;
            if ((unsigned)gy < HGT && (unsigned)gx < WID) {
                int cc = c0 + c;
                v = (cc < 64) ? d_nbr_warp[(b * 64 + cc) * HW + gy * WID + gx]
                              : ref[(b * 64 + cc - 64) * HW + gy * WID + gx];
            }
            sIn[i] = v;
        }
        // stage weights
        for (int i = threadIdx.x; i < 8 * 9 * 16; i += 256) {
            int oc = i & 15;
            int r = i >> 4;
            int kk = r % 9;
            int c = r / 9;
            sW[i] = wgt[((oc0 + oc) * 128 + c0 + c) * 9 + kk];
        }
        __syncthreads();

#pragma unroll
        for (int c = 0; c < 8; c++) {
#pragma unroll
            for (int kk = 0; kk < 9; kk++) {
                int ky = kk / 3, kx = kk - ky * 3;
                float v = sIn[c * 324 + (ty + ky) * 18 + tx + kx];
                unsigned long long vp = pack2(v, v);
                const unsigned long long* wq =
                    (const unsigned long long*)&sW[(c * 9 + kk) * 16];
#pragma unroll
                for (int j = 0; j < 8; j++) acc[j] = fma2(vp, wq[j], acc[j]);
            }
        }
    }

    int p = (gy0 + ty) * WID + gx0 + tx;
#pragma unroll
    for (int j = 0; j < 8; j++) {
        float lo, hi;
        unpack2(acc[j], lo, hi);
        lo += bias[oc0 + 2 * j];
        hi += bias[oc0 + 2 * j + 1];
        d_fea[(b * 64 + oc0 + 2 * j) * HW + p] = fmaxf(lo, 0.f);
        d_fea[(b * 64 + oc0 + 2 * j + 1) * HW + p] = fmaxf(hi, 0.f);
    }
}

// ---------------- kernel 4: om conv (66 -> 216, 3x3) ----------------
// block: 256 threads = 16x16 pixels; 24 output channels per block; IC chunks of 11.
__global__ void om_kernel(const float* __restrict__ flow,
                          const float* __restrict__ wgt,
                          const float* __restrict__ bias) {
    __shared__ __align__(16) float sIn[11 * 324];
    __shared__ __align__(16) float sW[11 * 9 * 24];   // [(c*9+kk)*24 + oc]

    int bz = blockIdx.z;
    int b = bz / 9;
    int oc0 = (bz - b * 9) * 24;
    int tx = threadIdx.x & 15, ty = threadIdx.x >> 4;
    int gx0 = blockIdx.x * 16, gy0 = blockIdx.y * 16;

    unsigned long long acc[12];
#pragma unroll
    for (int j = 0; j < 12; j++) acc[j] = 0ull;

    for (int c0 = 0; c0 < 66; c0 += 11) {
        __syncthreads();
        for (int i = threadIdx.x; i < 11 * 324; i += 256) {
            int c = i / 324;
            int pos = i - c * 324;
            int iy = pos / 18, ix = pos - iy * 18;
            int gy = gy0 + iy - 1, gx = gx0 + ix - 1;
            float v = 0.f;
            if ((unsigned)gy < HGT && (unsigned)gx < WID) {
                int cc = c0 + c;
                v = (cc < 64) ? d_fea[(b * 64 + cc) * HW + gy * WID + gx]
                              : flow[(b * 2 + cc - 64) * HW + gy * WID + gx];
            }
            sIn[i] = v;
        }
        for (int i = threadIdx.x; i < 11 * 9 * 24; i += 256) {
            int oc = i % 24;
            int r = i / 24;
            int kk = r % 9;
            int c = r / 9;
            sW[i] = wgt[((oc0 + oc) * 66 + c0 + c) * 9 + kk];
        }
        __syncthreads();

        for (int c = 0; c < 11; c++) {
#pragma unroll
            for (int kk = 0; kk < 9; kk++) {
                int ky = kk / 3, kx = kk - ky * 3;
                float v = sIn[c * 324 + (ty + ky) * 18 + tx + kx];
                unsigned long long vp = pack2(v, v);
                const unsigned long long* wq =
                    (const unsigned long long*)&sW[(c * 9 + kk) * 24];
#pragma unroll
                for (int j = 0; j < 12; j++) acc[j] = fma2(vp, wq[j], acc[j]);
            }
        }
    }

    int p = (gy0 + ty) * WID + gx0 + tx;
#pragma unroll
    for (int j = 0; j < 12; j++) {
        float lo, hi;
        unpack2(acc[j], lo, hi);
        d_om[(b * 216 + oc0 + 2 * j) * HW + p] = lo + bias[oc0 + 2 * j];
        d_om[(b * 216 + oc0 + 2 * j + 1) * HW + p] = hi + bias[oc0 + 2 * j + 1];
    }
}

// ---------------- kernel 5: deformable conv ----------------
// block: 256 threads = 16x16 pixels; 32 output channels per block (2 halves).
// Per-group weight slice [k][c][o32] staged in smem; bilinear taps read the
// channel-last transposed nbr via two float4 loads.
__global__ void dcn_kernel(const float* __restrict__ flow,
                           const float* __restrict__ dcnw,
                           const float* __restrict__ dcnb,
                           float* __restrict__ out) {
    __shared__ __align__(16) float sW[9 * 8 * 32];   // [(k*8+c)*32 + o]

    int bz = blockIdx.z;
    int b = bz >> 1;
    int o0 = (bz & 1) * 32;
    int tx = threadIdx.x & 15, ty = threadIdx.x >> 4;
    int x = blockIdx.x * 16 + tx;
    int y = blockIdx.y * 16 + ty;
    int p = y * WID + x;

    float fx = flow[(b * 2 + 0) * HW + p];
    float fy = flow[(b * 2 + 1) * HW + p];

    unsigned long long acc[16];
#pragma unroll
    for (int j = 0; j < 16; j++) acc[j] = 0ull;

    for (int g = 0; g < 8; g++) {
        __syncthreads();
        for (int i = threadIdx.x; i < 2304; i += 256) {
            int o = i & 31;
            int r = i >> 5;
            int c = r & 7;
            int k = r >> 3;
            sW[i] = dcnw[((o0 + o) * 64 + g * 8 + c) * 9 + k];
        }
        __syncthreads();

        const float* gbase = d_nbr_t + (size_t)(b * 8 + g) * HW * 8;

#pragma unroll 1
        for (int k = 0; k < 9; k++) {
            int ky = k / 3, kx = k - ky * 3;
            int ch = g * 9 + k;
            float dy = d_om[(b * 216 + ch * 2) * HW + p] + fy;
            float dx = d_om[(b * 216 + ch * 2 + 1) * HW + p] + fx;
            float mraw = d_om[(b * 216 + 144 + ch) * HW + p];
            float mval = 1.f / (1.f + expf(-mraw));

            float spy = (float)(y - 1 + ky) + dy;
            float spx = (float)(x - 1 + kx) + dx;
            float y0f = floorf(spy), x0f = floorf(spx);
            int iy0 = (int)y0f, ix0 = (int)x0f;
            float wy = spy - y0f, wx = spx - x0f;

            float v[8];
#pragma unroll
            for (int c = 0; c < 8; c++) v[c] = 0.f;

            {
                float wts[4] = {(1.f - wy) * (1.f - wx), (1.f - wy) * wx,
                                wy * (1.f - wx), wy * wx};
                int ys[4] = {iy0, iy0, iy0 + 1, iy0 + 1};
                int xs[4] = {ix0, ix0 + 1, ix0, ix0 + 1};
#pragma unroll
                for (int t = 0; t < 4; t++) {
                    int yi = ys[t], xi = xs[t];
                    if ((unsigned)yi < HGT && (unsigned)xi < WID) {
                        const float4* q =
                            (const float4*)(gbase + (size_t)(yi * WID + xi) * 8);
                        float4 a = q[0];
                        float4 bb = q[1];
                        float wt = wts[t];
                        v[0] += wt * a.x;  v[1] += wt * a.y;
                        v[2] += wt * a.z;  v[3] += wt * a.w;
                        v[4] += wt * bb.x; v[5] += wt * bb.y;
                        v[6] += wt * bb.z; v[7] += wt * bb.w;
                    }
                }
            }

#pragma unroll
            for (int c = 0; c < 8; c++) {
                float vm = v[c] * mval;
                unsigned long long vp = pack2(vm, vm);
                const unsigned long long* wq =
                    (const unsigned long long*)&sW[(k * 8 + c) * 32];
#pragma unroll
                for (int j = 0; j < 16; j++) acc[j] = fma2(vp, wq[j], acc[j]);
            }
        }
    }

#pragma unroll
    for (int j = 0; j < 16; j++) {
        float lo, hi;
        unpack2(acc[j], lo, hi);
        out[(b * 64 + o0 + 2 * j) * HW + p] = lo + dcnb[o0 + 2 * j];
        out[(b * 64 + o0 + 2 * j + 1) * HW + p] = hi + dcnb[o0 + 2 * j + 1];
    }
}

// ---------------- launch ----------------
extern "C" void kernel_launch(void* const* d_in, const int* in_sizes, int n_in,
                              void* d_out, int out_size) {
    const float* nbr = (const float*)d_in[0];
    const float* ref = (const float*)d_in[1];
    const float* flow = (const float*)d_in[2];
    const float* conv1_w = (const float*)d_in[3];
    const float* conv1_b = (const float*)d_in[4];
    const float* om_w = (const float*)d_in[5];
    const float* om_b = (const float*)d_in[6];
    const float* dcn_w = (const float*)d_in[7];
    const float* dcn_b = (const float*)d_in[8];
    float* out = (float*)d_out;

    // 1. flow warp of nbr (independent of 2)
    warp_kernel<<<(BAT * HW + 255) / 256, 256>>>(nbr, flow);

    // 2. transpose nbr for DCN sampling
    transpose_kernel<<<(BAT * DG * HW + 255) / 256, 256>>>(nbr);

    // 3. conv1: concat(warp, ref) -> fea
    conv1_kernel<<<dim3(16, 16, BAT * 4), 256>>>(ref, conv1_w, conv1_b);

    // 4. om conv: concat(fea, flow) -> om (216 ch)
    om_kernel<<<dim3(16, 16, BAT * 9), 256>>>(flow, om_w, om_b);

    // 5. deformable conv -> out
    dcn_kernel<<<dim3(16, 16, BAT * 2), 256>>>(flow, dcn_w, dcn_b, out);
}

// round 2
// speedup vs baseline: 1.0833x; 1.0833x over previous
#include <cuda_runtime.h>
#include <math.h>

#define WID 256
#define HGT 256
#define HW  65536
#define BAT 2
#define NF  64
#define DG  8
#define CG  8
#define NK  9

// ---------------- scratch (__device__ globals; no allocation) ----------------
__device__ float d_nbr_t[BAT * DG * HW * CG];   // [b][g][p][c8]   33.5 MB
__device__ float d_nbr_warp[BAT * NF * HW];     // NCHW            33.5 MB
__device__ float d_fea[BAT * NF * HW];          // NCHW            33.5 MB
__device__ float d_om[BAT * 216 * HW];          // NCHW (offsets pre-flow-added, masks pre-sigmoided)

// ---------------- packed f32x2 helpers ----------------
__device__ __forceinline__ unsigned long long pack2(float lo, float hi) {
    unsigned long long r;
    asm("mov.b64 %0, {%1, %2};" : "=l"(r) : "f"(lo), "f"(hi));
    return r;
}
__device__ __forceinline__ unsigned long long fma2(unsigned long long a,
                                                   unsigned long long b,
                                                   unsigned long long c) {
    unsigned long long d;
    asm("fma.rn.f32x2 %0, %1, %2, %3;" : "=l"(d) : "l"(a), "l"(b), "l"(c));
    return d;
}
__device__ __forceinline__ void unpack2(unsigned long long v, float& lo, float& hi) {
    asm("mov.b64 {%0, %1}, %2;" : "=f"(lo), "=f"(hi) : "l"(v));
}

// ---------------- kernel 1: bilinear flow warp of nbr ----------------
__global__ void warp_kernel(const float* __restrict__ nbr,
                            const float* __restrict__ flow) {
    int idx = blockIdx.x * blockDim.x + threadIdx.x;   // b*HW + p
    if (idx >= BAT * HW) return;
    int b = idx >> 16;
    int p = idx & 65535;
    int y = p >> 8, x = p & 255;

    float fx = flow[(b * 2 + 0) * HW + p];
    float fy = flow[(b * 2 + 1) * HW + p];
    float px = (float)x + fx;
    float py = (float)y + fy;
    float x0f = floorf(px), y0f = floorf(py);
    int ix0 = (int)x0f, iy0 = (int)y0f;
    float wx = px - x0f, wy = py - y0f;

    bool vx0 = (unsigned)ix0 < WID;
    bool vx1 = (unsigned)(ix0 + 1) < WID;
    bool vy0 = (unsigned)iy0 < HGT;
    bool vy1 = (unsigned)(iy0 + 1) < HGT;

    float w00 = (vy0 && vx0) ? (1.f - wy) * (1.f - wx) : 0.f;
    float w01 = (vy0 && vx1) ? (1.f - wy) * wx : 0.f;
    float w10 = (vy1 && vx0) ? wy * (1.f - wx) : 0.f;
    float w11 = (vy1 && vx1) ? wy * wx : 0.f;

    int cx0 = min(max(ix0, 0), WID - 1);
    int cx1 = min(max(ix0 + 1, 0), WID - 1);
    int cy0 = min(max(iy0, 0), HGT - 1);
    int cy1 = min(max(iy0 + 1, 0), HGT - 1);
    int i00 = cy0 * WID + cx0;
    int i01 = cy0 * WID + cx1;
    int i10 = cy1 * WID + cx0;
    int i11 = cy1 * WID + cx1;

    const float* base = nbr + (size_t)b * NF * HW;
#pragma unroll 4
    for (int c = 0; c < NF; c++) {
        const float* ch = base + c * HW;
        float v = w00 * ch[i00] + w01 * ch[i01] + w10 * ch[i10] + w11 * ch[i11];
        d_nbr_warp[(b * NF + c) * HW + p] = v;
    }
}

// ---------------- kernel 2: transpose nbr to [b][g][p][c8] ----------------
__global__ void transpose_kernel(const float* __restrict__ nbr) {
    int idx = blockIdx.x * blockDim.x + threadIdx.x;   // (b*8+g)*HW + p
    if (idx >= BAT * DG * HW) return;
    int bg = idx >> 16;                // b*8+g
    int p = idx & 65535;
    int b = bg >> 3;
    int g = bg & 7;
    float v[8];
#pragma unroll
    for (int c = 0; c < 8; c++)
        v[c] = nbr[((b * NF + g * 8 + c) * HW) + p];
    float4* dst = (float4*)&d_nbr_t[(size_t)idx * 8];
    dst[0] = make_float4(v[0], v[1], v[2], v[3]);
    dst[1] = make_float4(v[4], v[5], v[6], v[7]);
}

// ---------------- kernel 3: conv1 (128 -> 64, 3x3, relu) ----------------
// block: 256 threads; 32x32 pixel tile, each thread 2x2 pixels; 16 oc/block.
__global__ __launch_bounds__(256, 2)
void conv1_kernel(const float* __restrict__ ref,
                  const float* __restrict__ wgt,
                  const float* __restrict__ bias) {
    __shared__ __align__(16) float sIn[8 * 34 * 34];   // 37 KB
    __shared__ __align__(16) float sW[8 * 9 * 16];     // [(c*9+kk)*16 + oc]

    int bz = blockIdx.z;
    int b = bz >> 2;
    int oc0 = (bz & 3) * 16;
    int tx = threadIdx.x & 15, ty = threadIdx.x >> 4;
    int gx0 = blockIdx.x * 32, gy0 = blockIdx.y * 32;

    unsigned long long acc[4][8];
#pragma unroll
    for (int q = 0; q < 4; q++)
#pragma unroll
        for (int j = 0; j < 8; j++) acc[q][j] = 0ull;

    for (int c0 = 0; c0 < 128; c0 += 8) {
        __syncthreads();
        // stage input tile (34x34 x 8ch), zero-padded
        for (int i = threadIdx.x; i < 8 * 1156; i += 256) {
            int c = i / 1156;
            int pos = i - c * 1156;
            int iy = pos / 34, ix = pos - iy * 34;
            int gy = gy0 + iy - 1, gx = gx0 + ix - 1;
            float v = 0.f;
            if ((unsigned)gy < HGT && (unsigned)gx < WID) {
                int cc = c0 + c;
                v = (cc < 64) ? d_nbr_warp[(b * 64 + cc) * HW + gy * WID + gx]
                              : ref[(b * 64 + cc - 64) * HW + gy * WID + gx];
            }
            sIn[i] = v;
        }
        // stage weights
        for (int i = threadIdx.x; i < 8 * 9 * 16; i += 256) {
            int oc = i & 15;
            int r = i >> 4;
            int kk = r % 9;
            int c = r / 9;
            sW[i] = wgt[((oc0 + oc) * 128 + c0 + c) * 9 + kk];
        }
        __syncthreads();

#pragma unroll
        for (int c = 0; c < 8; c++) {
            const float* in0 = &sIn[c * 1156 + ty * 34 + tx];
#pragma unroll
            for (int kk = 0; kk < 9; kk++) {
                int ky = kk / 3, kx = kk - ky * 3;
                const unsigned long long* wq =
                    (const unsigned long long*)&sW[(c * 9 + kk) * 16];
                unsigned long long w[8];
#pragma unroll
                for (int j = 0; j < 8; j++) w[j] = wq[j];
                const float* ip = in0 + ky * 34 + kx;
                float v0 = ip[0];
                float v1 = ip[16];
                float v2 = ip[16 * 34];
                float v3 = ip[16 * 34 + 16];
                unsigned long long vp0 = pack2(v0, v0);
                unsigned long long vp1 = pack2(v1, v1);
                unsigned long long vp2 = pack2(v2, v2);
                unsigned long long vp3 = pack2(v3, v3);
#pragma unroll
                for (int j = 0; j < 8; j++) {
                    acc[0][j] = fma2(vp0, w[j], acc[0][j]);
                    acc[1][j] = fma2(vp1, w[j], acc[1][j]);
                    acc[2][j] = fma2(vp2, w[j], acc[2][j]);
                    acc[3][j] = fma2(vp3, w[j], acc[3][j]);
                }
            }
        }
    }

#pragma unroll
    for (int q = 0; q < 4; q++) {
        int yy = gy0 + ty + (q >> 1) * 16;
        int xx = gx0 + tx + (q & 1) * 16;
        int p = yy * WID + xx;
#pragma unroll
        for (int j = 0; j < 8; j++) {
            float lo, hi;
            unpack2(acc[q][j], lo, hi);
            lo += bias[oc0 + 2 * j];
            hi += bias[oc0 + 2 * j + 1];
            d_fea[(b * 64 + oc0 + 2 * j) * HW + p] = fmaxf(lo, 0.f);
            d_fea[(b * 64 + oc0 + 2 * j + 1) * HW + p] = fmaxf(hi, 0.f);
        }
    }
}

// ---------------- kernel 4: om conv (66 -> 216, 3x3) + fused epilogue --------
// block: 256 threads; 32x32 tile, each thread 2x2 pixels; 12 oc/block (18 slices).
// Epilogue: channels < 144 (offsets) get flow added (even->fy, odd->fx);
// channels >= 144 (masks) get sigmoid. 144 = 12*12 -> block-uniform branch.
__global__ __launch_bounds__(256, 2)
void om_kernel(const float* __restrict__ flow,
               const float* __restrict__ wgt,
               const float* __restrict__ bias) {
    __shared__ __align__(16) float sIn[6 * 34 * 34];   // 27.7 KB
    __shared__ __align__(16) float sW[6 * 9 * 12];     // [(c*9+kk)*12 + oc]

    int bz = blockIdx.z;
    int b = bz / 18;
    int oc0 = (bz - b * 18) * 12;
    int tx = threadIdx.x & 15, ty = threadIdx.x >> 4;
    int gx0 = blockIdx.x * 32, gy0 = blockIdx.y * 32;

    unsigned long long acc[4][6];
#pragma unroll
    for (int q = 0; q < 4; q++)
#pragma unroll
        for (int j = 0; j < 6; j++) acc[q][j] = 0ull;

    for (int c0 = 0; c0 < 66; c0 += 6) {
        __syncthreads();
        for (int i = threadIdx.x; i < 6 * 1156; i += 256) {
            int c = i / 1156;
            int pos = i - c * 1156;
            int iy = pos / 34, ix = pos - iy * 34;
            int gy = gy0 + iy - 1, gx = gx0 + ix - 1;
            float v = 0.f;
            if ((unsigned)gy < HGT && (unsigned)gx < WID) {
                int cc = c0 + c;
                v = (cc < 64) ? d_fea[(b * 64 + cc) * HW + gy * WID + gx]
                              : flow[(b * 2 + cc - 64) * HW + gy * WID + gx];
            }
            sIn[i] = v;
        }
        for (int i = threadIdx.x; i < 6 * 9 * 12; i += 256) {
            int oc = i % 12;
            int r = i / 12;
            int kk = r % 9;
            int c = r / 9;
            sW[i] = wgt[((oc0 + oc) * 66 + c0 + c) * 9 + kk];
        }
        __syncthreads();

#pragma unroll
        for (int c = 0; c < 6; c++) {
            const float* in0 = &sIn[c * 1156 + ty * 34 + tx];
#pragma unroll
            for (int kk = 0; kk < 9; kk++) {
                int ky = kk / 3, kx = kk - ky * 3;
                const unsigned long long* wq =
                    (const unsigned long long*)&sW[(c * 9 + kk) * 12];
                unsigned long long w[6];
#pragma unroll
                for (int j = 0; j < 6; j++) w[j] = wq[j];
                const float* ip = in0 + ky * 34 + kx;
                float v0 = ip[0];
                float v1 = ip[16];
                float v2 = ip[16 * 34];
                float v3 = ip[16 * 34 + 16];
                unsigned long long vp0 = pack2(v0, v0);
                unsigned long long vp1 = pack2(v1, v1);
                unsigned long long vp2 = pack2(v2, v2);
                unsigned long long vp3 = pack2(v3, v3);
#pragma unroll
                for (int j = 0; j < 6; j++) {
                    acc[0][j] = fma2(vp0, w[j], acc[0][j]);
                    acc[1][j] = fma2(vp1, w[j], acc[1][j]);
                    acc[2][j] = fma2(vp2, w[j], acc[2][j]);
                    acc[3][j] = fma2(vp3, w[j], acc[3][j]);
                }
            }
        }
    }

    bool is_mask = (oc0 >= 144);
#pragma unroll
    for (int q = 0; q < 4; q++) {
        int yy = gy0 + ty + (q >> 1) * 16;
        int xx = gx0 + tx + (q & 1) * 16;
        int p = yy * WID + xx;
        float fy = 0.f, fx = 0.f;
        if (!is_mask) {
            fx = flow[(b * 2 + 0) * HW + p];
            fy = flow[(b * 2 + 1) * HW + p];
        }
#pragma unroll
        for (int j = 0; j < 6; j++) {
            float lo, hi;
            unpack2(acc[q][j], lo, hi);
            lo += bias[oc0 + 2 * j];
            hi += bias[oc0 + 2 * j + 1];
            if (is_mask) {
                lo = 1.f / (1.f + expf(-lo));
                hi = 1.f / (1.f + expf(-hi));
            } else {
                lo += fy;    // even offset channel -> +flow[1]
                hi += fx;    // odd offset channel  -> +flow[0]
            }
            d_om[(b * 216 + oc0 + 2 * j) * HW + p] = lo;
            d_om[(b * 216 + oc0 + 2 * j + 1) * HW + p] = hi;
        }
    }
}

// ---------------- kernel 5: deformable conv ----------------
// block: 256 threads; 32x16 pixel tile, each thread 2 pixels (x, x+16);
// 32 oc/block. Offsets/masks are pre-processed by om_kernel.
__device__ __forceinline__ void dcn_gather(const float* __restrict__ gbase,
                                           int x, int y, int ky, int kx,
                                           float dy, float dx, float m,
                                           float* vm) {
    float spy = (float)(y - 1 + ky) + dy;
    float spx = (float)(x - 1 + kx) + dx;
    float y0f = floorf(spy), x0f = floorf(spx);
    int iy0 = (int)y0f, ix0 = (int)x0f;
    float wy = spy - y0f, wx = spx - x0f;

    float v[8];
#pragma unroll
    for (int c = 0; c < 8; c++) v[c] = 0.f;

    float wts[4] = {(1.f - wy) * (1.f - wx), (1.f - wy) * wx,
                    wy * (1.f - wx), wy * wx};
    int ys[4] = {iy0, iy0, iy0 + 1, iy0 + 1};
    int xs[4] = {ix0, ix0 + 1, ix0, ix0 + 1};
#pragma unroll
    for (int t = 0; t < 4; t++) {
        int yi = ys[t], xi = xs[t];
        if ((unsigned)yi < HGT && (unsigned)xi < WID) {
            const float4* q = (const float4*)(gbase + (size_t)(yi * WID + xi) * 8);
            float4 a = q[0];
            float4 bb = q[1];
            float wt = wts[t];
            v[0] += wt * a.x;  v[1] += wt * a.y;
            v[2] += wt * a.z;  v[3] += wt * a.w;
            v[4] += wt * bb.x; v[5] += wt * bb.y;
            v[6] += wt * bb.z; v[7] += wt * bb.w;
        }
    }
#pragma unroll
    for (int c = 0; c < 8; c++) vm[c] = v[c] * m;
}

__global__ __launch_bounds__(256, 2)
void dcn_kernel(const float* __restrict__ dcnw,
                const float* __restrict__ dcnb,
                float* __restrict__ out) {
    __shared__ __align__(16) float sW[9 * 8 * 32];   // [(k*8+c)*32 + o]

    int bz = blockIdx.z;
    int b = bz >> 1;
    int o0 = (bz & 1) * 32;
    int tx = threadIdx.x & 15, ty = threadIdx.x >> 4;
    int x0 = blockIdx.x * 32 + tx;
    int y = blockIdx.y * 16 + ty;
    int p0 = y * WID + x0;
    int p1 = p0 + 16;

    unsigned long long acc[2][16];
#pragma unroll
    for (int s = 0; s < 2; s++)
#pragma unroll
        for (int j = 0; j < 16; j++) acc[s][j] = 0ull;

    for (int g = 0; g < 8; g++) {
        __syncthreads();
        for (int i = threadIdx.x; i < 2304; i += 256) {
            int o = i & 31;
            int r = i >> 5;
            int c = r & 7;
            int k = r >> 3;
            sW[i] = dcnw[((o0 + o) * 64 + g * 8 + c) * 9 + k];
        }
        __syncthreads();

        const float* gbase = d_nbr_t + (size_t)(b * 8 + g) * HW * 8;
        const float* omb = d_om + (size_t)b * 216 * HW;

#pragma unroll 1
        for (int k = 0; k < 9; k++) {
            int ky = k / 3, kx = k - ky * 3;
            int ch = g * 9 + k;

            float vm0[8], vm1[8];
            {
                float dy = omb[(ch * 2) * HW + p0];
                float dx = omb[(ch * 2 + 1) * HW + p0];
                float m = omb[(144 + ch) * HW + p0];
                dcn_gather(gbase, x0, y, ky, kx, dy, dx, m, vm0);
            }
            {
                float dy = omb[(ch * 2) * HW + p1];
                float dx = omb[(ch * 2 + 1) * HW + p1];
                float m = omb[(144 + ch) * HW + p1];
                dcn_gather(gbase, x0 + 16, y, ky, kx, dy, dx, m, vm1);
            }

#pragma unroll
            for (int c = 0; c < 8; c++) {
                const unsigned long long* wq =
                    (const unsigned long long*)&sW[(k * 8 + c) * 32];
                unsigned long long vp0 = pack2(vm0[c], vm0[c]);
                unsigned long long vp1 = pack2(vm1[c], vm1[c]);
#pragma unroll
                for (int half = 0; half < 2; half++) {
                    unsigned long long w[8];
#pragma unroll
                    for (int j = 0; j < 8; j++) w[j] = wq[half * 8 + j];
#pragma unroll
                    for (int j = 0; j < 8; j++) {
                        acc[0][half * 8 + j] = fma2(vp0, w[j], acc[0][half * 8 + j]);
                        acc[1][half * 8 + j] = fma2(vp1, w[j], acc[1][half * 8 + j]);
                    }
                }
            }
        }
    }

#pragma unroll
    for (int s = 0; s < 2; s++) {
        int p = (s == 0) ? p0 : p1;
#pragma unroll
        for (int j = 0; j < 16; j++) {
            float lo, hi;
            unpack2(acc[s][j], lo, hi);
            out[(b * 64 + o0 + 2 * j) * HW + p] = lo + dcnb[o0 + 2 * j];
            out[(b * 64 + o0 + 2 * j + 1) * HW + p] = hi + dcnb[o0 + 2 * j + 1];
        }
    }
}

// ---------------- launch ----------------
extern "C" void kernel_launch(void* const* d_in, const int* in_sizes, int n_in,
                              void* d_out, int out_size) {
    const float* nbr = (const float*)d_in[0];
    const float* ref = (const float*)d_in[1];
    const float* flow = (const float*)d_in[2];
    const float* conv1_w = (const float*)d_in[3];
    const float* conv1_b = (const float*)d_in[4];
    const float* om_w = (const float*)d_in[5];
    const float* om_b = (const float*)d_in[6];
    const float* dcn_w = (const float*)d_in[7];
    const float* dcn_b = (const float*)d_in[8];
    float* out = (float*)d_out;

    warp_kernel<<<(BAT * HW + 255) / 256, 256>>>(nbr, flow);
    transpose_kernel<<<(BAT * DG * HW + 255) / 256, 256>>>(nbr);
    conv1_kernel<<<dim3(8, 8, BAT * 4), 256>>>(ref, conv1_w, conv1_b);
    om_kernel<<<dim3(8, 8, BAT * 18), 256>>>(flow, om_w, om_b);
    dcn_kernel<<<dim3(8, 16, BAT * 2), 256>>>(dcn_w, dcn_b, out);
}

// round 4
// speedup vs baseline: 1.4272x; 1.3174x over previous
#include <cuda_runtime.h>
#include <stdint.h>
#include <math.h>

#define WID 256
#define HGT 256
#define HW  65536
#define BAT 2
#define NF  64
#define DG  8
#define CG  8
#define NK  9

// ---------------- scratch (__device__ globals; no allocation) ----------------
__device__ float d_nbr_t[BAT * DG * HW * CG];   // [b][g][p][c8]
__device__ float d_nbr_warp[BAT * NF * HW];     // NCHW
__device__ float d_fea[BAT * NF * HW];          // NCHW
__device__ float d_om[BAT * 216 * HW];          // NCHW (offsets +flow, masks sigmoided)

// ---------------- packed f32x2 helpers ----------------
__device__ __forceinline__ unsigned long long pack2(float lo, float hi) {
    unsigned long long r;
    asm("mov.b64 %0, {%1, %2};" : "=l"(r) : "f"(lo), "f"(hi));
    return r;
}
__device__ __forceinline__ unsigned long long fma2(unsigned long long a,
                                                   unsigned long long b,
                                                   unsigned long long c) {
    unsigned long long d;
    asm("fma.rn.f32x2 %0, %1, %2, %3;" : "=l"(d) : "l"(a), "l"(b), "l"(c));
    return d;
}
__device__ __forceinline__ void unpack2(unsigned long long v, float& lo, float& hi) {
    asm("mov.b64 {%0, %1}, %2;" : "=f"(lo), "=f"(hi) : "l"(v));
}

// ---------------- cp.async helpers ----------------
__device__ __forceinline__ void cpa4(uint32_t dst, const float* src, bool ok) {
    int sz = ok ? 4 : 0;
    asm volatile("cp.async.ca.shared.global [%0], [%1], 4, %2;"
                 :: "r"(dst), "l"(src), "r"(sz) : "memory");
}
__device__ __forceinline__ void cpa_commit() {
    asm volatile("cp.async.commit_group;" ::: "memory");
}
__device__ __forceinline__ void cpa_wait0() {
    asm volatile("cp.async.wait_group 0;" ::: "memory");
}

// ---------------- kernel 1: bilinear flow warp of nbr ----------------
__global__ void warp_kernel(const float* __restrict__ nbr,
                            const float* __restrict__ flow) {
    int idx = blockIdx.x * blockDim.x + threadIdx.x;   // b*HW + p
    if (idx >= BAT * HW) return;
    int b = idx >> 16;
    int p = idx & 65535;
    int y = p >> 8, x = p & 255;

    float fx = flow[(b * 2 + 0) * HW + p];
    float fy = flow[(b * 2 + 1) * HW + p];
    float px = (float)x + fx;
    float py = (float)y + fy;
    float x0f = floorf(px), y0f = floorf(py);
    int ix0 = (int)x0f, iy0 = (int)y0f;
    float wx = px - x0f, wy = py - y0f;

    bool vx0 = (unsigned)ix0 < WID;
    bool vx1 = (unsigned)(ix0 + 1) < WID;
    bool vy0 = (unsigned)iy0 < HGT;
    bool vy1 = (unsigned)(iy0 + 1) < HGT;

    float w00 = (vy0 && vx0) ? (1.f - wy) * (1.f - wx) : 0.f;
    float w01 = (vy0 && vx1) ? (1.f - wy) * wx : 0.f;
    float w10 = (vy1 && vx0) ? wy * (1.f - wx) : 0.f;
    float w11 = (vy1 && vx1) ? wy * wx : 0.f;

    int cx0 = min(max(ix0, 0), WID - 1);
    int cx1 = min(max(ix0 + 1, 0), WID - 1);
    int cy0 = min(max(iy0, 0), HGT - 1);
    int cy1 = min(max(iy0 + 1, 0), HGT - 1);
    int i00 = cy0 * WID + cx0;
    int i01 = cy0 * WID + cx1;
    int i10 = cy1 * WID + cx0;
    int i11 = cy1 * WID + cx1;

    const float* base = nbr + (size_t)b * NF * HW;
#pragma unroll 4
    for (int c = 0; c < NF; c++) {
        const float* ch = base + c * HW;
        float v = w00 * ch[i00] + w01 * ch[i01] + w10 * ch[i10] + w11 * ch[i11];
        d_nbr_warp[(b * NF + c) * HW + p] = v;
    }
}

// ---------------- kernel 2: transpose nbr to [b][g][p][c8] ----------------
__global__ void transpose_kernel(const float* __restrict__ nbr) {
    int idx = blockIdx.x * blockDim.x + threadIdx.x;   // (b*8+g)*HW + p
    if (idx >= BAT * DG * HW) return;
    int bg = idx >> 16;                // b*8+g
    int p = idx & 65535;
    int b = bg >> 3;
    int g = bg & 7;
    float v[8];
#pragma unroll
    for (int c = 0; c < 8; c++)
        v[c] = nbr[((b * NF + g * 8 + c) * HW) + p];
    float4* dst = (float4*)&d_nbr_t[(size_t)idx * 8];
    dst[0] = make_float4(v[0], v[1], v[2], v[3]);
    dst[1] = make_float4(v[4], v[5], v[6], v[7]);
}

// ---------------- kernel 3: conv1 (128 -> 64, 3x3, relu) ----------------
// 256 threads; 32x32 tile, 2x2 px/thread; 16 oc/block; 8-ch chunks,
// cp.async double-buffered staging.
__global__ __launch_bounds__(256, 2)
void conv1_kernel(const float* __restrict__ ref,
                  const float* __restrict__ wgt,
                  const float* __restrict__ bias) {
    __shared__ __align__(16) float sIn[2][8 * 1156];   // 74 KB
    __shared__ __align__(16) float sW[2][8 * 9 * 16];  // [(c*9+kk)*16 + oc]

    int bz = blockIdx.z;
    int b = bz >> 2;
    int oc0 = (bz & 3) * 16;
    int tx = threadIdx.x & 15, ty = threadIdx.x >> 4;
    int gx0 = blockIdx.x * 32, gy0 = blockIdx.y * 32;

    unsigned long long acc[4][8];
#pragma unroll
    for (int q = 0; q < 4; q++)
#pragma unroll
        for (int j = 0; j < 8; j++) acc[q][j] = 0ull;

    // staging lambda (c0 = chunk base channel, buf index)
    auto stage = [&](int c0, int buf) {
        uint32_t sin_b = (uint32_t)__cvta_generic_to_shared(&sIn[buf][0]);
        uint32_t sw_b = (uint32_t)__cvta_generic_to_shared(&sW[buf][0]);
        for (int i = threadIdx.x; i < 8 * 1156; i += 256) {
            int c = i / 1156;
            int pos = i - c * 1156;
            int iy = pos / 34, ix = pos - iy * 34;
            int gy = gy0 + iy - 1, gx = gx0 + ix - 1;
            bool ok = ((unsigned)gy < HGT) && ((unsigned)gx < WID);
            int cc = c0 + c;
            const float* src;
            if (cc < 64)
                src = &d_nbr_warp[(b * 64 + cc) * HW + (ok ? gy * WID + gx : 0)];
            else
                src = &ref[(b * 64 + cc - 64) * HW + (ok ? gy * WID + gx : 0)];
            cpa4(sin_b + i * 4, src, ok);
        }
        for (int i = threadIdx.x; i < 8 * 9 * 16; i += 256) {
            int oc = i & 15;
            int r = i >> 4;
            int kk = r % 9;
            int c = r / 9;
            cpa4(sw_b + i * 4, &wgt[((oc0 + oc) * 128 + c0 + c) * 9 + kk], true);
        }
        cpa_commit();
    };

    stage(0, 0);
    for (int it = 0; it < 16; it++) {
        int buf = it & 1;
        cpa_wait0();
        __syncthreads();
        if (it + 1 < 16) stage((it + 1) * 8, buf ^ 1);

#pragma unroll
        for (int c = 0; c < 8; c++) {
            const float* in0 = &sIn[buf][c * 1156 + ty * 34 + tx];
#pragma unroll
            for (int kk = 0; kk < 9; kk++) {
                int ky = kk / 3, kx = kk - ky * 3;
                const unsigned long long* wq =
                    (const unsigned long long*)&sW[buf][(c * 9 + kk) * 16];
                unsigned long long w[8];
#pragma unroll
                for (int j = 0; j < 8; j++) w[j] = wq[j];
                const float* ip = in0 + ky * 34 + kx;
                float v0 = ip[0];
                float v1 = ip[16];
                float v2 = ip[16 * 34];
                float v3 = ip[16 * 34 + 16];
                unsigned long long vp0 = pack2(v0, v0);
                unsigned long long vp1 = pack2(v1, v1);
                unsigned long long vp2 = pack2(v2, v2);
                unsigned long long vp3 = pack2(v3, v3);
#pragma unroll
                for (int j = 0; j < 8; j++) {
                    acc[0][j] = fma2(vp0, w[j], acc[0][j]);
                    acc[1][j] = fma2(vp1, w[j], acc[1][j]);
                    acc[2][j] = fma2(vp2, w[j], acc[2][j]);
                    acc[3][j] = fma2(vp3, w[j], acc[3][j]);
                }
            }
        }
        __syncthreads();
    }

#pragma unroll
    for (int q = 0; q < 4; q++) {
        int yy = gy0 + ty + (q >> 1) * 16;
        int xx = gx0 + tx + (q & 1) * 16;
        int p = yy * WID + xx;
#pragma unroll
        for (int j = 0; j < 8; j++) {
            float lo, hi;
            unpack2(acc[q][j], lo, hi);
            lo += bias[oc0 + 2 * j];
            hi += bias[oc0 + 2 * j + 1];
            d_fea[(b * 64 + oc0 + 2 * j) * HW + p] = fmaxf(lo, 0.f);
            d_fea[(b * 64 + oc0 + 2 * j + 1) * HW + p] = fmaxf(hi, 0.f);
        }
    }
}

// ---------------- kernel 4: om conv (66 -> 216, 3x3) + fused epilogue --------
// 256 threads; 32x32 tile, 2x2 px/thread; 12 oc/block (18 z-slices);
// 6-ch chunks, cp.async double-buffered staging.
// Epilogue: ch<144 offsets get +flow (even->fy, odd->fx); ch>=144 sigmoid.
__global__ __launch_bounds__(256, 2)
void om_kernel(const float* __restrict__ flow,
               const float* __restrict__ wgt,
               const float* __restrict__ bias) {
    __shared__ __align__(16) float sIn[2][6 * 1156];   // 55.5 KB
    __shared__ __align__(16) float sW[2][6 * 9 * 12];

    int bz = blockIdx.z;
    int b = bz / 18;
    int oc0 = (bz - b * 18) * 12;
    int tx = threadIdx.x & 15, ty = threadIdx.x >> 4;
    int gx0 = blockIdx.x * 32, gy0 = blockIdx.y * 32;

    unsigned long long acc[4][6];
#pragma unroll
    for (int q = 0; q < 4; q++)
#pragma unroll
        for (int j = 0; j < 6; j++) acc[q][j] = 0ull;

    auto stage = [&](int c0, int buf) {
        uint32_t sin_b = (uint32_t)__cvta_generic_to_shared(&sIn[buf][0]);
        uint32_t sw_b = (uint32_t)__cvta_generic_to_shared(&sW[buf][0]);
        for (int i = threadIdx.x; i < 6 * 1156; i += 256) {
            int c = i / 1156;
            int pos = i - c * 1156;
            int iy = pos / 34, ix = pos - iy * 34;
            int gy = gy0 + iy - 1, gx = gx0 + ix - 1;
            bool ok = ((unsigned)gy < HGT) && ((unsigned)gx < WID);
            int cc = c0 + c;
            const float* src;
            if (cc < 64)
                src = &d_fea[(b * 64 + cc) * HW + (ok ? gy * WID + gx : 0)];
            else
                src = &flow[(b * 2 + cc - 64) * HW + (ok ? gy * WID + gx : 0)];
            cpa4(sin_b + i * 4, src, ok);
        }
        for (int i = threadIdx.x; i < 6 * 9 * 12; i += 256) {
            int oc = i % 12;
            int r = i / 12;
            int kk = r % 9;
            int c = r / 9;
            cpa4(sw_b + i * 4, &wgt[((oc0 + oc) * 66 + c0 + c) * 9 + kk], true);
        }
        cpa_commit();
    };

    stage(0, 0);
    for (int it = 0; it < 11; it++) {
        int buf = it & 1;
        cpa_wait0();
        __syncthreads();
        if (it + 1 < 11) stage((it + 1) * 6, buf ^ 1);

#pragma unroll
        for (int c = 0; c < 6; c++) {
            const float* in0 = &sIn[buf][c * 1156 + ty * 34 + tx];
#pragma unroll
            for (int kk = 0; kk < 9; kk++) {
                int ky = kk / 3, kx = kk - ky * 3;
                const unsigned long long* wq =
                    (const unsigned long long*)&sW[buf][(c * 9 + kk) * 12];
                unsigned long long w[6];
#pragma unroll
                for (int j = 0; j < 6; j++) w[j] = wq[j];
                const float* ip = in0 + ky * 34 + kx;
                float v0 = ip[0];
                float v1 = ip[16];
                float v2 = ip[16 * 34];
                float v3 = ip[16 * 34 + 16];
                unsigned long long vp0 = pack2(v0, v0);
                unsigned long long vp1 = pack2(v1, v1);
                unsigned long long vp2 = pack2(v2, v2);
                unsigned long long vp3 = pack2(v3, v3);
#pragma unroll
                for (int j = 0; j < 6; j++) {
                    acc[0][j] = fma2(vp0, w[j], acc[0][j]);
                    acc[1][j] = fma2(vp1, w[j], acc[1][j]);
                    acc[2][j] = fma2(vp2, w[j], acc[2][j]);
                    acc[3][j] = fma2(vp3, w[j], acc[3][j]);
                }
            }
        }
        __syncthreads();
    }

    bool is_mask = (oc0 >= 144);
#pragma unroll
    for (int q = 0; q < 4; q++) {
        int yy = gy0 + ty + (q >> 1) * 16;
        int xx = gx0 + tx + (q & 1) * 16;
        int p = yy * WID + xx;
        float fy = 0.f, fx = 0.f;
        if (!is_mask) {
            fx = flow[(b * 2 + 0) * HW + p];
            fy = flow[(b * 2 + 1) * HW + p];
        }
#pragma unroll
        for (int j = 0; j < 6; j++) {
            float lo, hi;
            unpack2(acc[q][j], lo, hi);
            lo += bias[oc0 + 2 * j];
            hi += bias[oc0 + 2 * j + 1];
            if (is_mask) {
                lo = 1.f / (1.f + expf(-lo));
                hi = 1.f / (1.f + expf(-hi));
            } else {
                lo += fy;
                hi += fx;
            }
            d_om[(b * 216 + oc0 + 2 * j) * HW + p] = lo;
            d_om[(b * 216 + oc0 + 2 * j + 1) * HW + p] = hi;
        }
    }
}

// ---------------- kernel 5: deformable conv ----------------
__device__ __forceinline__ void dcn_gather(const float* __restrict__ gbase,
                                           int x, int y, int ky, int kx,
                                           float dy, float dx, float m,
                                           float* vm) {
    float spy = (float)(y - 1 + ky) + dy;
    float spx = (float)(x - 1 + kx) + dx;
    float y0f = floorf(spy), x0f = floorf(spx);
    int iy0 = (int)y0f, ix0 = (int)x0f;
    float wy = spy - y0f, wx = spx - x0f;

    float v[8];
#pragma unroll
    for (int c = 0; c < 8; c++) v[c] = 0.f;

    float wts[4] = {(1.f - wy) * (1.f - wx), (1.f - wy) * wx,
                    wy * (1.f - wx), wy * wx};
    int ys[4] = {iy0, iy0, iy0 + 1, iy0 + 1};
    int xs[4] = {ix0, ix0 + 1, ix0, ix0 + 1};
#pragma unroll
    for (int t = 0; t < 4; t++) {
        int yi = ys[t], xi = xs[t];
        if ((unsigned)yi < HGT && (unsigned)xi < WID) {
            const float4* q = (const float4*)(gbase + (size_t)(yi * WID + xi) * 8);
            float4 a = q[0];
            float4 bb = q[1];
            float wt = wts[t];
            v[0] += wt * a.x;  v[1] += wt * a.y;
            v[2] += wt * a.z;  v[3] += wt * a.w;
            v[4] += wt * bb.x; v[5] += wt * bb.y;
            v[6] += wt * bb.z; v[7] += wt * bb.w;
        }
    }
#pragma unroll
    for (int c = 0; c < 8; c++) vm[c] = v[c] * m;
}

__global__ __launch_bounds__(256, 2)
void dcn_kernel(const float* __restrict__ dcnw,
                const float* __restrict__ dcnb,
                float* __restrict__ out) {
    __shared__ __align__(16) float sW[9 * 8 * 32];   // [(k*8+c)*32 + o]

    int bz = blockIdx.z;
    int b = bz >> 1;
    int o0 = (bz & 1) * 32;
    int tx = threadIdx.x & 15, ty = threadIdx.x >> 4;
    int x0 = blockIdx.x * 32 + tx;
    int y = blockIdx.y * 16 + ty;
    int p0 = y * WID + x0;
    int p1 = p0 + 16;

    unsigned long long acc[2][16];
#pragma unroll
    for (int s = 0; s < 2; s++)
#pragma unroll
        for (int j = 0; j < 16; j++) acc[s][j] = 0ull;

    for (int g = 0; g < 8; g++) {
        __syncthreads();
        for (int i = threadIdx.x; i < 2304; i += 256) {
            int o = i & 31;
            int r = i >> 5;
            int c = r & 7;
            int k = r >> 3;
            sW[i] = dcnw[((o0 + o) * 64 + g * 8 + c) * 9 + k];
        }
        __syncthreads();

        const float* gbase = d_nbr_t + (size_t)(b * 8 + g) * HW * 8;
        const float* omb = d_om + (size_t)b * 216 * HW;

#pragma unroll 1
        for (int k = 0; k < 9; k++) {
            int ky = k / 3, kx = k - ky * 3;
            int ch = g * 9 + k;

            float vm0[8], vm1[8];
            {
                float dy = omb[(ch * 2) * HW + p0];
                float dx = omb[(ch * 2 + 1) * HW + p0];
                float m = omb[(144 + ch) * HW + p0];
                dcn_gather(gbase, x0, y, ky, kx, dy, dx, m, vm0);
            }
            {
                float dy = omb[(ch * 2) * HW + p1];
                float dx = omb[(ch * 2 + 1) * HW + p1];
                float m = omb[(144 + ch) * HW + p1];
                dcn_gather(gbase, x0 + 16, y, ky, kx, dy, dx, m, vm1);
            }

#pragma unroll
            for (int c = 0; c < 8; c++) {
                const unsigned long long* wq =
                    (const unsigned long long*)&sW[(k * 8 + c) * 32];
                unsigned long long vp0 = pack2(vm0[c], vm0[c]);
                unsigned long long vp1 = pack2(vm1[c], vm1[c]);
#pragma unroll
                for (int half = 0; half < 2; half++) {
                    unsigned long long w[8];
#pragma unroll
                    for (int j = 0; j < 8; j++) w[j] = wq[half * 8 + j];
#pragma unroll
                    for (int j = 0; j < 8; j++) {
                        acc[0][half * 8 + j] = fma2(vp0, w[j], acc[0][half * 8 + j]);
                        acc[1][half * 8 + j] = fma2(vp1, w[j], acc[1][half * 8 + j]);
                    }
                }
            }
        }
    }

#pragma unroll
    for (int s = 0; s < 2; s++) {
        int p = (s == 0) ? p0 : p1;
#pragma unroll
        for (int j = 0; j < 16; j++) {
            float lo, hi;
            unpack2(acc[s][j], lo, hi);
            out[(b * 64 + o0 + 2 * j) * HW + p] = lo + dcnb[o0 + 2 * j];
            out[(b * 64 + o0 + 2 * j + 1) * HW + p] = hi + dcnb[o0 + 2 * j + 1];
        }
    }
}

// ---------------- launch ----------------
extern "C" void kernel_launch(void* const* d_in, const int* in_sizes, int n_in,
                              void* d_out, int out_size) {
    const float* nbr = (const float*)d_in[0];
    const float* ref = (const float*)d_in[1];
    const float* flow = (const float*)d_in[2];
    const float* conv1_w = (const float*)d_in[3];
    const float* conv1_b = (const float*)d_in[4];
    const float* om_w = (const float*)d_in[5];
    const float* om_b = (const float*)d_in[6];
    const float* dcn_w = (const float*)d_in[7];
    const float* dcn_b = (const float*)d_in[8];
    float* out = (float*)d_out;

    warp_kernel<<<(BAT * HW + 255) / 256, 256>>>(nbr, flow);
    transpose_kernel<<<(BAT * DG * HW + 255) / 256, 256>>>(nbr);
    conv1_kernel<<<dim3(8, 8, BAT * 4), 256>>>(ref, conv1_w, conv1_b);
    om_kernel<<<dim3(8, 8, BAT * 18), 256>>>(flow, om_w, om_b);
    dcn_kernel<<<dim3(8, 16, BAT * 2), 256>>>(dcn_w, dcn_b, out);
}

// round 5
// speedup vs baseline: 1.4295x; 1.0016x over previous
#include <cuda_runtime.h>
#include <stdint.h>
#include <math.h>

#define WID 256
#define HGT 256
#define HW  65536
#define BAT 2
#define NF  64
#define DG  8
#define CG  8
#define NK  9

// ---------------- scratch (__device__ globals; no allocation) ----------------
__device__ float d_nbr_t[BAT * DG * HW * CG];   // [b][g][p][c8]
__device__ float d_nbr_warp[BAT * NF * HW];     // NCHW
__device__ float d_fea[BAT * NF * HW];          // NCHW
__device__ float d_om[BAT * 216 * HW];          // NCHW (offsets +flow, masks sigmoided)

// ---------------- packed f32x2 helpers ----------------
__device__ __forceinline__ unsigned long long pack2(float lo, float hi) {
    unsigned long long r;
    asm("mov.b64 %0, {%1, %2};" : "=l"(r) : "f"(lo), "f"(hi));
    return r;
}
__device__ __forceinline__ unsigned long long fma2(unsigned long long a,
                                                   unsigned long long b,
                                                   unsigned long long c) {
    unsigned long long d;
    asm("fma.rn.f32x2 %0, %1, %2, %3;" : "=l"(d) : "l"(a), "l"(b), "l"(c));
    return d;
}
__device__ __forceinline__ void unpack2(unsigned long long v, float& lo, float& hi) {
    asm("mov.b64 {%0, %1}, %2;" : "=f"(lo), "=f"(hi) : "l"(v));
}

// ---------------- cp.async helpers ----------------
__device__ __forceinline__ void cpa4(uint32_t dst, const float* src, bool ok) {
    int sz = ok ? 4 : 0;
    asm volatile("cp.async.ca.shared.global [%0], [%1], 4, %2;"
                 :: "r"(dst), "l"(src), "r"(sz) : "memory");
}
__device__ __forceinline__ void cpa_commit() {
    asm volatile("cp.async.commit_group;" ::: "memory");
}
__device__ __forceinline__ void cpa_wait0() {
    asm volatile("cp.async.wait_group 0;" ::: "memory");
}

// ---------------- kernel 1: bilinear flow warp of nbr ----------------
__global__ void warp_kernel(const float* __restrict__ nbr,
                            const float* __restrict__ flow) {
    int idx = blockIdx.x * blockDim.x + threadIdx.x;   // b*HW + p
    if (idx >= BAT * HW) return;
    int b = idx >> 16;
    int p = idx & 65535;
    int y = p >> 8, x = p & 255;

    float fx = flow[(b * 2 + 0) * HW + p];
    float fy = flow[(b * 2 + 1) * HW + p];
    float px = (float)x + fx;
    float py = (float)y + fy;
    float x0f = floorf(px), y0f = floorf(py);
    int ix0 = (int)x0f, iy0 = (int)y0f;
    float wx = px - x0f, wy = py - y0f;

    bool vx0 = (unsigned)ix0 < WID;
    bool vx1 = (unsigned)(ix0 + 1) < WID;
    bool vy0 = (unsigned)iy0 < HGT;
    bool vy1 = (unsigned)(iy0 + 1) < HGT;

    float w00 = (vy0 && vx0) ? (1.f - wy) * (1.f - wx) : 0.f;
    float w01 = (vy0 && vx1) ? (1.f - wy) * wx : 0.f;
    float w10 = (vy1 && vx0) ? wy * (1.f - wx) : 0.f;
    float w11 = (vy1 && vx1) ? wy * wx : 0.f;

    int cx0 = min(max(ix0, 0), WID - 1);
    int cx1 = min(max(ix0 + 1, 0), WID - 1);
    int cy0 = min(max(iy0, 0), HGT - 1);
    int cy1 = min(max(iy0 + 1, 0), HGT - 1);
    int i00 = cy0 * WID + cx0;
    int i01 = cy0 * WID + cx1;
    int i10 = cy1 * WID + cx0;
    int i11 = cy1 * WID + cx1;

    const float* base = nbr + (size_t)b * NF * HW;
#pragma unroll 4
    for (int c = 0; c < NF; c++) {
        const float* ch = base + c * HW;
        float v = w00 * ch[i00] + w01 * ch[i01] + w10 * ch[i10] + w11 * ch[i11];
        d_nbr_warp[(b * NF + c) * HW + p] = v;
    }
}

// ---------------- kernel 2: transpose nbr to [b][g][p][c8] ----------------
__global__ void transpose_kernel(const float* __restrict__ nbr) {
    int idx = blockIdx.x * blockDim.x + threadIdx.x;   // (b*8+g)*HW + p
    if (idx >= BAT * DG * HW) return;
    int bg = idx >> 16;                // b*8+g
    int p = idx & 65535;
    int b = bg >> 3;
    int g = bg & 7;
    float v[8];
#pragma unroll
    for (int c = 0; c < 8; c++)
        v[c] = nbr[((b * NF + g * 8 + c) * HW) + p];
    float4* dst = (float4*)&d_nbr_t[(size_t)idx * 8];
    dst[0] = make_float4(v[0], v[1], v[2], v[3]);
    dst[1] = make_float4(v[4], v[5], v[6], v[7]);
}

// ---------------- kernel 3: conv1 (128 -> 64, 3x3, relu) ----------------
// 256 threads; 32x32 tile, 2x2 px/thread; 16 oc/block; 8-ch chunks,
// cp.async double-buffered staging.
__global__ __launch_bounds__(256, 2)
void conv1_kernel(const float* __restrict__ ref,
                  const float* __restrict__ wgt,
                  const float* __restrict__ bias) {
    __shared__ __align__(16) float sIn[2][8 * 1156];   // 74 KB
    __shared__ __align__(16) float sW[2][8 * 9 * 16];  // [(c*9+kk)*16 + oc]

    int bz = blockIdx.z;
    int b = bz >> 2;
    int oc0 = (bz & 3) * 16;
    int tx = threadIdx.x & 15, ty = threadIdx.x >> 4;
    int gx0 = blockIdx.x * 32, gy0 = blockIdx.y * 32;

    unsigned long long acc[4][8];
#pragma unroll
    for (int q = 0; q < 4; q++)
#pragma unroll
        for (int j = 0; j < 8; j++) acc[q][j] = 0ull;

    // staging lambda (c0 = chunk base channel, buf index)
    auto stage = [&](int c0, int buf) {
        uint32_t sin_b = (uint32_t)__cvta_generic_to_shared(&sIn[buf][0]);
        uint32_t sw_b = (uint32_t)__cvta_generic_to_shared(&sW[buf][0]);
        for (int i = threadIdx.x; i < 8 * 1156; i += 256) {
            int c = i / 1156;
            int pos = i - c * 1156;
            int iy = pos / 34, ix = pos - iy * 34;
            int gy = gy0 + iy - 1, gx = gx0 + ix - 1;
            bool ok = ((unsigned)gy < HGT) && ((unsigned)gx < WID);
            int cc = c0 + c;
            const float* src;
            if (cc < 64)
                src = &d_nbr_warp[(b * 64 + cc) * HW + (ok ? gy * WID + gx : 0)];
            else
                src = &ref[(b * 64 + cc - 64) * HW + (ok ? gy * WID + gx : 0)];
            cpa4(sin_b + i * 4, src, ok);
        }
        for (int i = threadIdx.x; i < 8 * 9 * 16; i += 256) {
            int oc = i & 15;
            int r = i >> 4;
            int kk = r % 9;
            int c = r / 9;
            cpa4(sw_b + i * 4, &wgt[((oc0 + oc) * 128 + c0 + c) * 9 + kk], true);
        }
        cpa_commit();
    };

    stage(0, 0);
    for (int it = 0; it < 16; it++) {
        int buf = it & 1;
        cpa_wait0();
        __syncthreads();
        if (it + 1 < 16) stage((it + 1) * 8, buf ^ 1);

#pragma unroll
        for (int c = 0; c < 8; c++) {
            const float* in0 = &sIn[buf][c * 1156 + ty * 34 + tx];
#pragma unroll
            for (int kk = 0; kk < 9; kk++) {
                int ky = kk / 3, kx = kk - ky * 3;
                const unsigned long long* wq =
                    (const unsigned long long*)&sW[buf][(c * 9 + kk) * 16];
                unsigned long long w[8];
#pragma unroll
                for (int j = 0; j < 8; j++) w[j] = wq[j];
                const float* ip = in0 + ky * 34 + kx;
                float v0 = ip[0];
                float v1 = ip[16];
                float v2 = ip[16 * 34];
                float v3 = ip[16 * 34 + 16];
                unsigned long long vp0 = pack2(v0, v0);
                unsigned long long vp1 = pack2(v1, v1);
                unsigned long long vp2 = pack2(v2, v2);
                unsigned long long vp3 = pack2(v3, v3);
#pragma unroll
                for (int j = 0; j < 8; j++) {
                    acc[0][j] = fma2(vp0, w[j], acc[0][j]);
                    acc[1][j] = fma2(vp1, w[j], acc[1][j]);
                    acc[2][j] = fma2(vp2, w[j], acc[2][j]);
                    acc[3][j] = fma2(vp3, w[j], acc[3][j]);
                }
            }
        }
        __syncthreads();
    }

#pragma unroll
    for (int q = 0; q < 4; q++) {
        int yy = gy0 + ty + (q >> 1) * 16;
        int xx = gx0 + tx + (q & 1) * 16;
        int p = yy * WID + xx;
#pragma unroll
        for (int j = 0; j < 8; j++) {
            float lo, hi;
            unpack2(acc[q][j], lo, hi);
            lo += bias[oc0 + 2 * j];
            hi += bias[oc0 + 2 * j + 1];
            d_fea[(b * 64 + oc0 + 2 * j) * HW + p] = fmaxf(lo, 0.f);
            d_fea[(b * 64 + oc0 + 2 * j + 1) * HW + p] = fmaxf(hi, 0.f);
        }
    }
}

// ---------------- kernel 4: om conv (66 -> 216, 3x3) + fused epilogue --------
// 256 threads; 32x32 tile, 2x2 px/thread; 12 oc/block (18 z-slices);
// 6-ch chunks, cp.async double-buffered staging.
// Epilogue: ch<144 offsets get +flow (even->fy, odd->fx); ch>=144 sigmoid.
__global__ __launch_bounds__(256, 2)
void om_kernel(const float* __restrict__ flow,
               const float* __restrict__ wgt,
               const float* __restrict__ bias) {
    __shared__ __align__(16) float sIn[2][6 * 1156];   // 55.5 KB
    __shared__ __align__(16) float sW[2][6 * 9 * 12];

    int bz = blockIdx.z;
    int b = bz / 18;
    int oc0 = (bz - b * 18) * 12;
    int tx = threadIdx.x & 15, ty = threadIdx.x >> 4;
    int gx0 = blockIdx.x * 32, gy0 = blockIdx.y * 32;

    unsigned long long acc[4][6];
#pragma unroll
    for (int q = 0; q < 4; q++)
#pragma unroll
        for (int j = 0; j < 6; j++) acc[q][j] = 0ull;

    auto stage = [&](int c0, int buf) {
        uint32_t sin_b = (uint32_t)__cvta_generic_to_shared(&sIn[buf][0]);
        uint32_t sw_b = (uint32_t)__cvta_generic_to_shared(&sW[buf][0]);
        for (int i = threadIdx.x; i < 6 * 1156; i += 256) {
            int c = i / 1156;
            int pos = i - c * 1156;
            int iy = pos / 34, ix = pos - iy * 34;
            int gy = gy0 + iy - 1, gx = gx0 + ix - 1;
            bool ok = ((unsigned)gy < HGT) && ((unsigned)gx < WID);
            int cc = c0 + c;
            const float* src;
            if (cc < 64)
                src = &d_fea[(b * 64 + cc) * HW + (ok ? gy * WID + gx : 0)];
            else
                src = &flow[(b * 2 + cc - 64) * HW + (ok ? gy * WID + gx : 0)];
            cpa4(sin_b + i * 4, src, ok);
        }
        for (int i = threadIdx.x; i < 6 * 9 * 12; i += 256) {
            int oc = i % 12;
            int r = i / 12;
            int kk = r % 9;
            int c = r / 9;
            cpa4(sw_b + i * 4, &wgt[((oc0 + oc) * 66 + c0 + c) * 9 + kk], true);
        }
        cpa_commit();
    };

    stage(0, 0);
    for (int it = 0; it < 11; it++) {
        int buf = it & 1;
        cpa_wait0();
        __syncthreads();
        if (it + 1 < 11) stage((it + 1) * 6, buf ^ 1);

#pragma unroll
        for (int c = 0; c < 6; c++) {
            const float* in0 = &sIn[buf][c * 1156 + ty * 34 + tx];
#pragma unroll
            for (int kk = 0; kk < 9; kk++) {
                int ky = kk / 3, kx = kk - ky * 3;
                const unsigned long long* wq =
                    (const unsigned long long*)&sW[buf][(c * 9 + kk) * 12];
                unsigned long long w[6];
#pragma unroll
                for (int j = 0; j < 6; j++) w[j] = wq[j];
                const float* ip = in0 + ky * 34 + kx;
                float v0 = ip[0];
                float v1 = ip[16];
                float v2 = ip[16 * 34];
                float v3 = ip[16 * 34 + 16];
                unsigned long long vp0 = pack2(v0, v0);
                unsigned long long vp1 = pack2(v1, v1);
                unsigned long long vp2 = pack2(v2, v2);
                unsigned long long vp3 = pack2(v3, v3);
#pragma unroll
                for (int j = 0; j < 6; j++) {
                    acc[0][j] = fma2(vp0, w[j], acc[0][j]);
                    acc[1][j] = fma2(vp1, w[j], acc[1][j]);
                    acc[2][j] = fma2(vp2, w[j], acc[2][j]);
                    acc[3][j] = fma2(vp3, w[j], acc[3][j]);
                }
            }
        }
        __syncthreads();
    }

    bool is_mask = (oc0 >= 144);
#pragma unroll
    for (int q = 0; q < 4; q++) {
        int yy = gy0 + ty + (q >> 1) * 16;
        int xx = gx0 + tx + (q & 1) * 16;
        int p = yy * WID + xx;
        float fy = 0.f, fx = 0.f;
        if (!is_mask) {
            fx = flow[(b * 2 + 0) * HW + p];
            fy = flow[(b * 2 + 1) * HW + p];
        }
#pragma unroll
        for (int j = 0; j < 6; j++) {
            float lo, hi;
            unpack2(acc[q][j], lo, hi);
            lo += bias[oc0 + 2 * j];
            hi += bias[oc0 + 2 * j + 1];
            if (is_mask) {
                lo = 1.f / (1.f + expf(-lo));
                hi = 1.f / (1.f + expf(-hi));
            } else {
                lo += fy;
                hi += fx;
            }
            d_om[(b * 216 + oc0 + 2 * j) * HW + p] = lo;
            d_om[(b * 216 + oc0 + 2 * j + 1) * HW + p] = hi;
        }
    }
}

// ---------------- kernel 5: deformable conv ----------------
__device__ __forceinline__ void dcn_gather(const float* __restrict__ gbase,
                                           int x, int y, int ky, int kx,
                                           float dy, float dx, float m,
                                           float* vm) {
    float spy = (float)(y - 1 + ky) + dy;
    float spx = (float)(x - 1 + kx) + dx;
    float y0f = floorf(spy), x0f = floorf(spx);
    int iy0 = (int)y0f, ix0 = (int)x0f;
    float wy = spy - y0f, wx = spx - x0f;

    float v[8];
#pragma unroll
    for (int c = 0; c < 8; c++) v[c] = 0.f;

    float wts[4] = {(1.f - wy) * (1.f - wx), (1.f - wy) * wx,
                    wy * (1.f - wx), wy * wx};
    int ys[4] = {iy0, iy0, iy0 + 1, iy0 + 1};
    int xs[4] = {ix0, ix0 + 1, ix0, ix0 + 1};
#pragma unroll
    for (int t = 0; t < 4; t++) {
        int yi = ys[t], xi = xs[t];
        if ((unsigned)yi < HGT && (unsigned)xi < WID) {
            const float4* q = (const float4*)(gbase + (size_t)(yi * WID + xi) * 8);
            float4 a = q[0];
            float4 bb = q[1];
            float wt = wts[t];
            v[0] += wt * a.x;  v[1] += wt * a.y;
            v[2] += wt * a.z;  v[3] += wt * a.w;
            v[4] += wt * bb.x; v[5] += wt * bb.y;
            v[6] += wt * bb.z; v[7] += wt * bb.w;
        }
    }
#pragma unroll
    for (int c = 0; c < 8; c++) vm[c] = v[c] * m;
}

__global__ __launch_bounds__(256, 2)
void dcn_kernel(const float* __restrict__ dcnw,
                const float* __restrict__ dcnb,
                float* __restrict__ out) {
    __shared__ __align__(16) float sW[9 * 8 * 32];   // [(k*8+c)*32 + o]

    int bz = blockIdx.z;
    int b = bz >> 1;
    int o0 = (bz & 1) * 32;
    int tx = threadIdx.x & 15, ty = threadIdx.x >> 4;
    int x0 = blockIdx.x * 32 + tx;
    int y = blockIdx.y * 16 + ty;
    int p0 = y * WID + x0;
    int p1 = p0 + 16;

    unsigned long long acc[2][16];
#pragma unroll
    for (int s = 0; s < 2; s++)
#pragma unroll
        for (int j = 0; j < 16; j++) acc[s][j] = 0ull;

    for (int g = 0; g < 8; g++) {
        __syncthreads();
        for (int i = threadIdx.x; i < 2304; i += 256) {
            int o = i & 31;
            int r = i >> 5;
            int c = r & 7;
            int k = r >> 3;
            sW[i] = dcnw[((o0 + o) * 64 + g * 8 + c) * 9 + k];
        }
        __syncthreads();

        const float* gbase = d_nbr_t + (size_t)(b * 8 + g) * HW * 8;
        const float* omb = d_om + (size_t)b * 216 * HW;

#pragma unroll 1
        for (int k = 0; k < 9; k++) {
            int ky = k / 3, kx = k - ky * 3;
            int ch = g * 9 + k;

            float vm0[8], vm1[8];
            {
                float dy = omb[(ch * 2) * HW + p0];
                float dx = omb[(ch * 2 + 1) * HW + p0];
                float m = omb[(144 + ch) * HW + p0];
                dcn_gather(gbase, x0, y, ky, kx, dy, dx, m, vm0);
            }
            {
                float dy = omb[(ch * 2) * HW + p1];
                float dx = omb[(ch * 2 + 1) * HW + p1];
                float m = omb[(144 + ch) * HW + p1];
                dcn_gather(gbase, x0 + 16, y, ky, kx, dy, dx, m, vm1);
            }

#pragma unroll
            for (int c = 0; c < 8; c++) {
                const unsigned long long* wq =
                    (const unsigned long long*)&sW[(k * 8 + c) * 32];
                unsigned long long vp0 = pack2(vm0[c], vm0[c]);
                unsigned long long vp1 = pack2(vm1[c], vm1[c]);
#pragma unroll
                for (int half = 0; half < 2; half++) {
                    unsigned long long w[8];
#pragma unroll
                    for (int j = 0; j < 8; j++) w[j] = wq[half * 8 + j];
#pragma unroll
                    for (int j = 0; j < 8; j++) {
                        acc[0][half * 8 + j] = fma2(vp0, w[j], acc[0][half * 8 + j]);
                        acc[1][half * 8 + j] = fma2(vp1, w[j], acc[1][half * 8 + j]);
                    }
                }
            }
        }
    }

#pragma unroll
    for (int s = 0; s < 2; s++) {
        int p = (s == 0) ? p0 : p1;
#pragma unroll
        for (int j = 0; j < 16; j++) {
            float lo, hi;
            unpack2(acc[s][j], lo, hi);
            out[(b * 64 + o0 + 2 * j) * HW + p] = lo + dcnb[o0 + 2 * j];
            out[(b * 64 + o0 + 2 * j + 1) * HW + p] = hi + dcnb[o0 + 2 * j + 1];
        }
    }
}

// ---------------- launch ----------------
extern "C" void kernel_launch(void* const* d_in, const int* in_sizes, int n_in,
                              void* d_out, int out_size) {
    const float* nbr = (const float*)d_in[0];
    const float* ref = (const float*)d_in[1];
    const float* flow = (const float*)d_in[2];
    const float* conv1_w = (const float*)d_in[3];
    const float* conv1_b = (const float*)d_in[4];
    const float* om_w = (const float*)d_in[5];
    const float* om_b = (const float*)d_in[6];
    const float* dcn_w = (const float*)d_in[7];
    const float* dcn_b = (const float*)d_in[8];
    float* out = (float*)d_out;

    warp_kernel<<<(BAT * HW + 255) / 256, 256>>>(nbr, flow);
    transpose_kernel<<<(BAT * DG * HW + 255) / 256, 256>>>(nbr);
    conv1_kernel<<<dim3(8, 8, BAT * 4), 256>>>(ref, conv1_w, conv1_b);
    om_kernel<<<dim3(8, 8, BAT * 18), 256>>>(flow, om_w, om_b);
    dcn_kernel<<<dim3(8, 16, BAT * 2), 256>>>(dcn_w, dcn_b, out);
}

// round 6
// speedup vs baseline: 1.6532x; 1.1565x over previous
#include <cuda_runtime.h>
#include <stdint.h>
#include <math.h>

#define WID 256
#define HGT 256
#define HW  65536
#define BAT 2
#define NF  64
#define DG  8
#define CST 424
#define RST 136
#define SINB 3392

__device__ float d_nbr_t[BAT * DG * HW * 8];
__device__ float d_nwh[BAT * NF * HW];
__device__ float d_nwl[BAT * NF * HW];
__device__ float d_refh[BAT * NF * HW];
__device__ float d_refl[BAT * NF * HW];
__device__ float d_feah[BAT * NF * HW];
__device__ float d_feal[BAT * NF * HW];
__device__ float d_flwh[BAT * 2 * HW];
__device__ float d_flwl[BAT * 2 * HW];
__device__ float d_om[BAT * 216 * HW];
__device__ float d_w1ph[73728];
__device__ float d_w1pl[73728];
__device__ float d_womph[165888];
__device__ float d_wompl[165888];

__device__ __forceinline__ float rna(float x) {
    uint32_t u; asm("cvt.rna.tf32.f32 %0, %1;" : "=r"(u) : "f"(x));
    return __uint_as_float(u);
}
__device__ __forceinline__ void mma8(float* c, const uint4& a, uint32_t b0, uint32_t b1) {
    asm volatile("mma.sync.aligned.m16n8k8.row.col.f32.tf32.tf32.f32 "
                 "{%0,%1,%2,%3},{%4,%5,%6,%7},{%8,%9},{%0,%1,%2,%3};"
                 : "+f"(c[0]), "+f"(c[1]), "+f"(c[2]), "+f"(c[3])
                 : "r"(a.x), "r"(a.y), "r"(a.z), "r"(a.w), "r"(b0), "r"(b1));
}
__device__ __forceinline__ void cpa16(uint32_t d, const float* s, bool ok) {
    int sz = ok ? 16 : 0;
    asm volatile("cp.async.cg.shared.global [%0], [%1], 16, %2;" :: "r"(d), "l"(s), "r"(sz) : "memory");
}
__device__ __forceinline__ void cpa4(uint32_t d, const float* s, bool ok) {
    int sz = ok ? 4 : 0;
    asm volatile("cp.async.ca.shared.global [%0], [%1], 4, %2;" :: "r"(d), "l"(s), "r"(sz) : "memory");
}
__device__ __forceinline__ void cpcommit() { asm volatile("cp.async.commit_group;" ::: "memory"); }
__device__ __forceinline__ void cpwait() { asm volatile("cp.async.wait_group 0;" ::: "memory"); }

__device__ __forceinline__ unsigned long long pack2(float lo, float hi) {
    unsigned long long r; asm("mov.b64 %0, {%1, %2};" : "=l"(r) : "f"(lo), "f"(hi)); return r;
}
__device__ __forceinline__ unsigned long long fma2(unsigned long long a, unsigned long long b, unsigned long long c) {
    unsigned long long d; asm("fma.rn.f32x2 %0, %1, %2, %3;" : "=l"(d) : "l"(a), "l"(b), "l"(c)); return d;
}
__device__ __forceinline__ void unpack2(unsigned long long v, float& lo, float& hi) {
    asm("mov.b64 {%0, %1}, %2;" : "=f"(lo), "=f"(hi) : "l"(v));
}

// ---------- prep: hi/lo splits ----------
__global__ void prep_ref(const float* __restrict__ ref) {
    int i = blockIdx.x * blockDim.x + threadIdx.x;
    if (i >= BAT * NF * HW / 4) return;
    float4 v = ((const float4*)ref)[i];
    float4 h, l;
    h.x = rna(v.x); l.x = rna(v.x - h.x);
    h.y = rna(v.y); l.y = rna(v.y - h.y);
    h.z = rna(v.z); l.z = rna(v.z - h.z);
    h.w = rna(v.w); l.w = rna(v.w - h.w);
    ((float4*)d_refh)[i] = h; ((float4*)d_refl)[i] = l;
}
__global__ void prep_flow(const float* __restrict__ flow) {
    int i = blockIdx.x * blockDim.x + threadIdx.x;
    if (i >= BAT * 2 * HW / 4) return;
    float4 v = ((const float4*)flow)[i];
    float4 h, l;
    h.x = rna(v.x); l.x = rna(v.x - h.x);
    h.y = rna(v.y); l.y = rna(v.y - h.y);
    h.z = rna(v.z); l.z = rna(v.z - h.z);
    h.w = rna(v.w); l.w = rna(v.w - h.w);
    ((float4*)d_flwh)[i] = h; ((float4*)d_flwl)[i] = l;
}

// ---------- weight packing (A-fragment layout) ----------
__global__ void pack_w1(const float* __restrict__ w) {
    int idx = blockIdx.x * blockDim.x + threadIdx.x;
    if (idx >= 18432) return;
    int chunk = idx / 1152, r = idx % 1152;
    int tap = r / 128, r2 = r & 127;
    int m = r2 >> 5, lane = r2 & 31;
    int gr = lane >> 2, tq = lane & 3;
    float4 h, l; float* hp = &h.x; float* lp = &l.x;
#pragma unroll
    for (int vi = 0; vi < 4; vi++) {
        int oc = 16 * m + gr + (vi & 1) * 8;
        int c = 8 * chunk + tq + (vi >> 1) * 4;
        float v = w[(oc * 128 + c) * 9 + tap];
        float hv = rna(v); hp[vi] = hv; lp[vi] = rna(v - hv);
    }
    ((float4*)d_w1ph)[idx] = h; ((float4*)d_w1pl)[idx] = l;
}
__global__ void pack_wom(const float* __restrict__ w) {
    int idx = blockIdx.x * blockDim.x + threadIdx.x;
    if (idx >= 41472) return;
    int slice = idx / 20736, r = idx % 20736;
    int chunk = r / 2304, r1 = r % 2304;
    int tap = r1 / 256, r2 = r1 & 255;
    int m = r2 >> 5, lane = r2 & 31;
    int gr = lane >> 2, tq = lane & 3;
    float4 h, l; float* hp = &h.x; float* lp = &l.x;
#pragma unroll
    for (int vi = 0; vi < 4; vi++) {
        int oc = 128 * slice + 16 * m + gr + (vi & 1) * 8;
        int c = 8 * chunk + tq + (vi >> 1) * 4;
        float v = 0.f;
        if (oc < 216 && c < 66) v = w[(oc * 66 + c) * 9 + tap];
        float hv = rna(v); hp[vi] = hv; lp[vi] = rna(v - hv);
    }
    ((float4*)d_womph)[idx] = h; ((float4*)d_wompl)[idx] = l;
}

// ---------- warp (bilinear) -> hi/lo ----------
__global__ void warp_kernel(const float* __restrict__ nbr, const float* __restrict__ flow) {
    int idx = blockIdx.x * blockDim.x + threadIdx.x;
    if (idx >= BAT * HW) return;
    int b = idx >> 16, p = idx & 65535;
    int y = p >> 8, x = p & 255;
    float fx = flow[(b * 2 + 0) * HW + p];
    float fy = flow[(b * 2 + 1) * HW + p];
    float px = (float)x + fx, py = (float)y + fy;
    float x0f = floorf(px), y0f = floorf(py);
    int ix0 = (int)x0f, iy0 = (int)y0f;
    float wx = px - x0f, wy = py - y0f;
    bool vx0 = (unsigned)ix0 < WID, vx1 = (unsigned)(ix0 + 1) < WID;
    bool vy0 = (unsigned)iy0 < HGT, vy1 = (unsigned)(iy0 + 1) < HGT;
    float w00 = (vy0 && vx0) ? (1.f - wy) * (1.f - wx) : 0.f;
    float w01 = (vy0 && vx1) ? (1.f - wy) * wx : 0.f;
    float w10 = (vy1 && vx0) ? wy * (1.f - wx) : 0.f;
    float w11 = (vy1 && vx1) ? wy * wx : 0.f;
    int cx0 = min(max(ix0, 0), WID - 1), cx1 = min(max(ix0 + 1, 0), WID - 1);
    int cy0 = min(max(iy0, 0), HGT - 1), cy1 = min(max(iy0 + 1, 0), HGT - 1);
    int i00 = cy0 * WID + cx0, i01 = cy0 * WID + cx1;
    int i10 = cy1 * WID + cx0, i11 = cy1 * WID + cx1;
    const float* base = nbr + (size_t)b * NF * HW;
#pragma unroll 4
    for (int c = 0; c < NF; c++) {
        const float* ch = base + c * HW;
        float v = w00 * ch[i00] + w01 * ch[i01] + w10 * ch[i10] + w11 * ch[i11];
        float hv = rna(v);
        d_nwh[(b * NF + c) * HW + p] = hv;
        d_nwl[(b * NF + c) * HW + p] = rna(v - hv);
    }
}

// ---------- transpose for dcn ----------
__global__ void transpose_kernel(const float* __restrict__ nbr) {
    int idx = blockIdx.x * blockDim.x + threadIdx.x;
    if (idx >= BAT * DG * HW) return;
    int bg = idx >> 16, p = idx & 65535;
    int b = bg >> 3, g = bg & 7;
    float v[8];
#pragma unroll
    for (int c = 0; c < 8; c++) v[c] = nbr[((b * NF + g * 8 + c) * HW) + p];
    float4* dst = (float4*)&d_nbr_t[(size_t)idx * 8];
    dst[0] = make_float4(v[0], v[1], v[2], v[3]);
    dst[1] = make_float4(v[4], v[5], v[6], v[7]);
}

// ---------- conv1 via tf32 MMA: 128->64, relu, out hi/lo ----------
// grid(2,256,BAT), 512 thr. warp: g=warp&3 (32px), h=warp>>2 (m-block, 16oc).
__global__ __launch_bounds__(512, 1)
void conv1_mma(const float* __restrict__ bias) {
    extern __shared__ float sm[];
    float* sInH = sm;
    float* sInL = sm + 6784;
    float* sWH = sm + 13568;
    float* sWL = sm + 22784;

    int tid = threadIdx.x;
    int warp = tid >> 5, lane = tid & 31;
    int g = warp & 3, h = warp >> 2;
    int gr = lane >> 2, tq = lane & 3;
    int b = blockIdx.z, y = blockIdx.y, x0 = blockIdx.x * 128;

    float acc[4][4];
#pragma unroll
    for (int j = 0; j < 4; j++)
#pragma unroll
        for (int k = 0; k < 4; k++) acc[j][k] = 0.f;

    auto stage = [&](int chunk, int buf) {
        for (int i = tid; i < 1536; i += 512) {
            int pr = i >= 768;
            int ii = pr ? i - 768 : i;
            int c = ii / 96, rr = ii - c * 96;
            int r = rr >> 5, k = rr & 31;
            int cc = chunk * 8 + c;
            int gy = y + r - 1;
            bool ok = (unsigned)gy < HGT;
            int gyc = ok ? gy : 0;
            const float* arr = (cc < 64) ? (pr ? d_nwl : d_nwh) : (pr ? d_refl : d_refh);
            int ci = (cc < 64) ? cc : cc - 64;
            const float* src = arr + (size_t)(b * 64 + ci) * HW + gyc * 256 + x0 + 4 * k;
            float* db = (pr ? sInL : sInH) + buf * SINB;
            cpa16((uint32_t)__cvta_generic_to_shared(db + c * CST + r * RST + 4 + 4 * k), src, ok);
        }
        for (int i = tid; i < 96; i += 512) {
            int pr = i >= 48;
            int ii = pr ? i - 48 : i;
            int c = ii / 6, rr = ii - c * 6;
            int r = rr >> 1, side = rr & 1;
            int cc = chunk * 8 + c;
            int gy = y + r - 1;
            int gx = side ? x0 + 128 : x0 - 1;
            bool ok = ((unsigned)gy < HGT) && ((unsigned)gx < WID);
            int gyc = ((unsigned)gy < HGT) ? gy : 0;
            int gxc = ((unsigned)gx < WID) ? gx : 0;
            const float* arr = (cc < 64) ? (pr ? d_nwl : d_nwh) : (pr ? d_refl : d_refh);
            int ci = (cc < 64) ? cc : cc - 64;
            const float* src = arr + (size_t)(b * 64 + ci) * HW + gyc * 256 + gxc;
            float* db = (pr ? sInL : sInH) + buf * SINB;
            cpa4((uint32_t)__cvta_generic_to_shared(db + c * CST + r * RST + (side ? 132 : 3)), src, ok);
        }
        for (int i = tid; i < 2304; i += 512) {
            int pr = i >= 1152;
            int ii = pr ? i - 1152 : i;
            const float* src = (pr ? d_w1pl : d_w1ph) + chunk * 4608 + ii * 4;
            float* db = (pr ? sWL : sWH) + buf * 4608;
            cpa16((uint32_t)__cvta_generic_to_shared(db + ii * 4), src, true);
        }
        cpcommit();
    };

    stage(0, 0);
    int bbase = tq * CST + 32 * g + gr + 3;
    for (int it = 0; it < 16; it++) {
        int buf = it & 1;
        cpwait();
        __syncthreads();
        if (it + 1 < 16) stage(it + 1, buf ^ 1);

        const float* siH = sInH + buf * SINB;
        const float* siL = sInL + buf * SINB;
        const float* swH = sWH + buf * 4608;
        const float* swL = sWL + buf * 4608;
#pragma unroll
        for (int dy = 0; dy < 3; dy++) {
#pragma unroll
            for (int dx = 0; dx < 3; dx++) {
                int tap = dy * 3 + dx;
                int wi = ((tap * 4 + h) * 32 + lane) * 4;
                uint4 Ah = *(const uint4*)(swH + wi);
                uint4 Al = *(const uint4*)(swL + wi);
                int fb = bbase + dy * RST + dx;
#pragma unroll
                for (int j = 0; j < 4; j++) {
                    int fi = fb + 8 * j;
                    uint32_t bh0 = __float_as_uint(siH[fi]);
                    uint32_t bh1 = __float_as_uint(siH[fi + 4 * CST]);
                    uint32_t bl0 = __float_as_uint(siL[fi]);
                    uint32_t bl1 = __float_as_uint(siL[fi + 4 * CST]);
                    mma8(acc[j], Ah, bh0, bh1);
                    mma8(acc[j], Ah, bl0, bl1);
                    mma8(acc[j], Al, bh0, bh1);
                }
            }
        }
        __syncthreads();
    }

#pragma unroll
    for (int j = 0; j < 4; j++) {
        int x = x0 + 32 * g + 8 * j + 2 * tq;
        int pA = y * 256 + x;
#pragma unroll
        for (int k = 0; k < 4; k++) {
            int ch = 16 * h + gr + (k >= 2 ? 8 : 0);
            int p = pA + (k & 1);
            float v = acc[j][k] + bias[ch];
            v = fmaxf(v, 0.f);
            float hv = rna(v);
            size_t o = (size_t)(b * 64 + ch) * HW + p;
            d_feah[o] = hv;
            d_feal[o] = rna(v - hv);
        }
    }
}

// ---------- om via tf32 MMA: 66->216, fused epilogue ----------
// grid(2,256,BAT*2), slice=z&1 -> oc base 128*slice. warp h: m-blocks 2h,2h+1.
__global__ __launch_bounds__(512, 1)
void om_mma(const float* __restrict__ bias, const float* __restrict__ flow) {
    extern __shared__ float sm[];
    float* sInH = sm;
    float* sInL = sm + 6784;
    float* sWH = sm + 13568;
    float* sWL = sm + 32000;

    int tid = threadIdx.x;
    int warp = tid >> 5, lane = tid & 31;
    int g = warp & 3, h = warp >> 2;
    int gr = lane >> 2, tq = lane & 3;
    int bz = blockIdx.z;
    int b = bz >> 1, slice = bz & 1;
    int y = blockIdx.y, x0 = blockIdx.x * 128;

    float acc[4][2][4];
#pragma unroll
    for (int j = 0; j < 4; j++)
#pragma unroll
        for (int mi = 0; mi < 2; mi++)
#pragma unroll
            for (int k = 0; k < 4; k++) acc[j][mi][k] = 0.f;

    auto stage = [&](int chunk, int buf) {
        for (int i = tid; i < 1536; i += 512) {
            int pr = i >= 768;
            int ii = pr ? i - 768 : i;
            int c = ii / 96, rr = ii - c * 96;
            int r = rr >> 5, k = rr & 31;
            int cc = chunk * 8 + c;
            int gy = y + r - 1;
            bool ok = ((unsigned)gy < HGT) && (cc < 66);
            int gyc = ((unsigned)gy < HGT) ? gy : 0;
            const float* arr = (cc < 64) ? (pr ? d_feal : d_feah) : (pr ? d_flwl : d_flwh);
            int ci, cm;
            if (cc < 64) { ci = cc; cm = 64; } else { ci = cc - 64; cm = 2; }
            if (ci >= cm) ci = 0;
            const float* src = arr + (size_t)(b * cm + ci) * HW + gyc * 256 + x0 + 4 * k;
            float* db = (pr ? sInL : sInH) + buf * SINB;
            cpa16((uint32_t)__cvta_generic_to_shared(db + c * CST + r * RST + 4 + 4 * k), src, ok);
        }
        for (int i = tid; i < 96; i += 512) {
            int pr = i >= 48;
            int ii = pr ? i - 48 : i;
            int c = ii / 6, rr = ii - c * 6;
            int r = rr >> 1, side = rr & 1;
            int cc = chunk * 8 + c;
            int gy = y + r - 1;
            int gx = side ? x0 + 128 : x0 - 1;
            bool ok = ((unsigned)gy < HGT) && ((unsigned)gx < WID) && (cc < 66);
            int gyc = ((unsigned)gy < HGT) ? gy : 0;
            int gxc = ((unsigned)gx < WID) ? gx : 0;
            const float* arr = (cc < 64) ? (pr ? d_feal : d_feah) : (pr ? d_flwl : d_flwh);
            int ci, cm;
            if (cc < 64) { ci = cc; cm = 64; } else { ci = cc - 64; cm = 2; }
            if (ci >= cm) ci = 0;
            const float* src = arr + (size_t)(b * cm + ci) * HW + gyc * 256 + gxc;
            float* db = (pr ? sInL : sInH) + buf * SINB;
            cpa4((uint32_t)__cvta_generic_to_shared(db + c * CST + r * RST + (side ? 132 : 3)), src, ok);
        }
        for (int i = tid; i < 4608; i += 512) {
            int pr = i >= 2304;
            int ii = pr ? i - 2304 : i;
            const float* src = (pr ? d_wompl : d_womph) + (slice * 9 + chunk) * 9216 + ii * 4;
            float* db = (pr ? sWL : sWH) + buf * 9216;
            cpa16((uint32_t)__cvta_generic_to_shared(db + ii * 4), src, true);
        }
        cpcommit();
    };

    stage(0, 0);
    int bbase = tq * CST + 32 * g + gr + 3;
    for (int it = 0; it < 9; it++) {
        int buf = it & 1;
        cpwait();
        __syncthreads();
        if (it + 1 < 9) stage(it + 1, buf ^ 1);

        const float* siH = sInH + buf * SINB;
        const float* siL = sInL + buf * SINB;
        const float* swH = sWH + buf * 9216;
        const float* swL = sWL + buf * 9216;
#pragma unroll
        for (int dy = 0; dy < 3; dy++) {
#pragma unroll
            for (int dx = 0; dx < 3; dx++) {
                int tap = dy * 3 + dx;
                int wi = ((tap * 8 + 2 * h) * 32 + lane) * 4;
                uint4 Ah0 = *(const uint4*)(swH + wi);
                uint4 Ah1 = *(const uint4*)(swH + wi + 128);
                uint4 Al0 = *(const uint4*)(swL + wi);
                uint4 Al1 = *(const uint4*)(swL + wi + 128);
                int fb = bbase + dy * RST + dx;
#pragma unroll
                for (int j = 0; j < 4; j++) {
                    int fi = fb + 8 * j;
                    uint32_t bh0 = __float_as_uint(siH[fi]);
                    uint32_t bh1 = __float_as_uint(siH[fi + 4 * CST]);
                    uint32_t bl0 = __float_as_uint(siL[fi]);
                    uint32_t bl1 = __float_as_uint(siL[fi + 4 * CST]);
                    mma8(acc[j][0], Ah0, bh0, bh1);
                    mma8(acc[j][0], Ah0, bl0, bl1);
                    mma8(acc[j][0], Al0, bh0, bh1);
                    mma8(acc[j][1], Ah1, bh0, bh1);
                    mma8(acc[j][1], Ah1, bl0, bl1);
                    mma8(acc[j][1], Al1, bh0, bh1);
                }
            }
        }
        __syncthreads();
    }

    int ocb = 128 * slice;
#pragma unroll
    for (int j = 0; j < 4; j++) {
        int x = x0 + 32 * g + 8 * j + 2 * tq;
        int pA = y * 256 + x;
#pragma unroll
        for (int mi = 0; mi < 2; mi++) {
            int chA = ocb + 16 * (2 * h + mi) + gr;
#pragma unroll
            for (int k = 0; k < 4; k++) {
                int ch = chA + (k >= 2 ? 8 : 0);
                if (ch >= 216) continue;
                int p = pA + (k & 1);
                float v = acc[j][mi][k] + bias[ch];
                if (ch < 144) {
                    v += (gr & 1) ? flow[(b * 2 + 0) * HW + p]
                                  : flow[(b * 2 + 1) * HW + p];
                } else {
                    v = 1.f / (1.f + expf(-v));
                }
                d_om[(size_t)(b * 216 + ch) * HW + p] = v;
            }
        }
    }
}

// ---------- dcn (unchanged scalar path) ----------
__device__ __forceinline__ void dcn_gather(const float* __restrict__ gbase,
                                           int x, int y, int ky, int kx,
                                           float dy, float dx, float m, float* vm) {
    float spy = (float)(y - 1 + ky) + dy;
    float spx = (float)(x - 1 + kx) + dx;
    float y0f = floorf(spy), x0f = floorf(spx);
    int iy0 = (int)y0f, ix0 = (int)x0f;
    float wy = spy - y0f, wx = spx - x0f;
    float v[8];
#pragma unroll
    for (int c = 0; c < 8; c++) v[c] = 0.f;
    float wts[4] = {(1.f - wy) * (1.f - wx), (1.f - wy) * wx, wy * (1.f - wx), wy * wx};
    int ys[4] = {iy0, iy0, iy0 + 1, iy0 + 1};
    int xs[4] = {ix0, ix0 + 1, ix0, ix0 + 1};
#pragma unroll
    for (int t = 0; t < 4; t++) {
        int yi = ys[t], xi = xs[t];
        if ((unsigned)yi < HGT && (unsigned)xi < WID) {
            const float4* q = (const float4*)(gbase + (size_t)(yi * WID + xi) * 8);
            float4 a = q[0];
            float4 bb = q[1];
            float wt = wts[t];
            v[0] += wt * a.x;  v[1] += wt * a.y;  v[2] += wt * a.z;  v[3] += wt * a.w;
            v[4] += wt * bb.x; v[5] += wt * bb.y; v[6] += wt * bb.z; v[7] += wt * bb.w;
        }
    }
#pragma unroll
    for (int c = 0; c < 8; c++) vm[c] = v[c] * m;
}

__global__ __launch_bounds__(256, 2)
void dcn_kernel(const float* __restrict__ dcnw, const float* __restrict__ dcnb,
                float* __restrict__ out) {
    __shared__ __align__(16) float sW[2304];

    int bz = blockIdx.z;
    int b = bz >> 1, o0 = (bz & 1) * 32;
    int tx = threadIdx.x & 15, ty = threadIdx.x >> 4;
    int x0 = blockIdx.x * 32 + tx;
    int y = blockIdx.y * 16 + ty;
    int p0 = y * WID + x0, p1 = p0 + 16;

    unsigned long long acc[2][16];
#pragma unroll
    for (int s = 0; s < 2; s++)
#pragma unroll
        for (int j = 0; j < 16; j++) acc[s][j] = 0ull;

    for (int g = 0; g < 8; g++) {
        __syncthreads();
        for (int i = threadIdx.x; i < 2304; i += 256) {
            int o = i & 31, r = i >> 5;
            int c = r & 7, k = r >> 3;
            sW[i] = dcnw[((o0 + o) * 64 + g * 8 + c) * 9 + k];
        }
        __syncthreads();

        const float* gbase = d_nbr_t + (size_t)(b * 8 + g) * HW * 8;
        const float* omb = d_om + (size_t)b * 216 * HW;

#pragma unroll 1
        for (int k = 0; k < 9; k++) {
            int ky = k / 3, kx = k - ky * 3;
            int ch = g * 9 + k;
            float vm0[8], vm1[8];
            {
                float dy = omb[(ch * 2) * HW + p0];
                float dx = omb[(ch * 2 + 1) * HW + p0];
                float m = omb[(144 + ch) * HW + p0];
                dcn_gather(gbase, x0, y, ky, kx, dy, dx, m, vm0);
            }
            {
                float dy = omb[(ch * 2) * HW + p1];
                float dx = omb[(ch * 2 + 1) * HW + p1];
                float m = omb[(144 + ch) * HW + p1];
                dcn_gather(gbase, x0 + 16, y, ky, kx, dy, dx, m, vm1);
            }
#pragma unroll
            for (int c = 0; c < 8; c++) {
                const unsigned long long* wq = (const unsigned long long*)&sW[(k * 8 + c) * 32];
                unsigned long long vp0 = pack2(vm0[c], vm0[c]);
                unsigned long long vp1 = pack2(vm1[c], vm1[c]);
#pragma unroll
                for (int half = 0; half < 2; half++) {
                    unsigned long long w[8];
#pragma unroll
                    for (int j = 0; j < 8; j++) w[j] = wq[half * 8 + j];
#pragma unroll
                    for (int j = 0; j < 8; j++) {
                        acc[0][half * 8 + j] = fma2(vp0, w[j], acc[0][half * 8 + j]);
                        acc[1][half * 8 + j] = fma2(vp1, w[j], acc[1][half * 8 + j]);
                    }
                }
            }
        }
    }

#pragma unroll
    for (int s = 0; s < 2; s++) {
        int p = (s == 0) ? p0 : p1;
#pragma unroll
        for (int j = 0; j < 16; j++) {
            float lo, hi;
            unpack2(acc[s][j], lo, hi);
            out[(b * 64 + o0 + 2 * j) * HW + p] = lo + dcnb[o0 + 2 * j];
            out[(b * 64 + o0 + 2 * j + 1) * HW + p] = hi + dcnb[o0 + 2 * j + 1];
        }
    }
}

// ---------- launch ----------
extern "C" void kernel_launch(void* const* d_in, const int* in_sizes, int n_in,
                              void* d_out, int out_size) {
    const float* nbr = (const float*)d_in[0];
    const float* ref = (const float*)d_in[1];
    const float* flow = (const float*)d_in[2];
    const float* conv1_w = (const float*)d_in[3];
    const float* conv1_b = (const float*)d_in[4];
    const float* om_w = (const float*)d_in[5];
    const float* om_b = (const float*)d_in[6];
    const float* dcn_w = (const float*)d_in[7];
    const float* dcn_b = (const float*)d_in[8];
    float* out = (float*)d_out;

    static bool attr_done = false;
    if (!attr_done) {
        cudaFuncSetAttribute(conv1_mma, cudaFuncAttributeMaxDynamicSharedMemorySize, 128000);
        cudaFuncSetAttribute(om_mma, cudaFuncAttributeMaxDynamicSharedMemorySize, 201728);
        attr_done = true;
    }

    prep_ref<<<(BAT * NF * HW / 4 + 255) / 256, 256>>>(ref);
    prep_flow<<<(BAT * 2 * HW / 4 + 255) / 256, 256>>>(flow);
    pack_w1<<<72, 256>>>(conv1_w);
    pack_wom<<<162, 256>>>(om_w);
    warp_kernel<<<(BAT * HW + 255) / 256, 256>>>(nbr, flow);
    transpose_kernel<<<(BAT * DG * HW + 255) / 256, 256>>>(nbr);

    conv1_mma<<<dim3(2, 256, BAT), 512, 128000>>>(conv1_b);
    om_mma<<<dim3(2, 256, BAT * 2), 512, 201728>>>(om_b, flow);
    dcn_kernel<<<dim3(8, 16, BAT * 2), 256>>>(dcn_w, dcn_b, out);
}

// round 7
// speedup vs baseline: 1.6911x; 1.0229x over previous
#include <cuda_runtime.h>
#include <stdint.h>
#include <math.h>

#define WID 256
#define HGT 256
#define HW  65536
#define BAT 2
#define NF  64
#define DG  8
#define CST 424
#define RST 136
#define SINB 3392

__device__ float d_nbr_t[BAT * DG * HW * 8];
__device__ float d_nwh[BAT * NF * HW];
__device__ float d_nwl[BAT * NF * HW];
__device__ float d_refh[BAT * NF * HW];
__device__ float d_refl[BAT * NF * HW];
__device__ float d_feah[BAT * NF * HW];
__device__ float d_feal[BAT * NF * HW];
__device__ float d_flwh[BAT * 2 * HW];
__device__ float d_flwl[BAT * 2 * HW];
__device__ float d_om[BAT * 216 * HW];
__device__ float d_w1ph[73728];
__device__ float d_w1pl[73728];
__device__ float d_womph[165888];
__device__ float d_wompl[165888];

__device__ __forceinline__ float rna(float x) {
    uint32_t u; asm("cvt.rna.tf32.f32 %0, %1;" : "=r"(u) : "f"(x));
    return __uint_as_float(u);
}
__device__ __forceinline__ void mma8(float* c, const uint4& a, uint32_t b0, uint32_t b1) {
    asm volatile("mma.sync.aligned.m16n8k8.row.col.f32.tf32.tf32.f32 "
                 "{%0,%1,%2,%3},{%4,%5,%6,%7},{%8,%9},{%0,%1,%2,%3};"
                 : "+f"(c[0]), "+f"(c[1]), "+f"(c[2]), "+f"(c[3])
                 : "r"(a.x), "r"(a.y), "r"(a.z), "r"(a.w), "r"(b0), "r"(b1));
}
__device__ __forceinline__ void cpa16(uint32_t d, const float* s, bool ok) {
    int sz = ok ? 16 : 0;
    asm volatile("cp.async.cg.shared.global [%0], [%1], 16, %2;" :: "r"(d), "l"(s), "r"(sz) : "memory");
}
__device__ __forceinline__ void cpa4(uint32_t d, const float* s, bool ok) {
    int sz = ok ? 4 : 0;
    asm volatile("cp.async.ca.shared.global [%0], [%1], 4, %2;" :: "r"(d), "l"(s), "r"(sz) : "memory");
}
__device__ __forceinline__ void cpcommit() { asm volatile("cp.async.commit_group;" ::: "memory"); }
__device__ __forceinline__ void cpwait() { asm volatile("cp.async.wait_group 0;" ::: "memory"); }

__device__ __forceinline__ unsigned long long pack2(float lo, float hi) {
    unsigned long long r; asm("mov.b64 %0, {%1, %2};" : "=l"(r) : "f"(lo), "f"(hi)); return r;
}
__device__ __forceinline__ unsigned long long fma2(unsigned long long a, unsigned long long b, unsigned long long c) {
    unsigned long long d; asm("fma.rn.f32x2 %0, %1, %2, %3;" : "=l"(d) : "l"(a), "l"(b), "l"(c)); return d;
}
__device__ __forceinline__ void unpack2(unsigned long long v, float& lo, float& hi) {
    asm("mov.b64 {%0, %1}, %2;" : "=f"(lo), "=f"(hi) : "l"(v));
}

// ---------- prep: hi/lo splits ----------
__global__ void prep_ref(const float* __restrict__ ref) {
    int i = blockIdx.x * blockDim.x + threadIdx.x;
    if (i >= BAT * NF * HW / 4) return;
    float4 v = ((const float4*)ref)[i];
    float4 h, l;
    h.x = rna(v.x); l.x = rna(v.x - h.x);
    h.y = rna(v.y); l.y = rna(v.y - h.y);
    h.z = rna(v.z); l.z = rna(v.z - h.z);
    h.w = rna(v.w); l.w = rna(v.w - h.w);
    ((float4*)d_refh)[i] = h; ((float4*)d_refl)[i] = l;
}
__global__ void prep_flow(const float* __restrict__ flow) {
    int i = blockIdx.x * blockDim.x + threadIdx.x;
    if (i >= BAT * 2 * HW / 4) return;
    float4 v = ((const float4*)flow)[i];
    float4 h, l;
    h.x = rna(v.x); l.x = rna(v.x - h.x);
    h.y = rna(v.y); l.y = rna(v.y - h.y);
    h.z = rna(v.z); l.z = rna(v.z - h.z);
    h.w = rna(v.w); l.w = rna(v.w - h.w);
    ((float4*)d_flwh)[i] = h; ((float4*)d_flwl)[i] = l;
}

// ---------- weight packing (A-fragment layout) ----------
__global__ void pack_w1(const float* __restrict__ w) {
    int idx = blockIdx.x * blockDim.x + threadIdx.x;
    if (idx >= 18432) return;
    int chunk = idx / 1152, r = idx % 1152;
    int tap = r / 128, r2 = r & 127;
    int m = r2 >> 5, lane = r2 & 31;
    int gr = lane >> 2, tq = lane & 3;
    float4 h, l; float* hp = &h.x; float* lp = &l.x;
#pragma unroll
    for (int vi = 0; vi < 4; vi++) {
        int oc = 16 * m + gr + (vi & 1) * 8;
        int c = 8 * chunk + tq + (vi >> 1) * 4;
        float v = w[(oc * 128 + c) * 9 + tap];
        float hv = rna(v); hp[vi] = hv; lp[vi] = rna(v - hv);
    }
    ((float4*)d_w1ph)[idx] = h; ((float4*)d_w1pl)[idx] = l;
}
__global__ void pack_wom(const float* __restrict__ w) {
    int idx = blockIdx.x * blockDim.x + threadIdx.x;
    if (idx >= 41472) return;
    int slice = idx / 20736, r = idx % 20736;
    int chunk = r / 2304, r1 = r % 2304;
    int tap = r1 / 256, r2 = r1 & 255;
    int m = r2 >> 5, lane = r2 & 31;
    int gr = lane >> 2, tq = lane & 3;
    float4 h, l; float* hp = &h.x; float* lp = &l.x;
#pragma unroll
    for (int vi = 0; vi < 4; vi++) {
        int oc = 128 * slice + 16 * m + gr + (vi & 1) * 8;
        int c = 8 * chunk + tq + (vi >> 1) * 4;
        float v = 0.f;
        if (oc < 216 && c < 66) v = w[(oc * 66 + c) * 9 + tap];
        float hv = rna(v); hp[vi] = hv; lp[vi] = rna(v - hv);
    }
    ((float4*)d_womph)[idx] = h; ((float4*)d_wompl)[idx] = l;
}

// ---------- transpose for dcn + warp ----------
__global__ void transpose_kernel(const float* __restrict__ nbr) {
    int idx = blockIdx.x * blockDim.x + threadIdx.x;
    if (idx >= BAT * DG * HW) return;
    int bg = idx >> 16, p = idx & 65535;
    int b = bg >> 3, g = bg & 7;
    float v[8];
#pragma unroll
    for (int c = 0; c < 8; c++) v[c] = nbr[((b * NF + g * 8 + c) * HW) + p];
    float4* dst = (float4*)&d_nbr_t[(size_t)idx * 8];
    dst[0] = make_float4(v[0], v[1], v[2], v[3]);
    dst[1] = make_float4(v[4], v[5], v[6], v[7]);
}

// ---------- warp (bilinear) reading channel-last d_nbr_t -> hi/lo ----------
__global__ void warp_kernel(const float* __restrict__ flow) {
    int idx = blockIdx.x * blockDim.x + threadIdx.x;
    if (idx >= BAT * HW) return;
    int b = idx >> 16, p = idx & 65535;
    int y = p >> 8, x = p & 255;
    float fx = flow[(b * 2 + 0) * HW + p];
    float fy = flow[(b * 2 + 1) * HW + p];
    float px = (float)x + fx, py = (float)y + fy;
    float x0f = floorf(px), y0f = floorf(py);
    int ix0 = (int)x0f, iy0 = (int)y0f;
    float wx = px - x0f, wy = py - y0f;
    bool vx0 = (unsigned)ix0 < WID, vx1 = (unsigned)(ix0 + 1) < WID;
    bool vy0 = (unsigned)iy0 < HGT, vy1 = (unsigned)(iy0 + 1) < HGT;
    float w00 = (vy0 && vx0) ? (1.f - wy) * (1.f - wx) : 0.f;
    float w01 = (vy0 && vx1) ? (1.f - wy) * wx : 0.f;
    float w10 = (vy1 && vx0) ? wy * (1.f - wx) : 0.f;
    float w11 = (vy1 && vx1) ? wy * wx : 0.f;
    int cx0 = min(max(ix0, 0), WID - 1), cx1 = min(max(ix0 + 1, 0), WID - 1);
    int cy0 = min(max(iy0, 0), HGT - 1), cy1 = min(max(iy0 + 1, 0), HGT - 1);
    size_t i00 = (size_t)(cy0 * WID + cx0) * 8;
    size_t i01 = (size_t)(cy0 * WID + cx1) * 8;
    size_t i10 = (size_t)(cy1 * WID + cx0) * 8;
    size_t i11 = (size_t)(cy1 * WID + cx1) * 8;

#pragma unroll 1
    for (int g = 0; g < 8; g++) {
        const float* gb = d_nbr_t + (size_t)(b * 8 + g) * HW * 8;
        float v[8];
#pragma unroll
        for (int half = 0; half < 2; half++) {
            float4 a00 = *(const float4*)(gb + i00 + 4 * half);
            float4 a01 = *(const float4*)(gb + i01 + 4 * half);
            float4 a10 = *(const float4*)(gb + i10 + 4 * half);
            float4 a11 = *(const float4*)(gb + i11 + 4 * half);
            v[4 * half + 0] = w00 * a00.x + w01 * a01.x + w10 * a10.x + w11 * a11.x;
            v[4 * half + 1] = w00 * a00.y + w01 * a01.y + w10 * a10.y + w11 * a11.y;
            v[4 * half + 2] = w00 * a00.z + w01 * a01.z + w10 * a10.z + w11 * a11.z;
            v[4 * half + 3] = w00 * a00.w + w01 * a01.w + w10 * a10.w + w11 * a11.w;
        }
#pragma unroll
        for (int c = 0; c < 8; c++) {
            float hv = rna(v[c]);
            size_t o = (size_t)(b * 64 + g * 8 + c) * HW + p;
            d_nwh[o] = hv;
            d_nwl[o] = rna(v[c] - hv);
        }
    }
}

// ---------- conv1 via tf32 MMA: 128->64, relu, out hi/lo ----------
__global__ __launch_bounds__(512, 1)
void conv1_mma(const float* __restrict__ bias) {
    extern __shared__ float sm[];
    float* sInH = sm;
    float* sInL = sm + 6784;
    float* sWH = sm + 13568;
    float* sWL = sm + 22784;

    int tid = threadIdx.x;
    int warp = tid >> 5, lane = tid & 31;
    int g = warp & 3, h = warp >> 2;
    int gr = lane >> 2, tq = lane & 3;
    int b = blockIdx.z, y = blockIdx.y, x0 = blockIdx.x * 128;

    float acc[4][4];
#pragma unroll
    for (int j = 0; j < 4; j++)
#pragma unroll
        for (int k = 0; k < 4; k++) acc[j][k] = 0.f;

    auto stage = [&](int chunk, int buf) {
        for (int i = tid; i < 1536; i += 512) {
            int pr = i >= 768;
            int ii = pr ? i - 768 : i;
            int c = ii / 96, rr = ii - c * 96;
            int r = rr >> 5, k = rr & 31;
            int cc = chunk * 8 + c;
            int gy = y + r - 1;
            bool ok = (unsigned)gy < HGT;
            int gyc = ok ? gy : 0;
            const float* arr = (cc < 64) ? (pr ? d_nwl : d_nwh) : (pr ? d_refl : d_refh);
            int ci = (cc < 64) ? cc : cc - 64;
            const float* src = arr + (size_t)(b * 64 + ci) * HW + gyc * 256 + x0 + 4 * k;
            float* db = (pr ? sInL : sInH) + buf * SINB;
            cpa16((uint32_t)__cvta_generic_to_shared(db + c * CST + r * RST + 4 + 4 * k), src, ok);
        }
        for (int i = tid; i < 96; i += 512) {
            int pr = i >= 48;
            int ii = pr ? i - 48 : i;
            int c = ii / 6, rr = ii - c * 6;
            int r = rr >> 1, side = rr & 1;
            int cc = chunk * 8 + c;
            int gy = y + r - 1;
            int gx = side ? x0 + 128 : x0 - 1;
            bool ok = ((unsigned)gy < HGT) && ((unsigned)gx < WID);
            int gyc = ((unsigned)gy < HGT) ? gy : 0;
            int gxc = ((unsigned)gx < WID) ? gx : 0;
            const float* arr = (cc < 64) ? (pr ? d_nwl : d_nwh) : (pr ? d_refl : d_refh);
            int ci = (cc < 64) ? cc : cc - 64;
            const float* src = arr + (size_t)(b * 64 + ci) * HW + gyc * 256 + gxc;
            float* db = (pr ? sInL : sInH) + buf * SINB;
            cpa4((uint32_t)__cvta_generic_to_shared(db + c * CST + r * RST + (side ? 132 : 3)), src, ok);
        }
        for (int i = tid; i < 2304; i += 512) {
            int pr = i >= 1152;
            int ii = pr ? i - 1152 : i;
            const float* src = (pr ? d_w1pl : d_w1ph) + chunk * 4608 + ii * 4;
            float* db = (pr ? sWL : sWH) + buf * 4608;
            cpa16((uint32_t)__cvta_generic_to_shared(db + ii * 4), src, true);
        }
        cpcommit();
    };

    stage(0, 0);
    int bbase = tq * CST + 32 * g + gr + 3;
    for (int it = 0; it < 16; it++) {
        int buf = it & 1;
        cpwait();
        __syncthreads();
        if (it + 1 < 16) stage(it + 1, buf ^ 1);

        const float* siH = sInH + buf * SINB;
        const float* siL = sInL + buf * SINB;
        const float* swH = sWH + buf * 4608;
        const float* swL = sWL + buf * 4608;
#pragma unroll
        for (int dy = 0; dy < 3; dy++) {
#pragma unroll
            for (int dx = 0; dx < 3; dx++) {
                int tap = dy * 3 + dx;
                int wi = ((tap * 4 + h) * 32 + lane) * 4;
                uint4 Ah = *(const uint4*)(swH + wi);
                uint4 Al = *(const uint4*)(swL + wi);
                int fb = bbase + dy * RST + dx;
#pragma unroll
                for (int j = 0; j < 4; j++) {
                    int fi = fb + 8 * j;
                    uint32_t bh0 = __float_as_uint(siH[fi]);
                    uint32_t bh1 = __float_as_uint(siH[fi + 4 * CST]);
                    uint32_t bl0 = __float_as_uint(siL[fi]);
                    uint32_t bl1 = __float_as_uint(siL[fi + 4 * CST]);
                    mma8(acc[j], Ah, bh0, bh1);
                    mma8(acc[j], Ah, bl0, bl1);
                    mma8(acc[j], Al, bh0, bh1);
                }
            }
        }
        __syncthreads();
    }

#pragma unroll
    for (int j = 0; j < 4; j++) {
        int x = x0 + 32 * g + 8 * j + 2 * tq;
        int pA = y * 256 + x;
#pragma unroll
        for (int k = 0; k < 4; k++) {
            int ch = 16 * h + gr + (k >= 2 ? 8 : 0);
            int p = pA + (k & 1);
            float v = acc[j][k] + bias[ch];
            v = fmaxf(v, 0.f);
            float hv = rna(v);
            size_t o = (size_t)(b * 64 + ch) * HW + p;
            d_feah[o] = hv;
            d_feal[o] = rna(v - hv);
        }
    }
}

// ---------- om via tf32 MMA: 66->216, fused epilogue ----------
__global__ __launch_bounds__(512, 1)
void om_mma(const float* __restrict__ bias, const float* __restrict__ flow) {
    extern __shared__ float sm[];
    float* sInH = sm;
    float* sInL = sm + 6784;
    float* sWH = sm + 13568;
    float* sWL = sm + 32000;

    int tid = threadIdx.x;
    int warp = tid >> 5, lane = tid & 31;
    int g = warp & 3, h = warp >> 2;
    int gr = lane >> 2, tq = lane & 3;
    int bz = blockIdx.z;
    int b = bz >> 1, slice = bz & 1;
    int y = blockIdx.y, x0 = blockIdx.x * 128;

    float acc[4][2][4];
#pragma unroll
    for (int j = 0; j < 4; j++)
#pragma unroll
        for (int mi = 0; mi < 2; mi++)
#pragma unroll
            for (int k = 0; k < 4; k++) acc[j][mi][k] = 0.f;

    auto stage = [&](int chunk, int buf) {
        for (int i = tid; i < 1536; i += 512) {
            int pr = i >= 768;
            int ii = pr ? i - 768 : i;
            int c = ii / 96, rr = ii - c * 96;
            int r = rr >> 5, k = rr & 31;
            int cc = chunk * 8 + c;
            int gy = y + r - 1;
            bool ok = ((unsigned)gy < HGT) && (cc < 66);
            int gyc = ((unsigned)gy < HGT) ? gy : 0;
            const float* arr = (cc < 64) ? (pr ? d_feal : d_feah) : (pr ? d_flwl : d_flwh);
            int ci, cm;
            if (cc < 64) { ci = cc; cm = 64; } else { ci = cc - 64; cm = 2; }
            if (ci >= cm) ci = 0;
            const float* src = arr + (size_t)(b * cm + ci) * HW + gyc * 256 + x0 + 4 * k;
            float* db = (pr ? sInL : sInH) + buf * SINB;
            cpa16((uint32_t)__cvta_generic_to_shared(db + c * CST + r * RST + 4 + 4 * k), src, ok);
        }
        for (int i = tid; i < 96; i += 512) {
            int pr = i >= 48;
            int ii = pr ? i - 48 : i;
            int c = ii / 6, rr = ii - c * 6;
            int r = rr >> 1, side = rr & 1;
            int cc = chunk * 8 + c;
            int gy = y + r - 1;
            int gx = side ? x0 + 128 : x0 - 1;
            bool ok = ((unsigned)gy < HGT) && ((unsigned)gx < WID) && (cc < 66);
            int gyc = ((unsigned)gy < HGT) ? gy : 0;
            int gxc = ((unsigned)gx < WID) ? gx : 0;
            const float* arr = (cc < 64) ? (pr ? d_feal : d_feah) : (pr ? d_flwl : d_flwh);
            int ci, cm;
            if (cc < 64) { ci = cc; cm = 64; } else { ci = cc - 64; cm = 2; }
            if (ci >= cm) ci = 0;
            const float* src = arr + (size_t)(b * cm + ci) * HW + gyc * 256 + gxc;
            float* db = (pr ? sInL : sInH) + buf * SINB;
            cpa4((uint32_t)__cvta_generic_to_shared(db + c * CST + r * RST + (side ? 132 : 3)), src, ok);
        }
        for (int i = tid; i < 4608; i += 512) {
            int pr = i >= 2304;
            int ii = pr ? i - 2304 : i;
            const float* src = (pr ? d_wompl : d_womph) + (slice * 9 + chunk) * 9216 + ii * 4;
            float* db = (pr ? sWL : sWH) + buf * 9216;
            cpa16((uint32_t)__cvta_generic_to_shared(db + ii * 4), src, true);
        }
        cpcommit();
    };

    stage(0, 0);
    int bbase = tq * CST + 32 * g + gr + 3;
    for (int it = 0; it < 9; it++) {
        int buf = it & 1;
        cpwait();
        __syncthreads();
        if (it + 1 < 9) stage(it + 1, buf ^ 1);

        const float* siH = sInH + buf * SINB;
        const float* siL = sInL + buf * SINB;
        const float* swH = sWH + buf * 9216;
        const float* swL = sWL + buf * 9216;
#pragma unroll
        for (int dy = 0; dy < 3; dy++) {
#pragma unroll
            for (int dx = 0; dx < 3; dx++) {
                int tap = dy * 3 + dx;
                int wi = ((tap * 8 + 2 * h) * 32 + lane) * 4;
                uint4 Ah0 = *(const uint4*)(swH + wi);
                uint4 Ah1 = *(const uint4*)(swH + wi + 128);
                uint4 Al0 = *(const uint4*)(swL + wi);
                uint4 Al1 = *(const uint4*)(swL + wi + 128);
                int fb = bbase + dy * RST + dx;
#pragma unroll
                for (int j = 0; j < 4; j++) {
                    int fi = fb + 8 * j;
                    uint32_t bh0 = __float_as_uint(siH[fi]);
                    uint32_t bh1 = __float_as_uint(siH[fi + 4 * CST]);
                    uint32_t bl0 = __float_as_uint(siL[fi]);
                    uint32_t bl1 = __float_as_uint(siL[fi + 4 * CST]);
                    mma8(acc[j][0], Ah0, bh0, bh1);
                    mma8(acc[j][0], Ah0, bl0, bl1);
                    mma8(acc[j][0], Al0, bh0, bh1);
                    mma8(acc[j][1], Ah1, bh0, bh1);
                    mma8(acc[j][1], Ah1, bl0, bl1);
                    mma8(acc[j][1], Al1, bh0, bh1);
                }
            }
        }
        __syncthreads();
    }

    int ocb = 128 * slice;
#pragma unroll
    for (int j = 0; j < 4; j++) {
        int x = x0 + 32 * g + 8 * j + 2 * tq;
        int pA = y * 256 + x;
#pragma unroll
        for (int mi = 0; mi < 2; mi++) {
            int chA = ocb + 16 * (2 * h + mi) + gr;
#pragma unroll
            for (int k = 0; k < 4; k++) {
                int ch = chA + (k >= 2 ? 8 : 0);
                if (ch >= 216) continue;
                int p = pA + (k & 1);
                float v = acc[j][mi][k] + bias[ch];
                if (ch < 144) {
                    v += (gr & 1) ? flow[(b * 2 + 0) * HW + p]
                                  : flow[(b * 2 + 1) * HW + p];
                } else {
                    v = 1.f / (1.f + expf(-v));
                }
                d_om[(size_t)(b * 216 + ch) * HW + p] = v;
            }
        }
    }
}

// ---------- dcn: 2 px/thread, ALL 64 oc per block (no duplicated gathers) ----
__device__ __forceinline__ void dcn_gather(const float* __restrict__ gbase,
                                           int x, int y, int ky, int kx,
                                           float dy, float dx, float m, float* vm) {
    float spy = (float)(y - 1 + ky) + dy;
    float spx = (float)(x - 1 + kx) + dx;
    float y0f = floorf(spy), x0f = floorf(spx);
    int iy0 = (int)y0f, ix0 = (int)x0f;
    float wy = spy - y0f, wx = spx - x0f;
    float v[8];
#pragma unroll
    for (int c = 0; c < 8; c++) v[c] = 0.f;
    float wts[4] = {(1.f - wy) * (1.f - wx), (1.f - wy) * wx, wy * (1.f - wx), wy * wx};
    int ys[4] = {iy0, iy0, iy0 + 1, iy0 + 1};
    int xs[4] = {ix0, ix0 + 1, ix0, ix0 + 1};
#pragma unroll
    for (int t = 0; t < 4; t++) {
        int yi = ys[t], xi = xs[t];
        if ((unsigned)yi < HGT && (unsigned)xi < WID) {
            const float4* q = (const float4*)(gbase + (size_t)(yi * WID + xi) * 8);
            float4 a = q[0];
            float4 bb = q[1];
            float wt = wts[t];
            v[0] += wt * a.x;  v[1] += wt * a.y;  v[2] += wt * a.z;  v[3] += wt * a.w;
            v[4] += wt * bb.x; v[5] += wt * bb.y; v[6] += wt * bb.z; v[7] += wt * bb.w;
        }
    }
#pragma unroll
    for (int c = 0; c < 8; c++) vm[c] = v[c] * m;
}

__global__ __launch_bounds__(256, 1)
void dcn_kernel(const float* __restrict__ dcnw, const float* __restrict__ dcnb,
                float* __restrict__ out) {
    __shared__ __align__(16) float sW[4608];   // [(k*8+c)*64 + o]

    int b = blockIdx.z;
    int tx = threadIdx.x & 15, ty = threadIdx.x >> 4;
    int x0 = blockIdx.x * 32 + tx;
    int y = blockIdx.y * 16 + ty;
    int p0 = y * WID + x0, p1 = p0 + 16;

    unsigned long long acc[2][32];
#pragma unroll
    for (int s = 0; s < 2; s++)
#pragma unroll
        for (int j = 0; j < 32; j++) acc[s][j] = 0ull;

    for (int g = 0; g < 8; g++) {
        __syncthreads();
        for (int i = threadIdx.x; i < 4608; i += 256) {
            int o = i & 63, r = i >> 6;
            int c = r & 7, k = r >> 3;
            sW[i] = dcnw[(o * 64 + g * 8 + c) * 9 + k];
        }
        __syncthreads();

        const float* gbase = d_nbr_t + (size_t)(b * 8 + g) * HW * 8;
        const float* omb = d_om + (size_t)b * 216 * HW;

#pragma unroll 1
        for (int k = 0; k < 9; k++) {
            int ky = k / 3, kx = k - ky * 3;
            int ch = g * 9 + k;
            float vm0[8], vm1[8];
            {
                float dy = omb[(ch * 2) * HW + p0];
                float dx = omb[(ch * 2 + 1) * HW + p0];
                float m = omb[(144 + ch) * HW + p0];
                dcn_gather(gbase, x0, y, ky, kx, dy, dx, m, vm0);
            }
            {
                float dy = omb[(ch * 2) * HW + p1];
                float dx = omb[(ch * 2 + 1) * HW + p1];
                float m = omb[(144 + ch) * HW + p1];
                dcn_gather(gbase, x0 + 16, y, ky, kx, dy, dx, m, vm1);
            }
#pragma unroll
            for (int c = 0; c < 8; c++) {
                const unsigned long long* wq = (const unsigned long long*)&sW[(k * 8 + c) * 64];
                unsigned long long vp0 = pack2(vm0[c], vm0[c]);
                unsigned long long vp1 = pack2(vm1[c], vm1[c]);
#pragma unroll
                for (int j = 0; j < 32; j++) {
                    unsigned long long w = wq[j];
                    acc[0][j] = fma2(vp0, w, acc[0][j]);
                    acc[1][j] = fma2(vp1, w, acc[1][j]);
                }
            }
        }
    }

#pragma unroll
    for (int s = 0; s < 2; s++) {
        int p = (s == 0) ? p0 : p1;
#pragma unroll
        for (int j = 0; j < 32; j++) {
            float lo, hi;
            unpack2(acc[s][j], lo, hi);
            out[(b * 64 + 2 * j) * HW + p] = lo + dcnb[2 * j];
            out[(b * 64 + 2 * j + 1) * HW + p] = hi + dcnb[2 * j + 1];
        }
    }
}

// ---------- launch ----------
extern "C" void kernel_launch(void* const* d_in, const int* in_sizes, int n_in,
                              void* d_out, int out_size) {
    const float* nbr = (const float*)d_in[0];
    const float* ref = (const float*)d_in[1];
    const float* flow = (const float*)d_in[2];
    const float* conv1_w = (const float*)d_in[3];
    const float* conv1_b = (const float*)d_in[4];
    const float* om_w = (const float*)d_in[5];
    const float* om_b = (const float*)d_in[6];
    const float* dcn_w = (const float*)d_in[7];
    const float* dcn_b = (const float*)d_in[8];
    float* out = (float*)d_out;

    static bool attr_done = false;
    if (!attr_done) {
        cudaFuncSetAttribute(conv1_mma, cudaFuncAttributeMaxDynamicSharedMemorySize, 128000);
        cudaFuncSetAttribute(om_mma, cudaFuncAttributeMaxDynamicSharedMemorySize, 201728);
        attr_done = true;
    }

    prep_ref<<<(BAT * NF * HW / 4 + 255) / 256, 256>>>(ref);
    prep_flow<<<(BAT * 2 * HW / 4 + 255) / 256, 256>>>(flow);
    pack_w1<<<72, 256>>>(conv1_w);
    pack_wom<<<162, 256>>>(om_w);
    transpose_kernel<<<(BAT * DG * HW + 255) / 256, 256>>>(nbr);
    warp_kernel<<<(BAT * HW + 255) / 256, 256>>>(flow);

    conv1_mma<<<dim3(2, 256, BAT), 512, 128000>>>(conv1_b);
    om_mma<<<dim3(2, 256, BAT * 2), 512, 201728>>>(om_b, flow);
    dcn_kernel<<<dim3(8, 16, BAT), 256>>>(dcn_w, dcn_b, out);
}

// round 9
// speedup vs baseline: 1.8603x; 1.1001x over previous
#include <cuda_runtime.h>
#include <stdint.h>
#include <math.h>

#define WID 256
#define HGT 256
#define HW  65536
#define BAT 2
#define NF  64
#define DG  8
#define CST 424
#define RST 136
#define SINB 3392

__device__ float d_nbr_t[BAT * DG * HW * 8];
__device__ float d_nwh[BAT * NF * HW];
__device__ float d_nwl[BAT * NF * HW];
__device__ float d_refh[BAT * NF * HW];
__device__ float d_refl[BAT * NF * HW];
__device__ float d_feah[BAT * NF * HW];
__device__ float d_feal[BAT * NF * HW];
__device__ float d_flwh[BAT * 2 * HW];
__device__ float d_flwl[BAT * 2 * HW];
__device__ float d_om[BAT * 216 * HW];
__device__ float d_w1ph[73728];
__device__ float d_w1pl[73728];
__device__ float d_womph[165888];
__device__ float d_wompl[165888];
__device__ float d_wdph[36864];
__device__ float d_wdpl[36864];

__device__ __forceinline__ float rna(float x) {
    uint32_t u; asm("cvt.rna.tf32.f32 %0, %1;" : "=r"(u) : "f"(x));
    return __uint_as_float(u);
}
__device__ __forceinline__ void mma8(float* c, const uint4& a, uint32_t b0, uint32_t b1) {
    asm volatile("mma.sync.aligned.m16n8k8.row.col.f32.tf32.tf32.f32 "
                 "{%0,%1,%2,%3},{%4,%5,%6,%7},{%8,%9},{%0,%1,%2,%3};"
                 : "+f"(c[0]), "+f"(c[1]), "+f"(c[2]), "+f"(c[3])
                 : "r"(a.x), "r"(a.y), "r"(a.z), "r"(a.w), "r"(b0), "r"(b1));
}
__device__ __forceinline__ void cpa16(uint32_t d, const float* s, bool ok) {
    int sz = ok ? 16 : 0;
    asm volatile("cp.async.cg.shared.global [%0], [%1], 16, %2;" :: "r"(d), "l"(s), "r"(sz) : "memory");
}
__device__ __forceinline__ void cpa4(uint32_t d, const float* s, bool ok) {
    int sz = ok ? 4 : 0;
    asm volatile("cp.async.ca.shared.global [%0], [%1], 4, %2;" :: "r"(d), "l"(s), "r"(sz) : "memory");
}
__device__ __forceinline__ void cpcommit() { asm volatile("cp.async.commit_group;" ::: "memory"); }
__device__ __forceinline__ void cpwait() { asm volatile("cp.async.wait_group 0;" ::: "memory"); }

// ---------- fused prep: hi/lo splits + all weight packs (one launch) ----------
#define PN0 2097152           // prep_ref float4s  (BAT*NF*HW/4)
#define PN1 65536             // prep_flow float4s (BAT*2*HW/4)
#define PN2 18432             // pack_w1 frags
#define PN3 41472             // pack_wom frags
#define PN4 9216              // pack_wdcn frags
__global__ void prep_all(const float* __restrict__ ref, const float* __restrict__ flow,
                         const float* __restrict__ w1, const float* __restrict__ wom,
                         const float* __restrict__ wd) {
    int idx = blockIdx.x * blockDim.x + threadIdx.x;
    if (idx < PN0) {
        float4 v = ((const float4*)ref)[idx];
        float4 h, l;
        h.x = rna(v.x); l.x = rna(v.x - h.x);
        h.y = rna(v.y); l.y = rna(v.y - h.y);
        h.z = rna(v.z); l.z = rna(v.z - h.z);
        h.w = rna(v.w); l.w = rna(v.w - h.w);
        ((float4*)d_refh)[idx] = h; ((float4*)d_refl)[idx] = l;
        return;
    }
    idx -= PN0;
    if (idx < PN1) {
        float4 v = ((const float4*)flow)[idx];
        float4 h, l;
        h.x = rna(v.x); l.x = rna(v.x - h.x);
        h.y = rna(v.y); l.y = rna(v.y - h.y);
        h.z = rna(v.z); l.z = rna(v.z - h.z);
        h.w = rna(v.w); l.w = rna(v.w - h.w);
        ((float4*)d_flwh)[idx] = h; ((float4*)d_flwl)[idx] = l;
        return;
    }
    idx -= PN1;
    if (idx < PN2) {
        int chunk = idx / 1152, r = idx % 1152;
        int tap = r / 128, r2 = r & 127;
        int m = r2 >> 5, lane = r2 & 31;
        int gr = lane >> 2, tq = lane & 3;
        float4 h, l; float* hp = &h.x; float* lp = &l.x;
#pragma unroll
        for (int vi = 0; vi < 4; vi++) {
            int oc = 16 * m + gr + (vi & 1) * 8;
            int c = 8 * chunk + tq + (vi >> 1) * 4;
            float v = w1[(oc * 128 + c) * 9 + tap];
            float hv = rna(v); hp[vi] = hv; lp[vi] = rna(v - hv);
        }
        ((float4*)d_w1ph)[idx] = h; ((float4*)d_w1pl)[idx] = l;
        return;
    }
    idx -= PN2;
    if (idx < PN3) {
        int slice = idx / 20736, r = idx % 20736;
        int chunk = r / 2304, r1 = r % 2304;
        int tap = r1 / 256, r2 = r1 & 255;
        int m = r2 >> 5, lane = r2 & 31;
        int gr = lane >> 2, tq = lane & 3;
        float4 h, l; float* hp = &h.x; float* lp = &l.x;
#pragma unroll
        for (int vi = 0; vi < 4; vi++) {
            int oc = 128 * slice + 16 * m + gr + (vi & 1) * 8;
            int c = 8 * chunk + tq + (vi >> 1) * 4;
            float v = 0.f;
            if (oc < 216 && c < 66) v = wom[(oc * 66 + c) * 9 + tap];
            float hv = rna(v); hp[vi] = hv; lp[vi] = rna(v - hv);
        }
        ((float4*)d_womph)[idx] = h; ((float4*)d_wompl)[idx] = l;
        return;
    }
    idx -= PN3;
    if (idx < PN4) {
        int g = idx / 1152, r = idx % 1152;
        int tap = r / 128, r2 = r & 127;
        int mt = r2 >> 5, lane = r2 & 31;
        int gr = lane >> 2, tq = lane & 3;
        float4 h, l; float* hp = &h.x; float* lp = &l.x;
#pragma unroll
        for (int vi = 0; vi < 4; vi++) {
            int oc = 16 * mt + gr + (vi & 1) * 8;
            int kc = tq + (vi >> 1) * 4;
            float v = wd[(oc * 64 + g * 8 + kc) * 9 + tap];
            float hv = rna(v); hp[vi] = hv; lp[vi] = rna(v - hv);
        }
        ((float4*)d_wdph)[idx] = h; ((float4*)d_wdpl)[idx] = l;
    }
}

// ---------- transpose for dcn + warp ----------
__global__ void transpose_kernel(const float* __restrict__ nbr) {
    int idx = blockIdx.x * blockDim.x + threadIdx.x;
    if (idx >= BAT * DG * HW) return;
    int bg = idx >> 16, p = idx & 65535;
    int b = bg >> 3, g = bg & 7;
    float v[8];
#pragma unroll
    for (int c = 0; c < 8; c++) v[c] = nbr[((b * NF + g * 8 + c) * HW) + p];
    float4* dst = (float4*)&d_nbr_t[(size_t)idx * 8];
    dst[0] = make_float4(v[0], v[1], v[2], v[3]);
    dst[1] = make_float4(v[4], v[5], v[6], v[7]);
}

// ---------- warp (bilinear) reading channel-last d_nbr_t -> hi/lo ----------
__global__ void warp_kernel(const float* __restrict__ flow) {
    int idx = blockIdx.x * blockDim.x + threadIdx.x;
    if (idx >= BAT * HW) return;
    int b = idx >> 16, p = idx & 65535;
    int y = p >> 8, x = p & 255;
    float fx = flow[(b * 2 + 0) * HW + p];
    float fy = flow[(b * 2 + 1) * HW + p];
    float px = (float)x + fx, py = (float)y + fy;
    float x0f = floorf(px), y0f = floorf(py);
    int ix0 = (int)x0f, iy0 = (int)y0f;
    float wx = px - x0f, wy = py - y0f;
    bool vx0 = (unsigned)ix0 < WID, vx1 = (unsigned)(ix0 + 1) < WID;
    bool vy0 = (unsigned)iy0 < HGT, vy1 = (unsigned)(iy0 + 1) < HGT;
    float w00 = (vy0 && vx0) ? (1.f - wy) * (1.f - wx) : 0.f;
    float w01 = (vy0 && vx1) ? (1.f - wy) * wx : 0.f;
    float w10 = (vy1 && vx0) ? wy * (1.f - wx) : 0.f;
    float w11 = (vy1 && vx1) ? wy * wx : 0.f;
    int cx0 = min(max(ix0, 0), WID - 1), cx1 = min(max(ix0 + 1, 0), WID - 1);
    int cy0 = min(max(iy0, 0), HGT - 1), cy1 = min(max(iy0 + 1, 0), HGT - 1);
    size_t i00 = (size_t)(cy0 * WID + cx0) * 8;
    size_t i01 = (size_t)(cy0 * WID + cx1) * 8;
    size_t i10 = (size_t)(cy1 * WID + cx0) * 8;
    size_t i11 = (size_t)(cy1 * WID + cx1) * 8;

#pragma unroll 1
    for (int g = 0; g < 8; g++) {
        const float* gb = d_nbr_t + (size_t)(b * 8 + g) * HW * 8;
        float v[8];
#pragma unroll
        for (int half = 0; half < 2; half++) {
            float4 a00 = *(const float4*)(gb + i00 + 4 * half);
            float4 a01 = *(const float4*)(gb + i01 + 4 * half);
            float4 a10 = *(const float4*)(gb + i10 + 4 * half);
            float4 a11 = *(const float4*)(gb + i11 + 4 * half);
            v[4 * half + 0] = w00 * a00.x + w01 * a01.x + w10 * a10.x + w11 * a11.x;
            v[4 * half + 1] = w00 * a00.y + w01 * a01.y + w10 * a10.y + w11 * a11.y;
            v[4 * half + 2] = w00 * a00.z + w01 * a01.z + w10 * a10.z + w11 * a11.z;
            v[4 * half + 3] = w00 * a00.w + w01 * a01.w + w10 * a10.w + w11 * a11.w;
        }
#pragma unroll
        for (int c = 0; c < 8; c++) {
            float hv = rna(v[c]);
            size_t o = (size_t)(b * 64 + g * 8 + c) * HW + p;
            d_nwh[o] = hv;
            d_nwl[o] = rna(v[c] - hv);
        }
    }
}

// ---------- conv1 via tf32 MMA: 128->64, relu, out hi/lo ----------
__global__ __launch_bounds__(512, 1)
void conv1_mma(const float* __restrict__ bias) {
    extern __shared__ float sm[];
    float* sInH = sm;
    float* sInL = sm + 6784;
    float* sWH = sm + 13568;
    float* sWL = sm + 22784;

    int tid = threadIdx.x;
    int warp = tid >> 5, lane = tid & 31;
    int g = warp & 3, h = warp >> 2;
    int gr = lane >> 2, tq = lane & 3;
    int b = blockIdx.z, y = blockIdx.y, x0 = blockIdx.x * 128;

    float acc[4][4];
#pragma unroll
    for (int j = 0; j < 4; j++)
#pragma unroll
        for (int k = 0; k < 4; k++) acc[j][k] = 0.f;

    auto stage = [&](int chunk, int buf) {
        for (int i = tid; i < 1536; i += 512) {
            int pr = i >= 768;
            int ii = pr ? i - 768 : i;
            int c = ii / 96, rr = ii - c * 96;
            int r = rr >> 5, k = rr & 31;
            int cc = chunk * 8 + c;
            int gy = y + r - 1;
            bool ok = (unsigned)gy < HGT;
            int gyc = ok ? gy : 0;
            const float* arr = (cc < 64) ? (pr ? d_nwl : d_nwh) : (pr ? d_refl : d_refh);
            int ci = (cc < 64) ? cc : cc - 64;
            const float* src = arr + (size_t)(b * 64 + ci) * HW + gyc * 256 + x0 + 4 * k;
            float* db = (pr ? sInL : sInH) + buf * SINB;
            cpa16((uint32_t)__cvta_generic_to_shared(db + c * CST + r * RST + 4 + 4 * k), src, ok);
        }
        for (int i = tid; i < 96; i += 512) {
            int pr = i >= 48;
            int ii = pr ? i - 48 : i;
            int c = ii / 6, rr = ii - c * 6;
            int r = rr >> 1, side = rr & 1;
            int cc = chunk * 8 + c;
            int gy = y + r - 1;
            int gx = side ? x0 + 128 : x0 - 1;
            bool ok = ((unsigned)gy < HGT) && ((unsigned)gx < WID);
            int gyc = ((unsigned)gy < HGT) ? gy : 0;
            int gxc = ((unsigned)gx < WID) ? gx : 0;
            const float* arr = (cc < 64) ? (pr ? d_nwl : d_nwh) : (pr ? d_refl : d_refh);
            int ci = (cc < 64) ? cc : cc - 64;
            const float* src = arr + (size_t)(b * 64 + ci) * HW + gyc * 256 + gxc;
            float* db = (pr ? sInL : sInH) + buf * SINB;
            cpa4((uint32_t)__cvta_generic_to_shared(db + c * CST + r * RST + (side ? 132 : 3)), src, ok);
        }
        for (int i = tid; i < 2304; i += 512) {
            int pr = i >= 1152;
            int ii = pr ? i - 1152 : i;
            const float* src = (pr ? d_w1pl : d_w1ph) + chunk * 4608 + ii * 4;
            float* db = (pr ? sWL : sWH) + buf * 4608;
            cpa16((uint32_t)__cvta_generic_to_shared(db + ii * 4), src, true);
        }
        cpcommit();
    };

    stage(0, 0);
    int bbase = tq * CST + 32 * g + gr + 3;
    for (int it = 0; it < 16; it++) {
        int buf = it & 1;
        cpwait();
        __syncthreads();
        if (it + 1 < 16) stage(it + 1, buf ^ 1);

        const float* siH = sInH + buf * SINB;
        const float* siL = sInL + buf * SINB;
        const float* swH = sWH + buf * 4608;
        const float* swL = sWL + buf * 4608;
#pragma unroll
        for (int dy = 0; dy < 3; dy++) {
#pragma unroll
            for (int dx = 0; dx < 3; dx++) {
                int tap = dy * 3 + dx;
                int wi = ((tap * 4 + h) * 32 + lane) * 4;
                uint4 Ah = *(const uint4*)(swH + wi);
                uint4 Al = *(const uint4*)(swL + wi);
                int fb = bbase + dy * RST + dx;
#pragma unroll
                for (int j = 0; j < 4; j++) {
                    int fi = fb + 8 * j;
                    uint32_t bh0 = __float_as_uint(siH[fi]);
                    uint32_t bh1 = __float_as_uint(siH[fi + 4 * CST]);
                    uint32_t bl0 = __float_as_uint(siL[fi]);
                    uint32_t bl1 = __float_as_uint(siL[fi + 4 * CST]);
                    mma8(acc[j], Ah, bh0, bh1);
                    mma8(acc[j], Ah, bl0, bl1);
                    mma8(acc[j], Al, bh0, bh1);
                }
            }
        }
        __syncthreads();
    }

#pragma unroll
    for (int j = 0; j < 4; j++) {
        int x = x0 + 32 * g + 8 * j + 2 * tq;
        int pA = y * 256 + x;
#pragma unroll
        for (int k = 0; k < 4; k++) {
            int ch = 16 * h + gr + (k >= 2 ? 8 : 0);
            int p = pA + (k & 1);
            float v = acc[j][k] + bias[ch];
            v = fmaxf(v, 0.f);
            float hv = rna(v);
            size_t o = (size_t)(b * 64 + ch) * HW + p;
            d_feah[o] = hv;
            d_feal[o] = rna(v - hv);
        }
    }
}

// ---------- om via tf32 MMA: 66->216, fused epilogue ----------
__global__ __launch_bounds__(512, 1)
void om_mma(const float* __restrict__ bias, const float* __restrict__ flow) {
    extern __shared__ float sm[];
    float* sInH = sm;
    float* sInL = sm + 6784;
    float* sWH = sm + 13568;
    float* sWL = sm + 32000;

    int tid = threadIdx.x;
    int warp = tid >> 5, lane = tid & 31;
    int g = warp & 3, h = warp >> 2;
    int gr = lane >> 2, tq = lane & 3;
    int bz = blockIdx.z;
    int b = bz >> 1, slice = bz & 1;
    int y = blockIdx.y, x0 = blockIdx.x * 128;

    float acc[4][2][4];
#pragma unroll
    for (int j = 0; j < 4; j++)
#pragma unroll
        for (int mi = 0; mi < 2; mi++)
#pragma unroll
            for (int k = 0; k < 4; k++) acc[j][mi][k] = 0.f;

    auto stage = [&](int chunk, int buf) {
        for (int i = tid; i < 1536; i += 512) {
            int pr = i >= 768;
            int ii = pr ? i - 768 : i;
            int c = ii / 96, rr = ii - c * 96;
            int r = rr >> 5, k = rr & 31;
            int cc = chunk * 8 + c;
            int gy = y + r - 1;
            bool ok = ((unsigned)gy < HGT) && (cc < 66);
            int gyc = ((unsigned)gy < HGT) ? gy : 0;
            const float* arr = (cc < 64) ? (pr ? d_feal : d_feah) : (pr ? d_flwl : d_flwh);
            int ci, cm;
            if (cc < 64) { ci = cc; cm = 64; } else { ci = cc - 64; cm = 2; }
            if (ci >= cm) ci = 0;
            const float* src = arr + (size_t)(b * cm + ci) * HW + gyc * 256 + x0 + 4 * k;
            float* db = (pr ? sInL : sInH) + buf * SINB;
            cpa16((uint32_t)__cvta_generic_to_shared(db + c * CST + r * RST + 4 + 4 * k), src, ok);
        }
        for (int i = tid; i < 96; i += 512) {
            int pr = i >= 48;
            int ii = pr ? i - 48 : i;
            int c = ii / 6, rr = ii - c * 6;
            int r = rr >> 1, side = rr & 1;
            int cc = chunk * 8 + c;
            int gy = y + r - 1;
            int gx = side ? x0 + 128 : x0 - 1;
            bool ok = ((unsigned)gy < HGT) && ((unsigned)gx < WID) && (cc < 66);
            int gyc = ((unsigned)gy < HGT) ? gy : 0;
            int gxc = ((unsigned)gx < WID) ? gx : 0;
            const float* arr = (cc < 64) ? (pr ? d_feal : d_feah) : (pr ? d_flwl : d_flwh);
            int ci, cm;
            if (cc < 64) { ci = cc; cm = 64; } else { ci = cc - 64; cm = 2; }
            if (ci >= cm) ci = 0;
            const float* src = arr + (size_t)(b * cm + ci) * HW + gyc * 256 + gxc;
            float* db = (pr ? sInL : sInH) + buf * SINB;
            cpa4((uint32_t)__cvta_generic_to_shared(db + c * CST + r * RST + (side ? 132 : 3)), src, ok);
        }
        for (int i = tid; i < 4608; i += 512) {
            int pr = i >= 2304;
            int ii = pr ? i - 2304 : i;
            const float* src = (pr ? d_wompl : d_womph) + (slice * 9 + chunk) * 9216 + ii * 4;
            float* db = (pr ? sWL : sWH) + buf * 9216;
            cpa16((uint32_t)__cvta_generic_to_shared(db + ii * 4), src, true);
        }
        cpcommit();
    };

    stage(0, 0);
    int bbase = tq * CST + 32 * g + gr + 3;
    for (int it = 0; it < 9; it++) {
        int buf = it & 1;
        cpwait();
        __syncthreads();
        if (it + 1 < 9) stage(it + 1, buf ^ 1);

        const float* siH = sInH + buf * SINB;
        const float* siL = sInL + buf * SINB;
        const float* swH = sWH + buf * 9216;
        const float* swL = sWL + buf * 9216;
#pragma unroll
        for (int dy = 0; dy < 3; dy++) {
#pragma unroll
            for (int dx = 0; dx < 3; dx++) {
                int tap = dy * 3 + dx;
                int wi = ((tap * 8 + 2 * h) * 32 + lane) * 4;
                uint4 Ah0 = *(const uint4*)(swH + wi);
                uint4 Ah1 = *(const uint4*)(swH + wi + 128);
                uint4 Al0 = *(const uint4*)(swL + wi);
                uint4 Al1 = *(const uint4*)(swL + wi + 128);
                int fb = bbase + dy * RST + dx;
#pragma unroll
                for (int j = 0; j < 4; j++) {
                    int fi = fb + 8 * j;
                    uint32_t bh0 = __float_as_uint(siH[fi]);
                    uint32_t bh1 = __float_as_uint(siH[fi + 4 * CST]);
                    uint32_t bl0 = __float_as_uint(siL[fi]);
                    uint32_t bl1 = __float_as_uint(siL[fi + 4 * CST]);
                    mma8(acc[j][0], Ah0, bh0, bh1);
                    mma8(acc[j][0], Ah0, bl0, bl1);
                    mma8(acc[j][0], Al0, bh0, bh1);
                    mma8(acc[j][1], Ah1, bh0, bh1);
                    mma8(acc[j][1], Ah1, bl0, bl1);
                    mma8(acc[j][1], Al1, bh0, bh1);
                }
            }
        }
        __syncthreads();
    }

    int ocb = 128 * slice;
#pragma unroll
    for (int j = 0; j < 4; j++) {
        int x = x0 + 32 * g + 8 * j + 2 * tq;
        int pA = y * 256 + x;
#pragma unroll
        for (int mi = 0; mi < 2; mi++) {
            int chA = ocb + 16 * (2 * h + mi) + gr;
#pragma unroll
            for (int k = 0; k < 4; k++) {
                int ch = chA + (k >= 2 ? 8 : 0);
                if (ch >= 216) continue;
                int p = pA + (k & 1);
                float v = acc[j][mi][k] + bias[ch];
                if (ch < 144) {
                    v += (gr & 1) ? flow[(b * 2 + 0) * HW + p]
                                  : flow[(b * 2 + 1) * HW + p];
                } else {
                    v = 1.f / (1.f + expf(-v));
                }
                d_om[(size_t)(b * 216 + ch) * HW + p] = v;
            }
        }
    }
}

// ---------- dcn via tf32 MMA: gathers -> per-warp B panel -> HMMA ----------
__device__ __forceinline__ void dcn_gather(const float* __restrict__ gbase,
                                           int x, int y, int ky, int kx,
                                           float dy, float dx, float m, float* vm) {
    float spy = (float)(y - 1 + ky) + dy;
    float spx = (float)(x - 1 + kx) + dx;
    float y0f = floorf(spy), x0f = floorf(spx);
    int iy0 = (int)y0f, ix0 = (int)x0f;
    float wy = spy - y0f, wx = spx - x0f;
    float v[8];
#pragma unroll
    for (int c = 0; c < 8; c++) v[c] = 0.f;
    float wts[4] = {(1.f - wy) * (1.f - wx), (1.f - wy) * wx, wy * (1.f - wx), wy * wx};
    int ys[4] = {iy0, iy0, iy0 + 1, iy0 + 1};
    int xs[4] = {ix0, ix0 + 1, ix0, ix0 + 1};
#pragma unroll
    for (int t = 0; t < 4; t++) {
        int yi = ys[t], xi = xs[t];
        if ((unsigned)yi < HGT && (unsigned)xi < WID) {
            const float4* q = (const float4*)(gbase + (size_t)(yi * WID + xi) * 8);
            float4 a = q[0];
            float4 bb = q[1];
            float wt = wts[t];
            v[0] += wt * a.x;  v[1] += wt * a.y;  v[2] += wt * a.z;  v[3] += wt * a.w;
            v[4] += wt * bb.x; v[5] += wt * bb.y; v[6] += wt * bb.z; v[7] += wt * bb.w;
        }
    }
#pragma unroll
    for (int c = 0; c < 8; c++) vm[c] = v[c] * m;
}

// block: 256 thr = 8 warps, each warp 32 consecutive px of one row; all 64 oc.
__global__ __launch_bounds__(256, 2)
void dcn_mma(const float* __restrict__ dcnb, float* __restrict__ out) {
    extern __shared__ float sm[];
    float* sWH = sm;
    float* sWL = sm + 4608;
    float* sBH = sm + 9216;
    float* sBL = sm + 11776;

    int tid = threadIdx.x;
    int warp = tid >> 5, lane = tid & 31;
    int gr = lane >> 2, tq = lane & 3;
    int y = blockIdx.x, b = blockIdx.y;
    int x = warp * 32 + lane;
    int p = y * 256 + x;

    float acc[4][4][4];
#pragma unroll
    for (int mt = 0; mt < 4; mt++)
#pragma unroll
        for (int nt = 0; nt < 4; nt++)
#pragma unroll
            for (int r = 0; r < 4; r++) acc[mt][nt][r] = 0.f;

    float* myBH = sBH + warp * 320;
    float* myBL = sBL + warp * 320;

    for (int g = 0; g < 8; g++) {
        __syncthreads();
        for (int i = tid; i < 2304; i += 256) {
            int pr = i >= 1152;
            int ii = pr ? i - 1152 : i;
            const float* src = (pr ? d_wdpl : d_wdph) + g * 4608 + ii * 4;
            float* db = pr ? sWL : sWH;
            cpa16((uint32_t)__cvta_generic_to_shared(db + ii * 4), src, true);
        }
        cpcommit();
        cpwait();
        __syncthreads();

        const float* gbase = d_nbr_t + (size_t)(b * 8 + g) * HW * 8;
        const float* omb = d_om + (size_t)b * 216 * HW;

#pragma unroll 1
        for (int k = 0; k < 9; k++) {
            int ky = k / 3, kx = k - ky * 3;
            int ch = g * 9 + k;
            float dy = omb[(ch * 2) * HW + p];
            float dx = omb[(ch * 2 + 1) * HW + p];
            float m = omb[(144 + ch) * HW + p];
            float vm[8];
            dcn_gather(gbase, x, y, ky, kx, dy, dx, m, vm);
            __syncwarp();
#pragma unroll
            for (int c = 0; c < 8; c++) {
                float hv = rna(vm[c]);
                myBH[c * 40 + lane] = hv;
                myBL[c * 40 + lane] = rna(vm[c] - hv);
            }
            __syncwarp();
            uint32_t bh0[4], bh1[4], bl0[4], bl1[4];
#pragma unroll
            for (int nt = 0; nt < 4; nt++) {
                int bi = tq * 40 + nt * 8 + gr;
                bh0[nt] = __float_as_uint(myBH[bi]);
                bh1[nt] = __float_as_uint(myBH[bi + 160]);
                bl0[nt] = __float_as_uint(myBL[bi]);
                bl1[nt] = __float_as_uint(myBL[bi + 160]);
            }
#pragma unroll
            for (int mt = 0; mt < 4; mt++) {
                int wi = ((k * 4 + mt) * 32 + lane) * 4;
                uint4 Ah = *(const uint4*)(sWH + wi);
                uint4 Al = *(const uint4*)(sWL + wi);
#pragma unroll
                for (int nt = 0; nt < 4; nt++) {
                    mma8(acc[mt][nt], Ah, bh0[nt], bh1[nt]);
                    mma8(acc[mt][nt], Ah, bl0[nt], bl1[nt]);
                    mma8(acc[mt][nt], Al, bh0[nt], bh1[nt]);
                }
            }
            __syncwarp();
        }
    }

#pragma unroll
    for (int mt = 0; mt < 4; mt++)
#pragma unroll
        for (int nt = 0; nt < 4; nt++) {
            int xo = warp * 32 + nt * 8 + 2 * tq;
            int pb = y * 256 + xo;
#pragma unroll
            for (int r = 0; r < 4; r++) {
                int oc = 16 * mt + gr + (r >= 2 ? 8 : 0);
                int pp = pb + (r & 1);
                out[(b * 64 + oc) * HW + pp] = acc[mt][nt][r] + dcnb[oc];
            }
        }
}

// ---------- launch ----------
extern "C" void kernel_launch(void* const* d_in, const int* in_sizes, int n_in,
                              void* d_out, int out_size) {
    const float* nbr = (const float*)d_in[0];
    const float* ref = (const float*)d_in[1];
    const float* flow = (const float*)d_in[2];
    const float* conv1_w = (const float*)d_in[3];
    const float* conv1_b = (const float*)d_in[4];
    const float* om_w = (const float*)d_in[5];
    const float* om_b = (const float*)d_in[6];
    const float* dcn_w = (const float*)d_in[7];
    const float* dcn_b = (const float*)d_in[8];
    float* out = (float*)d_out;

    static bool attr_done = false;
    if (!attr_done) {
        cudaFuncSetAttribute(conv1_mma, cudaFuncAttributeMaxDynamicSharedMemorySize, 128000);
        cudaFuncSetAttribute(om_mma, cudaFuncAttributeMaxDynamicSharedMemorySize, 201728);
        cudaFuncSetAttribute(dcn_mma, cudaFuncAttributeMaxDynamicSharedMemorySize, 57344);
        attr_done = true;
    }

    int prep_total = PN0 + PN1 + PN2 + PN3 + PN4;
    prep_all<<<(prep_total + 255) / 256, 256>>>(ref, flow, conv1_w, om_w, dcn_w);
    transpose_kernel<<<(BAT * DG * HW + 255) / 256, 256>>>(nbr);
    warp_kernel<<<(BAT * HW + 255) / 256, 256>>>(flow);
    conv1_mma<<<dim3(2, 256, BAT), 512, 128000>>>(conv1_b);
    om_mma<<<dim3(2, 256, BAT * 2), 512, 201728>>>(om_b, flow);
    dcn_mma<<<dim3(256, BAT), 256, 57344>>>(dcn_b, out);
}

// round 10
// speedup vs baseline: 2.5526x; 1.3722x over previous
#include <cuda_runtime.h>
#include <stdint.h>
#include <math.h>

#define WID 256
#define HGT 256
#define HW  65536
#define BAT 2
#define NF  64
#define DG  8
#define CST 424
#define RST 136
#define SINB 3392

__device__ float d_nbr_t[BAT * DG * HW * 8];
__device__ float d_nwh[BAT * NF * HW];
__device__ float d_refh[BAT * NF * HW];
__device__ float d_feah[BAT * NF * HW];
__device__ float d_flwh[BAT * 2 * HW];
__device__ float d_om[BAT * 216 * HW];
__device__ float d_w1ph[73728];
__device__ float d_w1pl[73728];
__device__ float d_womph[165888];
__device__ float d_wompl[165888];
__device__ float d_wdph[36864];
__device__ float d_wdpl[36864];

__device__ __forceinline__ float rna(float x) {
    uint32_t u; asm("cvt.rna.tf32.f32 %0, %1;" : "=r"(u) : "f"(x));
    return __uint_as_float(u);
}
__device__ __forceinline__ void mma8(float* c, const uint4& a, uint32_t b0, uint32_t b1) {
    asm volatile("mma.sync.aligned.m16n8k8.row.col.f32.tf32.tf32.f32 "
                 "{%0,%1,%2,%3},{%4,%5,%6,%7},{%8,%9},{%0,%1,%2,%3};"
                 : "+f"(c[0]), "+f"(c[1]), "+f"(c[2]), "+f"(c[3])
                 : "r"(a.x), "r"(a.y), "r"(a.z), "r"(a.w), "r"(b0), "r"(b1));
}
__device__ __forceinline__ void cpa16(uint32_t d, const float* s, bool ok) {
    int sz = ok ? 16 : 0;
    asm volatile("cp.async.cg.shared.global [%0], [%1], 16, %2;" :: "r"(d), "l"(s), "r"(sz) : "memory");
}
__device__ __forceinline__ void cpa4(uint32_t d, const float* s, bool ok) {
    int sz = ok ? 4 : 0;
    asm volatile("cp.async.ca.shared.global [%0], [%1], 4, %2;" :: "r"(d), "l"(s), "r"(sz) : "memory");
}
__device__ __forceinline__ void cpcommit() { asm volatile("cp.async.commit_group;" ::: "memory"); }
__device__ __forceinline__ void cpwait() { asm volatile("cp.async.wait_group 0;" ::: "memory"); }

// ---------- fused prep: tf32 rounding of ref/flow + hi/lo weight packs ------
#define PN0 2097152           // ref float4s  (BAT*NF*HW/4)
#define PN1 65536             // flow float4s (BAT*2*HW/4)
#define PN2 18432             // pack_w1 frags
#define PN3 41472             // pack_wom frags
#define PN4 9216              // pack_wdcn frags
__global__ void prep_all(const float* __restrict__ ref, const float* __restrict__ flow,
                         const float* __restrict__ w1, const float* __restrict__ wom,
                         const float* __restrict__ wd) {
    int idx = blockIdx.x * blockDim.x + threadIdx.x;
    if (idx < PN0) {
        float4 v = ((const float4*)ref)[idx];
        float4 h;
        h.x = rna(v.x); h.y = rna(v.y); h.z = rna(v.z); h.w = rna(v.w);
        ((float4*)d_refh)[idx] = h;
        return;
    }
    idx -= PN0;
    if (idx < PN1) {
        float4 v = ((const float4*)flow)[idx];
        float4 h;
        h.x = rna(v.x); h.y = rna(v.y); h.z = rna(v.z); h.w = rna(v.w);
        ((float4*)d_flwh)[idx] = h;
        return;
    }
    idx -= PN1;
    if (idx < PN2) {
        int chunk = idx / 1152, r = idx % 1152;
        int tap = r / 128, r2 = r & 127;
        int m = r2 >> 5, lane = r2 & 31;
        int gr = lane >> 2, tq = lane & 3;
        float4 h, l; float* hp = &h.x; float* lp = &l.x;
#pragma unroll
        for (int vi = 0; vi < 4; vi++) {
            int oc = 16 * m + gr + (vi & 1) * 8;
            int c = 8 * chunk + tq + (vi >> 1) * 4;
            float v = w1[(oc * 128 + c) * 9 + tap];
            float hv = rna(v); hp[vi] = hv; lp[vi] = rna(v - hv);
        }
        ((float4*)d_w1ph)[idx] = h; ((float4*)d_w1pl)[idx] = l;
        return;
    }
    idx -= PN2;
    if (idx < PN3) {
        int slice = idx / 20736, r = idx % 20736;
        int chunk = r / 2304, r1 = r % 2304;
        int tap = r1 / 256, r2 = r1 & 255;
        int m = r2 >> 5, lane = r2 & 31;
        int gr = lane >> 2, tq = lane & 3;
        float4 h, l; float* hp = &h.x; float* lp = &l.x;
#pragma unroll
        for (int vi = 0; vi < 4; vi++) {
            int oc = 128 * slice + 16 * m + gr + (vi & 1) * 8;
            int c = 8 * chunk + tq + (vi >> 1) * 4;
            float v = 0.f;
            if (oc < 216 && c < 66) v = wom[(oc * 66 + c) * 9 + tap];
            float hv = rna(v); hp[vi] = hv; lp[vi] = rna(v - hv);
        }
        ((float4*)d_womph)[idx] = h; ((float4*)d_wompl)[idx] = l;
        return;
    }
    idx -= PN3;
    if (idx < PN4) {
        int g = idx / 1152, r = idx % 1152;
        int tap = r / 128, r2 = r & 127;
        int mt = r2 >> 5, lane = r2 & 31;
        int gr = lane >> 2, tq = lane & 3;
        float4 h, l; float* hp = &h.x; float* lp = &l.x;
#pragma unroll
        for (int vi = 0; vi < 4; vi++) {
            int oc = 16 * mt + gr + (vi & 1) * 8;
            int kc = tq + (vi >> 1) * 4;
            float v = wd[(oc * 64 + g * 8 + kc) * 9 + tap];
            float hv = rna(v); hp[vi] = hv; lp[vi] = rna(v - hv);
        }
        ((float4*)d_wdph)[idx] = h; ((float4*)d_wdpl)[idx] = l;
    }
}

// ---------- transpose for dcn + warp ----------
__global__ void transpose_kernel(const float* __restrict__ nbr) {
    int idx = blockIdx.x * blockDim.x + threadIdx.x;
    if (idx >= BAT * DG * HW) return;
    int bg = idx >> 16, p = idx & 65535;
    int b = bg >> 3, g = bg & 7;
    float v[8];
#pragma unroll
    for (int c = 0; c < 8; c++) v[c] = nbr[((b * NF + g * 8 + c) * HW) + p];
    float4* dst = (float4*)&d_nbr_t[(size_t)idx * 8];
    dst[0] = make_float4(v[0], v[1], v[2], v[3]);
    dst[1] = make_float4(v[4], v[5], v[6], v[7]);
}

// ---------- warp (bilinear) reading channel-last d_nbr_t -> tf32 ----------
__global__ void warp_kernel(const float* __restrict__ flow) {
    int idx = blockIdx.x * blockDim.x + threadIdx.x;
    if (idx >= BAT * HW) return;
    int b = idx >> 16, p = idx & 65535;
    int y = p >> 8, x = p & 255;
    float fx = flow[(b * 2 + 0) * HW + p];
    float fy = flow[(b * 2 + 1) * HW + p];
    float px = (float)x + fx, py = (float)y + fy;
    float x0f = floorf(px), y0f = floorf(py);
    int ix0 = (int)x0f, iy0 = (int)y0f;
    float wx = px - x0f, wy = py - y0f;
    bool vx0 = (unsigned)ix0 < WID, vx1 = (unsigned)(ix0 + 1) < WID;
    bool vy0 = (unsigned)iy0 < HGT, vy1 = (unsigned)(iy0 + 1) < HGT;
    float w00 = (vy0 && vx0) ? (1.f - wy) * (1.f - wx) : 0.f;
    float w01 = (vy0 && vx1) ? (1.f - wy) * wx : 0.f;
    float w10 = (vy1 && vx0) ? wy * (1.f - wx) : 0.f;
    float w11 = (vy1 && vx1) ? wy * wx : 0.f;
    int cx0 = min(max(ix0, 0), WID - 1), cx1 = min(max(ix0 + 1, 0), WID - 1);
    int cy0 = min(max(iy0, 0), HGT - 1), cy1 = min(max(iy0 + 1, 0), HGT - 1);
    size_t i00 = (size_t)(cy0 * WID + cx0) * 8;
    size_t i01 = (size_t)(cy0 * WID + cx1) * 8;
    size_t i10 = (size_t)(cy1 * WID + cx0) * 8;
    size_t i11 = (size_t)(cy1 * WID + cx1) * 8;

#pragma unroll 1
    for (int g = 0; g < 8; g++) {
        const float* gb = d_nbr_t + (size_t)(b * 8 + g) * HW * 8;
        float v[8];
#pragma unroll
        for (int half = 0; half < 2; half++) {
            float4 a00 = *(const float4*)(gb + i00 + 4 * half);
            float4 a01 = *(const float4*)(gb + i01 + 4 * half);
            float4 a10 = *(const float4*)(gb + i10 + 4 * half);
            float4 a11 = *(const float4*)(gb + i11 + 4 * half);
            v[4 * half + 0] = w00 * a00.x + w01 * a01.x + w10 * a10.x + w11 * a11.x;
            v[4 * half + 1] = w00 * a00.y + w01 * a01.y + w10 * a10.y + w11 * a11.y;
            v[4 * half + 2] = w00 * a00.z + w01 * a01.z + w10 * a10.z + w11 * a11.z;
            v[4 * half + 3] = w00 * a00.w + w01 * a01.w + w10 * a10.w + w11 * a11.w;
        }
#pragma unroll
        for (int c = 0; c < 8; c++) {
            d_nwh[(size_t)(b * 64 + g * 8 + c) * HW + p] = rna(v[c]);
        }
    }
}

// ---------- conv1 via tf32 MMA (2-term weight split): 128->64, relu --------
__global__ __launch_bounds__(512, 1)
void conv1_mma(const float* __restrict__ bias) {
    extern __shared__ float sm[];
    float* sIn = sm;              // [2][3392]
    float* sWH = sm + 6784;       // [2][4608]
    float* sWL = sm + 16000;      // [2][4608]

    int tid = threadIdx.x;
    int warp = tid >> 5, lane = tid & 31;
    int g = warp & 3, h = warp >> 2;
    int gr = lane >> 2, tq = lane & 3;
    int b = blockIdx.z, y = blockIdx.y, x0 = blockIdx.x * 128;

    float acc[4][4];
#pragma unroll
    for (int j = 0; j < 4; j++)
#pragma unroll
        for (int k = 0; k < 4; k++) acc[j][k] = 0.f;

    auto stage = [&](int chunk, int buf) {
        for (int i = tid; i < 768; i += 512) {
            int c = i / 96, rr = i - c * 96;
            int r = rr >> 5, k = rr & 31;
            int cc = chunk * 8 + c;
            int gy = y + r - 1;
            bool ok = (unsigned)gy < HGT;
            int gyc = ok ? gy : 0;
            const float* arr = (cc < 64) ? d_nwh : d_refh;
            int ci = (cc < 64) ? cc : cc - 64;
            const float* src = arr + (size_t)(b * 64 + ci) * HW + gyc * 256 + x0 + 4 * k;
            cpa16((uint32_t)__cvta_generic_to_shared(sIn + buf * SINB + c * CST + r * RST + 4 + 4 * k), src, ok);
        }
        for (int i = tid; i < 48; i += 512) {
            int c = i / 6, rr = i - c * 6;
            int r = rr >> 1, side = rr & 1;
            int cc = chunk * 8 + c;
            int gy = y + r - 1;
            int gx = side ? x0 + 128 : x0 - 1;
            bool ok = ((unsigned)gy < HGT) && ((unsigned)gx < WID);
            int gyc = ((unsigned)gy < HGT) ? gy : 0;
            int gxc = ((unsigned)gx < WID) ? gx : 0;
            const float* arr = (cc < 64) ? d_nwh : d_refh;
            int ci = (cc < 64) ? cc : cc - 64;
            const float* src = arr + (size_t)(b * 64 + ci) * HW + gyc * 256 + gxc;
            cpa4((uint32_t)__cvta_generic_to_shared(sIn + buf * SINB + c * CST + r * RST + (side ? 132 : 3)), src, ok);
        }
        for (int i = tid; i < 2304; i += 512) {
            int pr = i >= 1152;
            int ii = pr ? i - 1152 : i;
            const float* src = (pr ? d_w1pl : d_w1ph) + chunk * 4608 + ii * 4;
            float* db = (pr ? sWL : sWH) + buf * 4608;
            cpa16((uint32_t)__cvta_generic_to_shared(db + ii * 4), src, true);
        }
        cpcommit();
    };

    stage(0, 0);
    int bbase = tq * CST + 32 * g + gr + 3;
    for (int it = 0; it < 16; it++) {
        int buf = it & 1;
        cpwait();
        __syncthreads();
        if (it + 1 < 16) stage(it + 1, buf ^ 1);

        const float* si = sIn + buf * SINB;
        const float* swH = sWH + buf * 4608;
        const float* swL = sWL + buf * 4608;
#pragma unroll
        for (int dy = 0; dy < 3; dy++) {
#pragma unroll
            for (int dx = 0; dx < 3; dx++) {
                int tap = dy * 3 + dx;
                int wi = ((tap * 4 + h) * 32 + lane) * 4;
                uint4 Ah = *(const uint4*)(swH + wi);
                uint4 Al = *(const uint4*)(swL + wi);
                int fb = bbase + dy * RST + dx;
#pragma unroll
                for (int j = 0; j < 4; j++) {
                    int fi = fb + 8 * j;
                    uint32_t b0 = __float_as_uint(si[fi]);
                    uint32_t b1 = __float_as_uint(si[fi + 4 * CST]);
                    mma8(acc[j], Ah, b0, b1);
                    mma8(acc[j], Al, b0, b1);
                }
            }
        }
        __syncthreads();
    }

#pragma unroll
    for (int j = 0; j < 4; j++) {
        int x = x0 + 32 * g + 8 * j + 2 * tq;
        int pA = y * 256 + x;
#pragma unroll
        for (int k = 0; k < 4; k++) {
            int ch = 16 * h + gr + (k >= 2 ? 8 : 0);
            int p = pA + (k & 1);
            float v = acc[j][k] + bias[ch];
            v = fmaxf(v, 0.f);
            d_feah[(size_t)(b * 64 + ch) * HW + p] = rna(v);
        }
    }
}

// ---------- om via tf32 MMA (2-term weight split): 66->216, fused epilogue --
__global__ __launch_bounds__(512, 1)
void om_mma(const float* __restrict__ bias, const float* __restrict__ flow) {
    extern __shared__ float sm[];
    float* sIn = sm;              // [2][3392]
    float* sWH = sm + 6784;       // [2][9216]
    float* sWL = sm + 25216;      // [2][9216]

    int tid = threadIdx.x;
    int warp = tid >> 5, lane = tid & 31;
    int g = warp & 3, h = warp >> 2;
    int gr = lane >> 2, tq = lane & 3;
    int bz = blockIdx.z;
    int b = bz >> 1, slice = bz & 1;
    int y = blockIdx.y, x0 = blockIdx.x * 128;

    float acc[4][2][4];
#pragma unroll
    for (int j = 0; j < 4; j++)
#pragma unroll
        for (int mi = 0; mi < 2; mi++)
#pragma unroll
            for (int k = 0; k < 4; k++) acc[j][mi][k] = 0.f;

    auto stage = [&](int chunk, int buf) {
        for (int i = tid; i < 768; i += 512) {
            int c = i / 96, rr = i - c * 96;
            int r = rr >> 5, k = rr & 31;
            int cc = chunk * 8 + c;
            int gy = y + r - 1;
            bool ok = ((unsigned)gy < HGT) && (cc < 66);
            int gyc = ((unsigned)gy < HGT) ? gy : 0;
            const float* arr = (cc < 64) ? d_feah : d_flwh;
            int ci, cm;
            if (cc < 64) { ci = cc; cm = 64; } else { ci = cc - 64; cm = 2; }
            if (ci >= cm) ci = 0;
            const float* src = arr + (size_t)(b * cm + ci) * HW + gyc * 256 + x0 + 4 * k;
            cpa16((uint32_t)__cvta_generic_to_shared(sIn + buf * SINB + c * CST + r * RST + 4 + 4 * k), src, ok);
        }
        for (int i = tid; i < 48; i += 512) {
            int c = i / 6, rr = i - c * 6;
            int r = rr >> 1, side = rr & 1;
            int cc = chunk * 8 + c;
            int gy = y + r - 1;
            int gx = side ? x0 + 128 : x0 - 1;
            bool ok = ((unsigned)gy < HGT) && ((unsigned)gx < WID) && (cc < 66);
            int gyc = ((unsigned)gy < HGT) ? gy : 0;
            int gxc = ((unsigned)gx < WID) ? gx : 0;
            const float* arr = (cc < 64) ? d_feah : d_flwh;
            int ci, cm;
            if (cc < 64) { ci = cc; cm = 64; } else { ci = cc - 64; cm = 2; }
            if (ci >= cm) ci = 0;
            const float* src = arr + (size_t)(b * cm + ci) * HW + gyc * 256 + gxc;
            cpa4((uint32_t)__cvta_generic_to_shared(sIn + buf * SINB + c * CST + r * RST + (side ? 132 : 3)), src, ok);
        }
        for (int i = tid; i < 4608; i += 512) {
            int pr = i >= 2304;
            int ii = pr ? i - 2304 : i;
            const float* src = (pr ? d_wompl : d_womph) + (slice * 9 + chunk) * 9216 + ii * 4;
            float* db = (pr ? sWL : sWH) + buf * 9216;
            cpa16((uint32_t)__cvta_generic_to_shared(db + ii * 4), src, true);
        }
        cpcommit();
    };

    stage(0, 0);
    int bbase = tq * CST + 32 * g + gr + 3;
    for (int it = 0; it < 9; it++) {
        int buf = it & 1;
        cpwait();
        __syncthreads();
        if (it + 1 < 9) stage(it + 1, buf ^ 1);

        const float* si = sIn + buf * SINB;
        const float* swH = sWH + buf * 9216;
        const float* swL = sWL + buf * 9216;
#pragma unroll
        for (int dy = 0; dy < 3; dy++) {
#pragma unroll
            for (int dx = 0; dx < 3; dx++) {
                int tap = dy * 3 + dx;
                int wi = ((tap * 8 + 2 * h) * 32 + lane) * 4;
                uint4 Ah0 = *(const uint4*)(swH + wi);
                uint4 Ah1 = *(const uint4*)(swH + wi + 128);
                uint4 Al0 = *(const uint4*)(swL + wi);
                uint4 Al1 = *(const uint4*)(swL + wi + 128);
                int fb = bbase + dy * RST + dx;
#pragma unroll
                for (int j = 0; j < 4; j++) {
                    int fi = fb + 8 * j;
                    uint32_t b0 = __float_as_uint(si[fi]);
                    uint32_t b1 = __float_as_uint(si[fi + 4 * CST]);
                    mma8(acc[j][0], Ah0, b0, b1);
                    mma8(acc[j][0], Al0, b0, b1);
                    mma8(acc[j][1], Ah1, b0, b1);
                    mma8(acc[j][1], Al1, b0, b1);
                }
            }
        }
        __syncthreads();
    }

    int ocb = 128 * slice;
#pragma unroll
    for (int j = 0; j < 4; j++) {
        int x = x0 + 32 * g + 8 * j + 2 * tq;
        int pA = y * 256 + x;
#pragma unroll
        for (int mi = 0; mi < 2; mi++) {
            int chA = ocb + 16 * (2 * h + mi) + gr;
#pragma unroll
            for (int k = 0; k < 4; k++) {
                int ch = chA + (k >= 2 ? 8 : 0);
                if (ch >= 216) continue;
                int p = pA + (k & 1);
                float v = acc[j][mi][k] + bias[ch];
                if (ch < 144) {
                    v += (gr & 1) ? flow[(b * 2 + 0) * HW + p]
                                  : flow[(b * 2 + 1) * HW + p];
                } else {
                    v = 1.f / (1.f + expf(-v));
                }
                d_om[(size_t)(b * 216 + ch) * HW + p] = v;
            }
        }
    }
}

// ---------- dcn via tf32 MMA (2-term weight split) ----------
__device__ __forceinline__ void dcn_gather(const float* __restrict__ gbase,
                                           int x, int y, int ky, int kx,
                                           float dy, float dx, float m, float* vm) {
    float spy = (float)(y - 1 + ky) + dy;
    float spx = (float)(x - 1 + kx) + dx;
    float y0f = floorf(spy), x0f = floorf(spx);
    int iy0 = (int)y0f, ix0 = (int)x0f;
    float wy = spy - y0f, wx = spx - x0f;
    float v[8];
#pragma unroll
    for (int c = 0; c < 8; c++) v[c] = 0.f;
    float wts[4] = {(1.f - wy) * (1.f - wx), (1.f - wy) * wx, wy * (1.f - wx), wy * wx};
    int ys[4] = {iy0, iy0, iy0 + 1, iy0 + 1};
    int xs[4] = {ix0, ix0 + 1, ix0, ix0 + 1};
#pragma unroll
    for (int t = 0; t < 4; t++) {
        int yi = ys[t], xi = xs[t];
        if ((unsigned)yi < HGT && (unsigned)xi < WID) {
            const float4* q = (const float4*)(gbase + (size_t)(yi * WID + xi) * 8);
            float4 a = q[0];
            float4 bb = q[1];
            float wt = wts[t];
            v[0] += wt * a.x;  v[1] += wt * a.y;  v[2] += wt * a.z;  v[3] += wt * a.w;
            v[4] += wt * bb.x; v[5] += wt * bb.y; v[6] += wt * bb.z; v[7] += wt * bb.w;
        }
    }
#pragma unroll
    for (int c = 0; c < 8; c++) vm[c] = v[c] * m;
}

__global__ __launch_bounds__(256, 2)
void dcn_mma(const float* __restrict__ dcnb, float* __restrict__ out) {
    extern __shared__ float sm[];
    float* sWH = sm;              // 4608
    float* sWL = sm + 4608;       // 4608
    float* sBH = sm + 9216;       // 8*320

    int tid = threadIdx.x;
    int warp = tid >> 5, lane = tid & 31;
    int gr = lane >> 2, tq = lane & 3;
    int y = blockIdx.x, b = blockIdx.y;
    int x = warp * 32 + lane;
    int p = y * 256 + x;

    float acc[4][4][4];
#pragma unroll
    for (int mt = 0; mt < 4; mt++)
#pragma unroll
        for (int nt = 0; nt < 4; nt++)
#pragma unroll
            for (int r = 0; r < 4; r++) acc[mt][nt][r] = 0.f;

    float* myBH = sBH + warp * 320;

    for (int g = 0; g < 8; g++) {
        __syncthreads();
        for (int i = tid; i < 2304; i += 256) {
            int pr = i >= 1152;
            int ii = pr ? i - 1152 : i;
            const float* src = (pr ? d_wdpl : d_wdph) + g * 4608 + ii * 4;
            float* db = pr ? sWL : sWH;
            cpa16((uint32_t)__cvta_generic_to_shared(db + ii * 4), src, true);
        }
        cpcommit();
        cpwait();
        __syncthreads();

        const float* gbase = d_nbr_t + (size_t)(b * 8 + g) * HW * 8;
        const float* omb = d_om + (size_t)b * 216 * HW;

#pragma unroll 1
        for (int k = 0; k < 9; k++) {
            int ky = k / 3, kx = k - ky * 3;
            int ch = g * 9 + k;
            float dy = omb[(ch * 2) * HW + p];
            float dx = omb[(ch * 2 + 1) * HW + p];
            float m = omb[(144 + ch) * HW + p];
            float vm[8];
            dcn_gather(gbase, x, y, ky, kx, dy, dx, m, vm);
            __syncwarp();
#pragma unroll
            for (int c = 0; c < 8; c++) {
                myBH[c * 40 + lane] = rna(vm[c]);
            }
            __syncwarp();
            uint32_t b0[4], b1[4];
#pragma unroll
            for (int nt = 0; nt < 4; nt++) {
                int bi = tq * 40 + nt * 8 + gr;
                b0[nt] = __float_as_uint(myBH[bi]);
                b1[nt] = __float_as_uint(myBH[bi + 160]);
            }
#pragma unroll
            for (int mt = 0; mt < 4; mt++) {
                int wi = ((k * 4 + mt) * 32 + lane) * 4;
                uint4 Ah = *(const uint4*)(sWH + wi);
                uint4 Al = *(const uint4*)(sWL + wi);
#pragma unroll
                for (int nt = 0; nt < 4; nt++) {
                    mma8(acc[mt][nt], Ah, b0[nt], b1[nt]);
                    mma8(acc[mt][nt], Al, b0[nt], b1[nt]);
                }
            }
            __syncwarp();
        }
    }

#pragma unroll
    for (int mt = 0; mt < 4; mt++)
#pragma unroll
        for (int nt = 0; nt < 4; nt++) {
            int xo = warp * 32 + nt * 8 + 2 * tq;
            int pb = y * 256 + xo;
#pragma unroll
            for (int r = 0; r < 4; r++) {
                int oc = 16 * mt + gr + (r >= 2 ? 8 : 0);
                int pp = pb + (r & 1);
                out[(b * 64 + oc) * HW + pp] = acc[mt][nt][r] + dcnb[oc];
            }
        }
}

// ---------- launch ----------
extern "C" void kernel_launch(void* const* d_in, const int* in_sizes, int n_in,
                              void* d_out, int out_size) {
    const float* nbr = (const float*)d_in[0];
    const float* ref = (const float*)d_in[1];
    const float* flow = (const float*)d_in[2];
    const float* conv1_w = (const float*)d_in[3];
    const float* conv1_b = (const float*)d_in[4];
    const float* om_w = (const float*)d_in[5];
    const float* om_b = (const float*)d_in[6];
    const float* dcn_w = (const float*)d_in[7];
    const float* dcn_b = (const float*)d_in[8];
    float* out = (float*)d_out;

    static bool attr_done = false;
    if (!attr_done) {
        cudaFuncSetAttribute(conv1_mma, cudaFuncAttributeMaxDynamicSharedMemorySize, 100864);
        cudaFuncSetAttribute(om_mma, cudaFuncAttributeMaxDynamicSharedMemorySize, 174592);
        cudaFuncSetAttribute(dcn_mma, cudaFuncAttributeMaxDynamicSharedMemorySize, 49152);
        attr_done = true;
    }

    int prep_total = PN0 + PN1 + PN2 + PN3 + PN4;
    prep_all<<<(prep_total + 255) / 256, 256>>>(ref, flow, conv1_w, om_w, dcn_w);
    transpose_kernel<<<(BAT * DG * HW + 255) / 256, 256>>>(nbr);
    warp_kernel<<<(BAT * HW + 255) / 256, 256>>>(flow);
    conv1_mma<<<dim3(2, 256, BAT), 512, 100864>>>(conv1_b);
    om_mma<<<dim3(2, 256, BAT * 2), 512, 174592>>>(om_b, flow);
    dcn_mma<<<dim3(256, BAT), 256, 49152>>>(dcn_b, out);
}

// round 11
// speedup vs baseline: 2.8484x; 1.1159x over previous
#include <cuda_runtime.h>
#include <cuda_bf16.h>
#include <stdint.h>
#include <math.h>

#define WID 256
#define HGT 256
#define HW  65536
#define BAT 2
#define NF  64
#define DG  8
#define CST 424
#define RST 136
#define SINB 3392

// fp32 scratch (dcn path unchanged)
__device__ float d_nbr_t[BAT * DG * HW * 8];
__device__ float d_om[BAT * 216 * HW];
__device__ float d_wdph[36864];
__device__ float d_wdpl[36864];
// bf16 packed-pair activations (uint32 = 2 channels) hi/lo
__device__ unsigned int d_nwph[BAT * 32 * HW];
__device__ unsigned int d_nwpl[BAT * 32 * HW];
__device__ unsigned int d_refph[BAT * 32 * HW];
__device__ unsigned int d_refpl[BAT * 32 * HW];
__device__ unsigned int d_feaph[BAT * 32 * HW];
__device__ unsigned int d_feapl[BAT * 32 * HW];
__device__ unsigned int d_flwph[BAT * HW];
__device__ unsigned int d_flwpl[BAT * HW];
// bf16 packed weights (A-fragment layout)
__device__ unsigned int d_w1bh[36864];
__device__ unsigned int d_w1bl[36864];
__device__ unsigned int d_wobh[92160];
__device__ unsigned int d_wobl[92160];

__device__ __forceinline__ float rna(float x) {
    uint32_t u; asm("cvt.rna.tf32.f32 %0, %1;" : "=r"(u) : "f"(x));
    return __uint_as_float(u);
}
__device__ __forceinline__ float bf16f(float x) {
    return __bfloat162float(__float2bfloat16_rn(x));
}
__device__ __forceinline__ uint32_t pkbf(float a, float b) {
    uint32_t lo = (uint32_t)__bfloat16_as_ushort(__float2bfloat16_rn(a));
    uint32_t hi = (uint32_t)__bfloat16_as_ushort(__float2bfloat16_rn(b));
    return lo | (hi << 16);
}
__device__ __forceinline__ void mma16(float* c, const uint4& a, uint32_t b0, uint32_t b1) {
    asm volatile("mma.sync.aligned.m16n8k16.row.col.f32.bf16.bf16.f32 "
                 "{%0,%1,%2,%3},{%4,%5,%6,%7},{%8,%9},{%0,%1,%2,%3};"
                 : "+f"(c[0]), "+f"(c[1]), "+f"(c[2]), "+f"(c[3])
                 : "r"(a.x), "r"(a.y), "r"(a.z), "r"(a.w), "r"(b0), "r"(b1));
}
__device__ __forceinline__ void mma8t(float* c, const uint4& a, uint32_t b0, uint32_t b1) {
    asm volatile("mma.sync.aligned.m16n8k8.row.col.f32.tf32.tf32.f32 "
                 "{%0,%1,%2,%3},{%4,%5,%6,%7},{%8,%9},{%0,%1,%2,%3};"
                 : "+f"(c[0]), "+f"(c[1]), "+f"(c[2]), "+f"(c[3])
                 : "r"(a.x), "r"(a.y), "r"(a.z), "r"(a.w), "r"(b0), "r"(b1));
}
__device__ __forceinline__ void cpa16(uint32_t d, const void* s, bool ok) {
    int sz = ok ? 16 : 0;
    asm volatile("cp.async.cg.shared.global [%0], [%1], 16, %2;" :: "r"(d), "l"(s), "r"(sz) : "memory");
}
__device__ __forceinline__ void cpa4(uint32_t d, const void* s, bool ok) {
    int sz = ok ? 4 : 0;
    asm volatile("cp.async.ca.shared.global [%0], [%1], 4, %2;" :: "r"(d), "l"(s), "r"(sz) : "memory");
}
__device__ __forceinline__ void cpcommit() { asm volatile("cp.async.commit_group;" ::: "memory"); }
__device__ __forceinline__ void cpwait() { asm volatile("cp.async.wait_group 0;" ::: "memory"); }

// ---------------- fused prep ----------------
#define PN0 1048576   // ref pack uint4s (BAT*32*HW/4)
#define PN1 32768     // flow pack uint4s (BAT*HW/4)
#define PN2 36864     // w1 bf16 frag words
#define PN3 92160     // wom bf16 frag words
#define PN4 9216      // dcn tf32 frags (float4)
__global__ void prep_all(const float* __restrict__ ref, const float* __restrict__ flow,
                         const float* __restrict__ w1, const float* __restrict__ wom,
                         const float* __restrict__ wd) {
    int idx = blockIdx.x * blockDim.x + threadIdx.x;
    if (idx < PN0) {
        int row = idx / 16384;            // b*32 + c2
        int p4 = idx - row * 16384;
        int b = row >> 5, c2 = row & 31;
        int pix = p4 * 4;
        float4 va = *(const float4*)(ref + (size_t)(b * 64 + 2 * c2) * HW + pix);
        float4 vb = *(const float4*)(ref + (size_t)(b * 64 + 2 * c2 + 1) * HW + pix);
        const float* ap = &va.x; const float* bp = &vb.x;
        uint4 wh, wl;
        uint32_t* whp = &wh.x; uint32_t* wlp = &wl.x;
#pragma unroll
        for (int j = 0; j < 4; j++) {
            float a = ap[j], c = bp[j];
            float ah = bf16f(a), ch = bf16f(c);
            whp[j] = pkbf(a, c);
            wlp[j] = pkbf(a - ah, c - ch);
        }
        ((uint4*)d_refph)[idx] = wh;
        ((uint4*)d_refpl)[idx] = wl;
        return;
    }
    idx -= PN0;
    if (idx < PN1) {
        int b = idx / 16384;
        int pix = (idx - b * 16384) * 4;
        float4 fx4 = *(const float4*)(flow + (size_t)(b * 2) * HW + pix);
        float4 fy4 = *(const float4*)(flow + (size_t)(b * 2 + 1) * HW + pix);
        const float* xp = &fx4.x; const float* yp = &fy4.x;
        uint4 wh, wl;
        uint32_t* whp = &wh.x; uint32_t* wlp = &wl.x;
#pragma unroll
        for (int j = 0; j < 4; j++) {
            float a = xp[j], c = yp[j];
            float ah = bf16f(a), ch = bf16f(c);
            whp[j] = pkbf(a, c);
            wlp[j] = pkbf(a - ah, c - ch);
        }
        ((uint4*)d_flwph)[idx] = wh;
        ((uint4*)d_flwpl)[idx] = wl;
        return;
    }
    idx -= PN1;
    if (idx < PN2) {
        int vi = idx & 3;
        int lane = (idx >> 2) & 31;
        int m = (idx >> 7) & 3;
        int tap = (idx >> 9) % 9;
        int chunk = idx / 4608;
        int gr = lane >> 2, tq = lane & 3;
        int oc = 16 * m + gr + (vi & 1) * 8;
        int kb = 16 * chunk + 2 * tq + ((vi >> 1) ? 8 : 0);
        float v0 = w1[(oc * 128 + kb) * 9 + tap];
        float v1 = w1[(oc * 128 + kb + 1) * 9 + tap];
        float h0 = bf16f(v0), h1 = bf16f(v1);
        d_w1bh[idx] = pkbf(v0, v1);
        d_w1bl[idx] = pkbf(v0 - h0, v1 - h1);
        return;
    }
    idx -= PN2;
    if (idx < PN3) {
        int cs = idx / 9216;              // slice*5 + chunk
        int w = idx - cs * 9216;
        int slice = cs / 5, chunk = cs - slice * 5;
        int tap = w / 1024;
        int r2 = w - tap * 1024;
        int m = r2 >> 7;
        int lane = (r2 >> 2) & 31;
        int vi = r2 & 3;
        int gr = lane >> 2, tq = lane & 3;
        int oc = 128 * slice + 16 * m + gr + (vi & 1) * 8;
        int kb = 16 * chunk + 2 * tq + ((vi >> 1) ? 8 : 0);
        float v0 = 0.f, v1 = 0.f;
        if (oc < 216 && kb < 66) v0 = wom[(oc * 66 + kb) * 9 + tap];
        if (oc < 216 && kb + 1 < 66) v1 = wom[(oc * 66 + kb + 1) * 9 + tap];
        float h0 = bf16f(v0), h1 = bf16f(v1);
        d_wobh[idx] = pkbf(v0, v1);
        d_wobl[idx] = pkbf(v0 - h0, v1 - h1);
        return;
    }
    idx -= PN3;
    if (idx < PN4) {
        int g = idx / 1152, r = idx % 1152;
        int tap = r / 128, r2 = r & 127;
        int mt = r2 >> 5, lane = r2 & 31;
        int gr = lane >> 2, tq = lane & 3;
        float4 h, l; float* hp = &h.x; float* lp = &l.x;
#pragma unroll
        for (int vi = 0; vi < 4; vi++) {
            int oc = 16 * mt + gr + (vi & 1) * 8;
            int kc = tq + (vi >> 1) * 4;
            float v = wd[(oc * 64 + g * 8 + kc) * 9 + tap];
            float hv = rna(v); hp[vi] = hv; lp[vi] = rna(v - hv);
        }
        ((float4*)d_wdph)[idx] = h;
        ((float4*)d_wdpl)[idx] = l;
    }
}

// ---------------- transpose for dcn + warp ----------------
__global__ void transpose_kernel(const float* __restrict__ nbr) {
    int idx = blockIdx.x * blockDim.x + threadIdx.x;
    if (idx >= BAT * DG * HW) return;
    int bg = idx >> 16, p = idx & 65535;
    int b = bg >> 3, g = bg & 7;
    float v[8];
#pragma unroll
    for (int c = 0; c < 8; c++) v[c] = nbr[((b * NF + g * 8 + c) * HW) + p];
    float4* dst = (float4*)&d_nbr_t[(size_t)idx * 8];
    dst[0] = make_float4(v[0], v[1], v[2], v[3]);
    dst[1] = make_float4(v[4], v[5], v[6], v[7]);
}

// ---------------- warp (bilinear) -> packed bf16 hi/lo ----------------
__global__ void warp_kernel(const float* __restrict__ flow) {
    int idx = blockIdx.x * blockDim.x + threadIdx.x;
    if (idx >= BAT * HW) return;
    int b = idx >> 16, p = idx & 65535;
    int y = p >> 8, x = p & 255;
    float fx = flow[(b * 2 + 0) * HW + p];
    float fy = flow[(b * 2 + 1) * HW + p];
    float px = (float)x + fx, py = (float)y + fy;
    float x0f = floorf(px), y0f = floorf(py);
    int ix0 = (int)x0f, iy0 = (int)y0f;
    float wx = px - x0f, wy = py - y0f;
    bool vx0 = (unsigned)ix0 < WID, vx1 = (unsigned)(ix0 + 1) < WID;
    bool vy0 = (unsigned)iy0 < HGT, vy1 = (unsigned)(iy0 + 1) < HGT;
    float w00 = (vy0 && vx0) ? (1.f - wy) * (1.f - wx) : 0.f;
    float w01 = (vy0 && vx1) ? (1.f - wy) * wx : 0.f;
    float w10 = (vy1 && vx0) ? wy * (1.f - wx) : 0.f;
    float w11 = (vy1 && vx1) ? wy * wx : 0.f;
    int cx0 = min(max(ix0, 0), WID - 1), cx1 = min(max(ix0 + 1, 0), WID - 1);
    int cy0 = min(max(iy0, 0), HGT - 1), cy1 = min(max(iy0 + 1, 0), HGT - 1);
    size_t i00 = (size_t)(cy0 * WID + cx0) * 8;
    size_t i01 = (size_t)(cy0 * WID + cx1) * 8;
    size_t i10 = (size_t)(cy1 * WID + cx0) * 8;
    size_t i11 = (size_t)(cy1 * WID + cx1) * 8;

#pragma unroll 1
    for (int g = 0; g < 8; g++) {
        const float* gb = d_nbr_t + (size_t)(b * 8 + g) * HW * 8;
        float v[8];
#pragma unroll
        for (int half = 0; half < 2; half++) {
            float4 a00 = *(const float4*)(gb + i00 + 4 * half);
            float4 a01 = *(const float4*)(gb + i01 + 4 * half);
            float4 a10 = *(const float4*)(gb + i10 + 4 * half);
            float4 a11 = *(const float4*)(gb + i11 + 4 * half);
            v[4 * half + 0] = w00 * a00.x + w01 * a01.x + w10 * a10.x + w11 * a11.x;
            v[4 * half + 1] = w00 * a00.y + w01 * a01.y + w10 * a10.y + w11 * a11.y;
            v[4 * half + 2] = w00 * a00.z + w01 * a01.z + w10 * a10.z + w11 * a11.z;
            v[4 * half + 3] = w00 * a00.w + w01 * a01.w + w10 * a10.w + w11 * a11.w;
        }
#pragma unroll
        for (int cl = 0; cl < 4; cl++) {
            float a = v[2 * cl], c = v[2 * cl + 1];
            float ah = bf16f(a), ch = bf16f(c);
            size_t o = (size_t)(b * 32 + g * 4 + cl) * HW + p;
            d_nwph[o] = pkbf(a, c);
            d_nwpl[o] = pkbf(a - ah, c - ch);
        }
    }
}

// ---------------- conv1 via bf16 k16 MMA (3-term): 128->64, relu ------------
// 512 thr: g=warp&3 (32px), h=warp>>2 (m-block of 16 oc). 8 chunks of 16 ch.
__global__ __launch_bounds__(512, 1)
void conv1_mma(const float* __restrict__ bias) {
    extern __shared__ unsigned int sm[];
    unsigned int* sInH = sm;              // [2][3392]
    unsigned int* sInL = sm + 6784;
    unsigned int* sWH  = sm + 13568;      // [2][4608]
    unsigned int* sWL  = sm + 22784;

    int tid = threadIdx.x;
    int warp = tid >> 5, lane = tid & 31;
    int g = warp & 3, h = warp >> 2;
    int gr = lane >> 2, tq = lane & 3;
    int b = blockIdx.z, y = blockIdx.y, x0 = blockIdx.x * 128;

    float acc[4][4];
#pragma unroll
    for (int j = 0; j < 4; j++)
#pragma unroll
        for (int k = 0; k < 4; k++) acc[j][k] = 0.f;

    auto stage = [&](int chunk, int buf) {
        for (int i = tid; i < 1536; i += 512) {
            int pr = i >= 768;
            int ii = pr ? i - 768 : i;
            int c2l = ii / 96, rr = ii - c2l * 96;
            int r = rr >> 5, k = rr & 31;
            int row = chunk * 8 + c2l;
            int gy = y + r - 1;
            bool ok = (unsigned)gy < HGT;
            int gyc = ok ? gy : 0;
            const unsigned int* arr = (row < 32) ? (pr ? d_nwpl : d_nwph) : (pr ? d_refpl : d_refph);
            int rl = (row < 32) ? row : row - 32;
            const unsigned int* src = arr + (size_t)(b * 32 + rl) * HW + gyc * 256 + x0 + 4 * k;
            unsigned int* db = (pr ? sInL : sInH) + buf * SINB;
            cpa16((uint32_t)__cvta_generic_to_shared(db + c2l * CST + r * RST + 4 + 4 * k), src, ok);
        }
        for (int i = tid; i < 96; i += 512) {
            int pr = i >= 48;
            int ii = pr ? i - 48 : i;
            int c2l = ii / 6, rr = ii - c2l * 6;
            int r = rr >> 1, side = rr & 1;
            int row = chunk * 8 + c2l;
            int gy = y + r - 1;
            int gx = side ? x0 + 128 : x0 - 1;
            bool ok = ((unsigned)gy < HGT) && ((unsigned)gx < WID);
            int gyc = ((unsigned)gy < HGT) ? gy : 0;
            int gxc = ((unsigned)gx < WID) ? gx : 0;
            const unsigned int* arr = (row < 32) ? (pr ? d_nwpl : d_nwph) : (pr ? d_refpl : d_refph);
            int rl = (row < 32) ? row : row - 32;
            const unsigned int* src = arr + (size_t)(b * 32 + rl) * HW + gyc * 256 + gxc;
            unsigned int* db = (pr ? sInL : sInH) + buf * SINB;
            cpa4((uint32_t)__cvta_generic_to_shared(db + c2l * CST + r * RST + (side ? 132 : 3)), src, ok);
        }
        for (int i = tid; i < 2304; i += 512) {
            int pr = i >= 1152;
            int ii = pr ? i - 1152 : i;
            const unsigned int* src = (pr ? d_w1bl : d_w1bh) + chunk * 4608 + ii * 4;
            unsigned int* db = (pr ? sWL : sWH) + buf * 4608;
            cpa16((uint32_t)__cvta_generic_to_shared(db + ii * 4), src, true);
        }
        cpcommit();
    };

    stage(0, 0);
    int bbase = tq * CST + 32 * g + gr + 3;
    for (int it = 0; it < 8; it++) {
        int buf = it & 1;
        cpwait();
        __syncthreads();
        if (it + 1 < 8) stage(it + 1, buf ^ 1);

        const unsigned int* siH = sInH + buf * SINB;
        const unsigned int* siL = sInL + buf * SINB;
        const unsigned int* swH = sWH + buf * 4608;
        const unsigned int* swL = sWL + buf * 4608;
#pragma unroll
        for (int dy = 0; dy < 3; dy++) {
#pragma unroll
            for (int dx = 0; dx < 3; dx++) {
                int tap = dy * 3 + dx;
                int wi = ((tap * 4 + h) * 32 + lane) * 4;
                uint4 Ah = *(const uint4*)(swH + wi);
                uint4 Al = *(const uint4*)(swL + wi);
                int fb = bbase + dy * RST + dx;
#pragma unroll
                for (int j = 0; j < 4; j++) {
                    int fi = fb + 8 * j;
                    uint32_t bh0 = siH[fi];
                    uint32_t bh1 = siH[fi + 4 * CST];
                    uint32_t bl0 = siL[fi];
                    uint32_t bl1 = siL[fi + 4 * CST];
                    mma16(acc[j], Ah, bh0, bh1);
                    mma16(acc[j], Ah, bl0, bl1);
                    mma16(acc[j], Al, bh0, bh1);
                }
            }
        }
        __syncthreads();
    }

#pragma unroll
    for (int j = 0; j < 4; j++) {
        int x = x0 + 32 * g + 8 * j + 2 * tq;
        int pA = y * 256 + x;
#pragma unroll
        for (int kk = 0; kk < 4; kk++) {
            int oc = 16 * h + gr + (kk >= 2 ? 8 : 0);
            int p = pA + (kk & 1);
            float v = acc[j][kk] + bias[oc];
            v = fmaxf(v, 0.f);
            float vp = __shfl_xor_sync(0xffffffffu, v, 4);
            if ((lane & 4) == 0) {
                float vh = bf16f(v), vph = bf16f(vp);
                int c2 = 8 * h + (kk >= 2 ? 4 : 0) + (gr >> 1);
                size_t o = (size_t)(b * 32 + c2) * HW + p;
                d_feaph[o] = pkbf(v, vp);
                d_feapl[o] = pkbf(v - vh, vp - vph);
            }
        }
    }
}

// ---------------- om via bf16 k16 MMA (3-term): 66->216, fused epilogue -----
// 512 thr: g=warp&3, h=warp>>2 (m-blocks 2h,2h+1). 5 chunks of 16 ch.
__global__ __launch_bounds__(512, 1)
void om_mma(const float* __restrict__ bias, const float* __restrict__ flow) {
    extern __shared__ unsigned int sm[];
    unsigned int* sInH = sm;              // [2][3392]
    unsigned int* sInL = sm + 6784;
    unsigned int* sWH  = sm + 13568;      // [2][9216]
    unsigned int* sWL  = sm + 32000;

    int tid = threadIdx.x;
    int warp = tid >> 5, lane = tid & 31;
    int g = warp & 3, h = warp >> 2;
    int gr = lane >> 2, tq = lane & 3;
    int bz = blockIdx.z;
    int b = bz >> 1, slice = bz & 1;
    int y = blockIdx.y, x0 = blockIdx.x * 128;

    float acc[4][2][4];
#pragma unroll
    for (int j = 0; j < 4; j++)
#pragma unroll
        for (int mi = 0; mi < 2; mi++)
#pragma unroll
            for (int k = 0; k < 4; k++) acc[j][mi][k] = 0.f;

    auto stage = [&](int chunk, int buf) {
        for (int i = tid; i < 1536; i += 512) {
            int pr = i >= 768;
            int ii = pr ? i - 768 : i;
            int c2l = ii / 96, rr = ii - c2l * 96;
            int r = rr >> 5, k = rr & 31;
            int row = chunk * 8 + c2l;
            int gy = y + r - 1;
            bool ok = ((unsigned)gy < HGT) && (row <= 32);
            int gyc = ((unsigned)gy < HGT) ? gy : 0;
            const unsigned int* arr;
            size_t base;
            if (row < 32) { arr = pr ? d_feapl : d_feaph; base = (size_t)(b * 32 + row) * HW; }
            else { arr = pr ? d_flwpl : d_flwph; base = (size_t)b * HW; }
            const unsigned int* src = arr + base + gyc * 256 + x0 + 4 * k;
            unsigned int* db = (pr ? sInL : sInH) + buf * SINB;
            cpa16((uint32_t)__cvta_generic_to_shared(db + c2l * CST + r * RST + 4 + 4 * k), src, ok);
        }
        for (int i = tid; i < 96; i += 512) {
            int pr = i >= 48;
            int ii = pr ? i - 48 : i;
            int c2l = ii / 6, rr = ii - c2l * 6;
            int r = rr >> 1, side = rr & 1;
            int row = chunk * 8 + c2l;
            int gy = y + r - 1;
            int gx = side ? x0 + 128 : x0 - 1;
            bool ok = ((unsigned)gy < HGT) && ((unsigned)gx < WID) && (row <= 32);
            int gyc = ((unsigned)gy < HGT) ? gy : 0;
            int gxc = ((unsigned)gx < WID) ? gx : 0;
            const unsigned int* arr;
            size_t base;
            if (row < 32) { arr = pr ? d_feapl : d_feaph; base = (size_t)(b * 32 + row) * HW; }
            else { arr = pr ? d_flwpl : d_flwph; base = (size_t)b * HW; }
            const unsigned int* src = arr + base + gyc * 256 + gxc;
            unsigned int* db = (pr ? sInL : sInH) + buf * SINB;
            cpa4((uint32_t)__cvta_generic_to_shared(db + c2l * CST + r * RST + (side ? 132 : 3)), src, ok);
        }
        for (int i = tid; i < 4608; i += 512) {
            int pr = i >= 2304;
            int ii = pr ? i - 2304 : i;
            const unsigned int* src = (pr ? d_wobl : d_wobh) + (slice * 5 + chunk) * 9216 + ii * 4;
            unsigned int* db = (pr ? sWL : sWH) + buf * 9216;
            cpa16((uint32_t)__cvta_generic_to_shared(db + ii * 4), src, true);
        }
        cpcommit();
    };

    stage(0, 0);
    int bbase = tq * CST + 32 * g + gr + 3;
    for (int it = 0; it < 5; it++) {
        int buf = it & 1;
        cpwait();
        __syncthreads();
        if (it + 1 < 5) stage(it + 1, buf ^ 1);

        const unsigned int* siH = sInH + buf * SINB;
        const unsigned int* siL = sInL + buf * SINB;
        const unsigned int* swH = sWH + buf * 9216;
        const unsigned int* swL = sWL + buf * 9216;
#pragma unroll
        for (int dy = 0; dy < 3; dy++) {
#pragma unroll
            for (int dx = 0; dx < 3; dx++) {
                int tap = dy * 3 + dx;
                int wi = ((tap * 8 + 2 * h) * 32 + lane) * 4;
                uint4 Ah0 = *(const uint4*)(swH + wi);
                uint4 Ah1 = *(const uint4*)(swH + wi + 128);
                uint4 Al0 = *(const uint4*)(swL + wi);
                uint4 Al1 = *(const uint4*)(swL + wi + 128);
                int fb = bbase + dy * RST + dx;
#pragma unroll
                for (int j = 0; j < 4; j++) {
                    int fi = fb + 8 * j;
                    uint32_t bh0 = siH[fi];
                    uint32_t bh1 = siH[fi + 4 * CST];
                    uint32_t bl0 = siL[fi];
                    uint32_t bl1 = siL[fi + 4 * CST];
                    mma16(acc[j][0], Ah0, bh0, bh1);
                    mma16(acc[j][0], Ah0, bl0, bl1);
                    mma16(acc[j][0], Al0, bh0, bh1);
                    mma16(acc[j][1], Ah1, bh0, bh1);
                    mma16(acc[j][1], Ah1, bl0, bl1);
                    mma16(acc[j][1], Al1, bh0, bh1);
                }
            }
        }
        __syncthreads();
    }

    int ocb = 128 * slice;
#pragma unroll
    for (int j = 0; j < 4; j++) {
        int x = x0 + 32 * g + 8 * j + 2 * tq;
        int pA = y * 256 + x;
#pragma unroll
        for (int mi = 0; mi < 2; mi++) {
            int chA = ocb + 16 * (2 * h + mi) + gr;
#pragma unroll
            for (int k = 0; k < 4; k++) {
                int ch = chA + (k >= 2 ? 8 : 0);
                if (ch >= 216) continue;
                int p = pA + (k & 1);
                float v = acc[j][mi][k] + bias[ch];
                if (ch < 144) {
                    v += (gr & 1) ? flow[(b * 2 + 0) * HW + p]
                                  : flow[(b * 2 + 1) * HW + p];
                } else {
                    v = 1.f / (1.f + expf(-v));
                }
                d_om[(size_t)(b * 216 + ch) * HW + p] = v;
            }
        }
    }
}

// ---------------- dcn via tf32 MMA (unchanged) ----------------
__device__ __forceinline__ void dcn_gather(const float* __restrict__ gbase,
                                           int x, int y, int ky, int kx,
                                           float dy, float dx, float m, float* vm) {
    float spy = (float)(y - 1 + ky) + dy;
    float spx = (float)(x - 1 + kx) + dx;
    float y0f = floorf(spy), x0f = floorf(spx);
    int iy0 = (int)y0f, ix0 = (int)x0f;
    float wy = spy - y0f, wx = spx - x0f;
    float v[8];
#pragma unroll
    for (int c = 0; c < 8; c++) v[c] = 0.f;
    float wts[4] = {(1.f - wy) * (1.f - wx), (1.f - wy) * wx, wy * (1.f - wx), wy * wx};
    int ys[4] = {iy0, iy0, iy0 + 1, iy0 + 1};
    int xs[4] = {ix0, ix0 + 1, ix0, ix0 + 1};
#pragma unroll
    for (int t = 0; t < 4; t++) {
        int yi = ys[t], xi = xs[t];
        if ((unsigned)yi < HGT && (unsigned)xi < WID) {
            const float4* q = (const float4*)(gbase + (size_t)(yi * WID + xi) * 8);
            float4 a = q[0];
            float4 bb = q[1];
            float wt = wts[t];
            v[0] += wt * a.x;  v[1] += wt * a.y;  v[2] += wt * a.z;  v[3] += wt * a.w;
            v[4] += wt * bb.x; v[5] += wt * bb.y; v[6] += wt * bb.z; v[7] += wt * bb.w;
        }
    }
#pragma unroll
    for (int c = 0; c < 8; c++) vm[c] = v[c] * m;
}

__global__ __launch_bounds__(256, 2)
void dcn_mma(const float* __restrict__ dcnb, float* __restrict__ out) {
    extern __shared__ float smf[];
    float* sWH = smf;
    float* sWL = smf + 4608;
    float* sBH = smf + 9216;

    int tid = threadIdx.x;
    int warp = tid >> 5, lane = tid & 31;
    int gr = lane >> 2, tq = lane & 3;
    int y = blockIdx.x, b = blockIdx.y;
    int x = warp * 32 + lane;
    int p = y * 256 + x;

    float acc[4][4][4];
#pragma unroll
    for (int mt = 0; mt < 4; mt++)
#pragma unroll
        for (int nt = 0; nt < 4; nt++)
#pragma unroll
            for (int r = 0; r < 4; r++) acc[mt][nt][r] = 0.f;

    float* myBH = sBH + warp * 320;

    for (int g = 0; g < 8; g++) {
        __syncthreads();
        for (int i = tid; i < 2304; i += 256) {
            int pr = i >= 1152;
            int ii = pr ? i - 1152 : i;
            const float* src = (pr ? d_wdpl : d_wdph) + g * 4608 + ii * 4;
            float* db = pr ? sWL : sWH;
            cpa16((uint32_t)__cvta_generic_to_shared(db + ii * 4), src, true);
        }
        cpcommit();
        cpwait();
        __syncthreads();

        const float* gbase = d_nbr_t + (size_t)(b * 8 + g) * HW * 8;
        const float* omb = d_om + (size_t)b * 216 * HW;

#pragma unroll 1
        for (int k = 0; k < 9; k++) {
            int ky = k / 3, kx = k - ky * 3;
            int ch = g * 9 + k;
            float dy = omb[(ch * 2) * HW + p];
            float dx = omb[(ch * 2 + 1) * HW + p];
            float m = omb[(144 + ch) * HW + p];
            float vm[8];
            dcn_gather(gbase, x, y, ky, kx, dy, dx, m, vm);
            __syncwarp();
#pragma unroll
            for (int c = 0; c < 8; c++) {
                myBH[c * 40 + lane] = rna(vm[c]);
            }
            __syncwarp();
            uint32_t b0[4], b1[4];
#pragma unroll
            for (int nt = 0; nt < 4; nt++) {
                int bi = tq * 40 + nt * 8 + gr;
                b0[nt] = __float_as_uint(myBH[bi]);
                b1[nt] = __float_as_uint(myBH[bi + 160]);
            }
#pragma unroll
            for (int mt = 0; mt < 4; mt++) {
                int wi = ((k * 4 + mt) * 32 + lane) * 4;
                uint4 Ah = *(const uint4*)(sWH + wi);
                uint4 Al = *(const uint4*)(sWL + wi);
#pragma unroll
                for (int nt = 0; nt < 4; nt++) {
                    mma8t(acc[mt][nt], Ah, b0[nt], b1[nt]);
                    mma8t(acc[mt][nt], Al, b0[nt], b1[nt]);
                }
            }
            __syncwarp();
        }
    }

#pragma unroll
    for (int mt = 0; mt < 4; mt++)
#pragma unroll
        for (int nt = 0; nt < 4; nt++) {
            int xo = warp * 32 + nt * 8 + 2 * tq;
            int pb = y * 256 + xo;
#pragma unroll
            for (int r = 0; r < 4; r++) {
                int oc = 16 * mt + gr + (r >= 2 ? 8 : 0);
                int pp = pb + (r & 1);
                out[(b * 64 + oc) * HW + pp] = acc[mt][nt][r] + dcnb[oc];
            }
        }
}

// ---------------- launch ----------------
extern "C" void kernel_launch(void* const* d_in, const int* in_sizes, int n_in,
                              void* d_out, int out_size) {
    const float* nbr = (const float*)d_in[0];
    const float* ref = (const float*)d_in[1];
    const float* flow = (const float*)d_in[2];
    const float* conv1_w = (const float*)d_in[3];
    const float* conv1_b = (const float*)d_in[4];
    const float* om_w = (const float*)d_in[5];
    const float* om_b = (const float*)d_in[6];
    const float* dcn_w = (const float*)d_in[7];
    const float* dcn_b = (const float*)d_in[8];
    float* out = (float*)d_out;

    static bool attr_done = false;
    if (!attr_done) {
        cudaFuncSetAttribute(conv1_mma, cudaFuncAttributeMaxDynamicSharedMemorySize, 128000);
        cudaFuncSetAttribute(om_mma, cudaFuncAttributeMaxDynamicSharedMemorySize, 201728);
        cudaFuncSetAttribute(dcn_mma, cudaFuncAttributeMaxDynamicSharedMemorySize, 49152);
        attr_done = true;
    }

    int prep_total = PN0 + PN1 + PN2 + PN3 + PN4;
    prep_all<<<(prep_total + 255) / 256, 256>>>(ref, flow, conv1_w, om_w, dcn_w);
    transpose_kernel<<<(BAT * DG * HW + 255) / 256, 256>>>(nbr);
    warp_kernel<<<(BAT * HW + 255) / 256, 256>>>(flow);
    conv1_mma<<<dim3(2, 256, BAT), 512, 128000>>>(conv1_b);
    om_mma<<<dim3(2, 256, BAT * 2), 512, 201728>>>(om_b, flow);
    dcn_mma<<<dim3(256, BAT), 256, 49152>>>(dcn_b, out);
}

// round 13
// speedup vs baseline: 2.9045x; 1.0197x over previous
#include <cuda_runtime.h>
#include <cuda_bf16.h>
#include <stdint.h>
#include <math.h>

#define WID 256
#define HGT 256
#define HW  65536
#define BAT 2
#define NF  64
#define DG  8
#define CST 424
#define RST 136
#define SINB 3392
// conv1 full-row tile constants
#define C1CST 808          // channel-pair stride (808 % 32 == 8 -> conflict-free)
#define C1RST 264          // row stride (256 px + 2 halo + pad)
#define C1SINB 6464        // 8 * 808

// fp32 scratch (dcn path)
__device__ float d_nbr_t[BAT * DG * HW * 8];
__device__ float d_om[BAT * 216 * HW];
__device__ float d_wdph[36864];
__device__ float d_wdpl[36864];
// bf16 packed-pair activations (uint32 = 2 channels) hi/lo
__device__ unsigned int d_nwph[BAT * 32 * HW];
__device__ unsigned int d_nwpl[BAT * 32 * HW];
__device__ unsigned int d_refph[BAT * 32 * HW];
__device__ unsigned int d_refpl[BAT * 32 * HW];
__device__ unsigned int d_feaph[BAT * 32 * HW];
__device__ unsigned int d_feapl[BAT * 32 * HW];
__device__ unsigned int d_flwph[BAT * HW];
__device__ unsigned int d_flwpl[BAT * HW];
// bf16 packed weights (A-fragment layout)
__device__ unsigned int d_w1bh[36864];
__device__ unsigned int d_w1bl[36864];
__device__ unsigned int d_wobh[92160];
__device__ unsigned int d_wobl[92160];

__device__ __forceinline__ float rna(float x) {
    uint32_t u; asm("cvt.rna.tf32.f32 %0, %1;" : "=r"(u) : "f"(x));
    return __uint_as_float(u);
}
__device__ __forceinline__ float bf16f(float x) {
    return __bfloat162float(__float2bfloat16_rn(x));
}
__device__ __forceinline__ uint32_t pkbf(float a, float b) {
    uint32_t lo = (uint32_t)__bfloat16_as_ushort(__float2bfloat16_rn(a));
    uint32_t hi = (uint32_t)__bfloat16_as_ushort(__float2bfloat16_rn(b));
    return lo | (hi << 16);
}
__device__ __forceinline__ void mma16(float* c, const uint4& a, uint32_t b0, uint32_t b1) {
    asm volatile("mma.sync.aligned.m16n8k16.row.col.f32.bf16.bf16.f32 "
                 "{%0,%1,%2,%3},{%4,%5,%6,%7},{%8,%9},{%0,%1,%2,%3};"
                 : "+f"(c[0]), "+f"(c[1]), "+f"(c[2]), "+f"(c[3])
                 : "r"(a.x), "r"(a.y), "r"(a.z), "r"(a.w), "r"(b0), "r"(b1));
}
__device__ __forceinline__ void mma8t(float* c, const uint4& a, uint32_t b0, uint32_t b1) {
    asm volatile("mma.sync.aligned.m16n8k8.row.col.f32.tf32.tf32.f32 "
                 "{%0,%1,%2,%3},{%4,%5,%6,%7},{%8,%9},{%0,%1,%2,%3};"
                 : "+f"(c[0]), "+f"(c[1]), "+f"(c[2]), "+f"(c[3])
                 : "r"(a.x), "r"(a.y), "r"(a.z), "r"(a.w), "r"(b0), "r"(b1));
}
__device__ __forceinline__ void cpa16(uint32_t d, const void* s, bool ok) {
    int sz = ok ? 16 : 0;
    asm volatile("cp.async.cg.shared.global [%0], [%1], 16, %2;" :: "r"(d), "l"(s), "r"(sz) : "memory");
}
__device__ __forceinline__ void cpa4(uint32_t d, const void* s, bool ok) {
    int sz = ok ? 4 : 0;
    asm volatile("cp.async.ca.shared.global [%0], [%1], 4, %2;" :: "r"(d), "l"(s), "r"(sz) : "memory");
}
__device__ __forceinline__ void cpcommit() { asm volatile("cp.async.commit_group;" ::: "memory"); }
__device__ __forceinline__ void cpwait() { asm volatile("cp.async.wait_group 0;" ::: "memory"); }

// ---------------- fused prep ----------------
#define PN0 1048576
#define PN1 32768
#define PN2 36864
#define PN3 92160
#define PN4 9216
__global__ void prep_all(const float* __restrict__ ref, const float* __restrict__ flow,
                         const float* __restrict__ w1, const float* __restrict__ wom,
                         const float* __restrict__ wd) {
    int idx = blockIdx.x * blockDim.x + threadIdx.x;
    if (idx < PN0) {
        int row = idx / 16384;
        int p4 = idx - row * 16384;
        int b = row >> 5, c2 = row & 31;
        int pix = p4 * 4;
        float4 va = *(const float4*)(ref + (size_t)(b * 64 + 2 * c2) * HW + pix);
        float4 vb = *(const float4*)(ref + (size_t)(b * 64 + 2 * c2 + 1) * HW + pix);
        const float* ap = &va.x; const float* bp = &vb.x;
        uint4 wh, wl;
        uint32_t* whp = &wh.x; uint32_t* wlp = &wl.x;
#pragma unroll
        for (int j = 0; j < 4; j++) {
            float a = ap[j], c = bp[j];
            float ah = bf16f(a), ch = bf16f(c);
            whp[j] = pkbf(a, c);
            wlp[j] = pkbf(a - ah, c - ch);
        }
        ((uint4*)d_refph)[idx] = wh;
        ((uint4*)d_refpl)[idx] = wl;
        return;
    }
    idx -= PN0;
    if (idx < PN1) {
        int b = idx / 16384;
        int pix = (idx - b * 16384) * 4;
        float4 fx4 = *(const float4*)(flow + (size_t)(b * 2) * HW + pix);
        float4 fy4 = *(const float4*)(flow + (size_t)(b * 2 + 1) * HW + pix);
        const float* xp = &fx4.x; const float* yp = &fy4.x;
        uint4 wh, wl;
        uint32_t* whp = &wh.x; uint32_t* wlp = &wl.x;
#pragma unroll
        for (int j = 0; j < 4; j++) {
            float a = xp[j], c = yp[j];
            float ah = bf16f(a), ch = bf16f(c);
            whp[j] = pkbf(a, c);
            wlp[j] = pkbf(a - ah, c - ch);
        }
        ((uint4*)d_flwph)[idx] = wh;
        ((uint4*)d_flwpl)[idx] = wl;
        return;
    }
    idx -= PN1;
    if (idx < PN2) {
        int vi = idx & 3;
        int lane = (idx >> 2) & 31;
        int m = (idx >> 7) & 3;
        int tap = (idx >> 9) % 9;
        int chunk = idx / 4608;
        int gr = lane >> 2, tq = lane & 3;
        int oc = 16 * m + gr + (vi & 1) * 8;
        int kb = 16 * chunk + 2 * tq + ((vi >> 1) ? 8 : 0);
        float v0 = w1[(oc * 128 + kb) * 9 + tap];
        float v1 = w1[(oc * 128 + kb + 1) * 9 + tap];
        float h0 = bf16f(v0), h1 = bf16f(v1);
        d_w1bh[idx] = pkbf(v0, v1);
        d_w1bl[idx] = pkbf(v0 - h0, v1 - h1);
        return;
    }
    idx -= PN2;
    if (idx < PN3) {
        int cs = idx / 9216;
        int w = idx - cs * 9216;
        int slice = cs / 5, chunk = cs - slice * 5;
        int tap = w / 1024;
        int r2 = w - tap * 1024;
        int m = r2 >> 7;
        int lane = (r2 >> 2) & 31;
        int vi = r2 & 3;
        int gr = lane >> 2, tq = lane & 3;
        int oc = 128 * slice + 16 * m + gr + (vi & 1) * 8;
        int kb = 16 * chunk + 2 * tq + ((vi >> 1) ? 8 : 0);
        float v0 = 0.f, v1 = 0.f;
        if (oc < 216 && kb < 66) v0 = wom[(oc * 66 + kb) * 9 + tap];
        if (oc < 216 && kb + 1 < 66) v1 = wom[(oc * 66 + kb + 1) * 9 + tap];
        float h0 = bf16f(v0), h1 = bf16f(v1);
        d_wobh[idx] = pkbf(v0, v1);
        d_wobl[idx] = pkbf(v0 - h0, v1 - h1);
        return;
    }
    idx -= PN3;
    if (idx < PN4) {
        int g = idx / 1152, r = idx % 1152;
        int tap = r / 128, r2 = r & 127;
        int mt = r2 >> 5, lane = r2 & 31;
        int gr = lane >> 2, tq = lane & 3;
        float4 h, l; float* hp = &h.x; float* lp = &l.x;
#pragma unroll
        for (int vi = 0; vi < 4; vi++) {
            int oc = 16 * mt + gr + (vi & 1) * 8;
            int kc = tq + (vi >> 1) * 4;
            float v = wd[(oc * 64 + g * 8 + kc) * 9 + tap];
            float hv = rna(v); hp[vi] = hv; lp[vi] = rna(v - hv);
        }
        ((float4*)d_wdph)[idx] = h;
        ((float4*)d_wdpl)[idx] = l;
    }
}

// ---------------- transpose for dcn + warp ----------------
__global__ void transpose_kernel(const float* __restrict__ nbr) {
    int idx = blockIdx.x * blockDim.x + threadIdx.x;
    if (idx >= BAT * DG * HW) return;
    int bg = idx >> 16, p = idx & 65535;
    int b = bg >> 3, g = bg & 7;
    float v[8];
#pragma unroll
    for (int c = 0; c < 8; c++) v[c] = nbr[((b * NF + g * 8 + c) * HW) + p];
    float4* dst = (float4*)&d_nbr_t[(size_t)idx * 8];
    dst[0] = make_float4(v[0], v[1], v[2], v[3]);
    dst[1] = make_float4(v[4], v[5], v[6], v[7]);
}

// ---------------- warp (bilinear) -> packed bf16 hi/lo ----------------
__global__ void warp_kernel(const float* __restrict__ flow) {
    int idx = blockIdx.x * blockDim.x + threadIdx.x;
    if (idx >= BAT * HW) return;
    int b = idx >> 16, p = idx & 65535;
    int y = p >> 8, x = p & 255;
    float fx = flow[(b * 2 + 0) * HW + p];
    float fy = flow[(b * 2 + 1) * HW + p];
    float px = (float)x + fx, py = (float)y + fy;
    float x0f = floorf(px), y0f = floorf(py);
    int ix0 = (int)x0f, iy0 = (int)y0f;
    float wx = px - x0f, wy = py - y0f;
    bool vx0 = (unsigned)ix0 < WID, vx1 = (unsigned)(ix0 + 1) < WID;
    bool vy0 = (unsigned)iy0 < HGT, vy1 = (unsigned)(iy0 + 1) < HGT;
    float w00 = (vy0 && vx0) ? (1.f - wy) * (1.f - wx) : 0.f;
    float w01 = (vy0 && vx1) ? (1.f - wy) * wx : 0.f;
    float w10 = (vy1 && vx0) ? wy * (1.f - wx) : 0.f;
    float w11 = (vy1 && vx1) ? wy * wx : 0.f;
    int cx0 = min(max(ix0, 0), WID - 1), cx1 = min(max(ix0 + 1, 0), WID - 1);
    int cy0 = min(max(iy0, 0), HGT - 1), cy1 = min(max(iy0 + 1, 0), HGT - 1);
    size_t i00 = (size_t)(cy0 * WID + cx0) * 8;
    size_t i01 = (size_t)(cy0 * WID + cx1) * 8;
    size_t i10 = (size_t)(cy1 * WID + cx0) * 8;
    size_t i11 = (size_t)(cy1 * WID + cx1) * 8;

#pragma unroll 1
    for (int g = 0; g < 8; g++) {
        const float* gb = d_nbr_t + (size_t)(b * 8 + g) * HW * 8;
        float v[8];
#pragma unroll
        for (int half = 0; half < 2; half++) {
            float4 a00 = *(const float4*)(gb + i00 + 4 * half);
            float4 a01 = *(const float4*)(gb + i01 + 4 * half);
            float4 a10 = *(const float4*)(gb + i10 + 4 * half);
            float4 a11 = *(const float4*)(gb + i11 + 4 * half);
            v[4 * half + 0] = w00 * a00.x + w01 * a01.x + w10 * a10.x + w11 * a11.x;
            v[4 * half + 1] = w00 * a00.y + w01 * a01.y + w10 * a10.y + w11 * a11.y;
            v[4 * half + 2] = w00 * a00.z + w01 * a01.z + w10 * a10.z + w11 * a11.z;
            v[4 * half + 3] = w00 * a00.w + w01 * a01.w + w10 * a10.w + w11 * a11.w;
        }
#pragma unroll
        for (int cl = 0; cl < 4; cl++) {
            float a = v[2 * cl], c = v[2 * cl + 1];
            float ah = bf16f(a), ch = bf16f(c);
            size_t o = (size_t)(b * 32 + g * 4 + cl) * HW + p;
            d_nwph[o] = pkbf(a, c);
            d_nwpl[o] = pkbf(a - ah, c - ch);
        }
    }
}

// ---------------- conv1: bf16 k16, full-row, 2 m-blocks/warp ----------------
// grid (256 rows, BAT); 512 thr; g=warp&7 (32px groups), h=warp>>3 (m 2h,2h+1)
__global__ __launch_bounds__(512, 1)
void conv1_mma(const float* __restrict__ bias) {
    extern __shared__ unsigned int sm[];
    unsigned int* sInH = sm;                   // [2][6464]
    unsigned int* sInL = sm + 12928;
    unsigned int* sWH  = sm + 25856;           // [2][4608]
    unsigned int* sWL  = sm + 35072;

    int tid = threadIdx.x;
    int warp = tid >> 5, lane = tid & 31;
    int g = warp & 7, h = warp >> 3;
    int gr = lane >> 2, tq = lane & 3;
    int y = blockIdx.x, b = blockIdx.y;

    float acc[4][2][4];
#pragma unroll
    for (int j = 0; j < 4; j++)
#pragma unroll
        for (int mi = 0; mi < 2; mi++)
#pragma unroll
            for (int k = 0; k < 4; k++) acc[j][mi][k] = 0.f;

    auto stage = [&](int chunk, int buf) {
        for (int i = tid; i < 3072; i += 512) {
            int pr = i >= 1536;
            int ii = pr ? i - 1536 : i;
            int c2l = ii / 192, rr = ii - c2l * 192;
            int r = rr >> 6, k = rr & 63;
            int row = chunk * 8 + c2l;
            int gy = y + r - 1;
            bool ok = (unsigned)gy < HGT;
            int gyc = ok ? gy : 0;
            const unsigned int* arr = (row < 32) ? (pr ? d_nwpl : d_nwph) : (pr ? d_refpl : d_refph);
            int rl = (row < 32) ? row : row - 32;
            const unsigned int* src = arr + (size_t)(b * 32 + rl) * HW + gyc * 256 + 4 * k;
            unsigned int* db = (pr ? sInL : sInH) + buf * C1SINB;
            cpa16((uint32_t)__cvta_generic_to_shared(db + c2l * C1CST + r * C1RST + 4 + 4 * k), src, ok);
        }
        for (int i = tid; i < 96; i += 512) {
            int pr = i >= 48;
            int ii = pr ? i - 48 : i;
            int c2l = ii / 6, rr = ii - c2l * 6;
            int r = rr >> 1, side = rr & 1;
            int row = chunk * 8 + c2l;
            int gy = y + r - 1;
            int gx = side ? 256 : -1;
            bool ok = ((unsigned)gy < HGT) && ((unsigned)gx < WID);
            int gyc = ((unsigned)gy < HGT) ? gy : 0;
            int gxc = ((unsigned)gx < WID) ? gx : 0;
            const unsigned int* arr = (row < 32) ? (pr ? d_nwpl : d_nwph) : (pr ? d_refpl : d_refph);
            int rl = (row < 32) ? row : row - 32;
            const unsigned int* src = arr + (size_t)(b * 32 + rl) * HW + gyc * 256 + gxc;
            unsigned int* db = (pr ? sInL : sInH) + buf * C1SINB;
            cpa4((uint32_t)__cvta_generic_to_shared(db + c2l * C1CST + r * C1RST + (side ? 260 : 3)), src, ok);
        }
        for (int i = tid; i < 2304; i += 512) {
            int pr = i >= 1152;
            int ii = pr ? i - 1152 : i;
            const unsigned int* src = (pr ? d_w1bl : d_w1bh) + chunk * 4608 + ii * 4;
            unsigned int* db = (pr ? sWL : sWH) + buf * 4608;
            cpa16((uint32_t)__cvta_generic_to_shared(db + ii * 4), src, true);
        }
        cpcommit();
    };

    stage(0, 0);
    int bbase = tq * C1CST + 32 * g + gr + 3;
    for (int it = 0; it < 8; it++) {
        int buf = it & 1;
        cpwait();
        __syncthreads();
        if (it + 1 < 8) stage(it + 1, buf ^ 1);

        const unsigned int* siH = sInH + buf * C1SINB;
        const unsigned int* siL = sInL + buf * C1SINB;
        const unsigned int* swH = sWH + buf * 4608;
        const unsigned int* swL = sWL + buf * 4608;
#pragma unroll
        for (int dy = 0; dy < 3; dy++) {
#pragma unroll
            for (int dx = 0; dx < 3; dx++) {
                int tap = dy * 3 + dx;
                int wi = ((tap * 4 + 2 * h) * 32 + lane) * 4;
                uint4 Ah0 = *(const uint4*)(swH + wi);
                uint4 Ah1 = *(const uint4*)(swH + wi + 128);
                uint4 Al0 = *(const uint4*)(swL + wi);
                uint4 Al1 = *(const uint4*)(swL + wi + 128);
                int fb = bbase + dy * C1RST + dx;
#pragma unroll
                for (int j = 0; j < 4; j++) {
                    int fi = fb + 8 * j;
                    uint32_t bh0 = siH[fi];
                    uint32_t bh1 = siH[fi + 4 * C1CST];
                    uint32_t bl0 = siL[fi];
                    uint32_t bl1 = siL[fi + 4 * C1CST];
                    mma16(acc[j][0], Ah0, bh0, bh1);
                    mma16(acc[j][0], Ah0, bl0, bl1);
                    mma16(acc[j][0], Al0, bh0, bh1);
                    mma16(acc[j][1], Ah1, bh0, bh1);
                    mma16(acc[j][1], Ah1, bl0, bl1);
                    mma16(acc[j][1], Al1, bh0, bh1);
                }
            }
        }
        __syncthreads();
    }

#pragma unroll
    for (int j = 0; j < 4; j++) {
        int x = 32 * g + 8 * j + 2 * tq;
        int pA = y * 256 + x;
#pragma unroll
        for (int mi = 0; mi < 2; mi++) {
            int m = 2 * h + mi;
#pragma unroll
            for (int kk = 0; kk < 4; kk++) {
                int oc = 16 * m + gr + (kk >= 2 ? 8 : 0);
                int p = pA + (kk & 1);
                float v = acc[j][mi][kk] + bias[oc];
                v = fmaxf(v, 0.f);
                float vp = __shfl_xor_sync(0xffffffffu, v, 4);
                if ((lane & 4) == 0) {
                    float vh = bf16f(v), vph = bf16f(vp);
                    int c2 = 8 * m + (kk >= 2 ? 4 : 0) + (gr >> 1);
                    size_t o = (size_t)(b * 32 + c2) * HW + p;
                    d_feaph[o] = pkbf(v, vp);
                    d_feapl[o] = pkbf(v - vh, vp - vph);
                }
            }
        }
    }
}

// ---------------- om via bf16 k16 MMA (3-term): 66->216, fused epilogue -----
__global__ __launch_bounds__(512, 1)
void om_mma(const float* __restrict__ bias, const float* __restrict__ flow) {
    extern __shared__ unsigned int sm[];
    unsigned int* sInH = sm;
    unsigned int* sInL = sm + 6784;
    unsigned int* sWH  = sm + 13568;
    unsigned int* sWL  = sm + 32000;

    int tid = threadIdx.x;
    int warp = tid >> 5, lane = tid & 31;
    int g = warp & 3, h = warp >> 2;
    int gr = lane >> 2, tq = lane & 3;
    int bz = blockIdx.z;
    int b = bz >> 1, slice = bz & 1;
    int y = blockIdx.y, x0 = blockIdx.x * 128;

    float acc[4][2][4];
#pragma unroll
    for (int j = 0; j < 4; j++)
#pragma unroll
        for (int mi = 0; mi < 2; mi++)
#pragma unroll
            for (int k = 0; k < 4; k++) acc[j][mi][k] = 0.f;

    auto stage = [&](int chunk, int buf) {
        for (int i = tid; i < 1536; i += 512) {
            int pr = i >= 768;
            int ii = pr ? i - 768 : i;
            int c2l = ii / 96, rr = ii - c2l * 96;
            int r = rr >> 5, k = rr & 31;
            int row = chunk * 8 + c2l;
            int gy = y + r - 1;
            bool ok = ((unsigned)gy < HGT) && (row <= 32);
            int gyc = ((unsigned)gy < HGT) ? gy : 0;
            const unsigned int* arr;
            size_t base;
            if (row < 32) { arr = pr ? d_feapl : d_feaph; base = (size_t)(b * 32 + row) * HW; }
            else { arr = pr ? d_flwpl : d_flwph; base = (size_t)b * HW; }
            const unsigned int* src = arr + base + gyc * 256 + x0 + 4 * k;
            unsigned int* db = (pr ? sInL : sInH) + buf * SINB;
            cpa16((uint32_t)__cvta_generic_to_shared(db + c2l * CST + r * RST + 4 + 4 * k), src, ok);
        }
        for (int i = tid; i < 96; i += 512) {
            int pr = i >= 48;
            int ii = pr ? i - 48 : i;
            int c2l = ii / 6, rr = ii - c2l * 6;
            int r = rr >> 1, side = rr & 1;
            int row = chunk * 8 + c2l;
            int gy = y + r - 1;
            int gx = side ? x0 + 128 : x0 - 1;
            bool ok = ((unsigned)gy < HGT) && ((unsigned)gx < WID) && (row <= 32);
            int gyc = ((unsigned)gy < HGT) ? gy : 0;
            int gxc = ((unsigned)gx < WID) ? gx : 0;
            const unsigned int* arr;
            size_t base;
            if (row < 32) { arr = pr ? d_feapl : d_feaph; base = (size_t)(b * 32 + row) * HW; }
            else { arr = pr ? d_flwpl : d_flwph; base = (size_t)b * HW; }
            const unsigned int* src = arr + base + gyc * 256 + gxc;
            unsigned int* db = (pr ? sInL : sInH) + buf * SINB;
            cpa4((uint32_t)__cvta_generic_to_shared(db + c2l * CST + r * RST + (side ? 132 : 3)), src, ok);
        }
        for (int i = tid; i < 4608; i += 512) {
            int pr = i >= 2304;
            int ii = pr ? i - 2304 : i;
            const unsigned int* src = (pr ? d_wobl : d_wobh) + (slice * 5 + chunk) * 9216 + ii * 4;
            unsigned int* db = (pr ? sWL : sWH) + buf * 9216;
            cpa16((uint32_t)__cvta_generic_to_shared(db + ii * 4), src, true);
        }
        cpcommit();
    };

    stage(0, 0);
    int bbase = tq * CST + 32 * g + gr + 3;
    for (int it = 0; it < 5; it++) {
        int buf = it & 1;
        cpwait();
        __syncthreads();
        if (it + 1 < 5) stage(it + 1, buf ^ 1);

        const unsigned int* siH = sInH + buf * SINB;
        const unsigned int* siL = sInL + buf * SINB;
        const unsigned int* swH = sWH + buf * 9216;
        const unsigned int* swL = sWL + buf * 9216;
#pragma unroll
        for (int dy = 0; dy < 3; dy++) {
#pragma unroll
            for (int dx = 0; dx < 3; dx++) {
                int tap = dy * 3 + dx;
                int wi = ((tap * 8 + 2 * h) * 32 + lane) * 4;
                uint4 Ah0 = *(const uint4*)(swH + wi);
                uint4 Ah1 = *(const uint4*)(swH + wi + 128);
                uint4 Al0 = *(const uint4*)(swL + wi);
                uint4 Al1 = *(const uint4*)(swL + wi + 128);
                int fb = bbase + dy * RST + dx;
#pragma unroll
                for (int j = 0; j < 4; j++) {
                    int fi = fb + 8 * j;
                    uint32_t bh0 = siH[fi];
                    uint32_t bh1 = siH[fi + 4 * CST];
                    uint32_t bl0 = siL[fi];
                    uint32_t bl1 = siL[fi + 4 * CST];
                    mma16(acc[j][0], Ah0, bh0, bh1);
                    mma16(acc[j][0], Ah0, bl0, bl1);
                    mma16(acc[j][0], Al0, bh0, bh1);
                    mma16(acc[j][1], Ah1, bh0, bh1);
                    mma16(acc[j][1], Ah1, bl0, bl1);
                    mma16(acc[j][1], Al1, bh0, bh1);
                }
            }
        }
        __syncthreads();
    }

    int ocb = 128 * slice;
#pragma unroll
    for (int j = 0; j < 4; j++) {
        int x = x0 + 32 * g + 8 * j + 2 * tq;
        int pA = y * 256 + x;
#pragma unroll
        for (int mi = 0; mi < 2; mi++) {
            int chA = ocb + 16 * (2 * h + mi) + gr;
#pragma unroll
            for (int k = 0; k < 4; k++) {
                int ch = chA + (k >= 2 ? 8 : 0);
                if (ch >= 216) continue;
                int p = pA + (k & 1);
                float v = acc[j][mi][k] + bias[ch];
                if (ch < 144) {
                    v += (gr & 1) ? flow[(b * 2 + 0) * HW + p]
                                  : flow[(b * 2 + 1) * HW + p];
                } else {
                    v = 1.f / (1.f + expf(-v));
                }
                d_om[(size_t)(b * 216 + ch) * HW + p] = v;
            }
        }
    }
}

// ---------------- dcn via tf32 MMA, software-pipelined gathers ----------------
__device__ __forceinline__ void dcn_gather(const float* __restrict__ gbase,
                                           int x, int y, int ky, int kx,
                                           float dy, float dx, float m, float* vm) {
    float spy = (float)(y - 1 + ky) + dy;
    float spx = (float)(x - 1 + kx) + dx;
    float y0f = floorf(spy), x0f = floorf(spx);
    int iy0 = (int)y0f, ix0 = (int)x0f;
    float wy = spy - y0f, wx = spx - x0f;
    float v[8];
#pragma unroll
    for (int c = 0; c < 8; c++) v[c] = 0.f;
    float wts[4] = {(1.f - wy) * (1.f - wx), (1.f - wy) * wx, wy * (1.f - wx), wy * wx};
    int ys[4] = {iy0, iy0, iy0 + 1, iy0 + 1};
    int xs[4] = {ix0, ix0 + 1, ix0, ix0 + 1};
#pragma unroll
    for (int t = 0; t < 4; t++) {
        int yi = ys[t], xi = xs[t];
        if ((unsigned)yi < HGT && (unsigned)xi < WID) {
            const float4* q = (const float4*)(gbase + (size_t)(yi * WID + xi) * 8);
            float4 a = q[0];
            float4 bb = q[1];
            float wt = wts[t];
            v[0] += wt * a.x;  v[1] += wt * a.y;  v[2] += wt * a.z;  v[3] += wt * a.w;
            v[4] += wt * bb.x; v[5] += wt * bb.y; v[6] += wt * bb.z; v[7] += wt * bb.w;
        }
    }
#pragma unroll
    for (int c = 0; c < 8; c++) vm[c] = v[c] * m;
}

__global__ __launch_bounds__(256, 2)
void dcn_mma(const float* __restrict__ dcnb, float* __restrict__ out) {
    extern __shared__ float smf[];
    float* sWH = smf;
    float* sWL = smf + 4608;
    float* sBH = smf + 9216;

    int tid = threadIdx.x;
    int warp = tid >> 5, lane = tid & 31;
    int gr = lane >> 2, tq = lane & 3;
    int y = blockIdx.x, b = blockIdx.y;
    int x = warp * 32 + lane;
    int p = y * 256 + x;

    float acc[4][4][4];
#pragma unroll
    for (int mt = 0; mt < 4; mt++)
#pragma unroll
        for (int nt = 0; nt < 4; nt++)
#pragma unroll
            for (int r = 0; r < 4; r++) acc[mt][nt][r] = 0.f;

    float* myBH = sBH + warp * 320;

    for (int g = 0; g < 8; g++) {
        // prefetch all 9 taps' offsets/masks (27 independent LDGs -> MLP)
        const float* omb = d_om + (size_t)b * 216 * HW;
        float ody[9], odx[9], omk[9];
#pragma unroll
        for (int k = 0; k < 9; k++) {
            int ch = g * 9 + k;
            ody[k] = omb[(ch * 2) * HW + p];
            odx[k] = omb[(ch * 2 + 1) * HW + p];
            omk[k] = omb[(144 + ch) * HW + p];
        }

        __syncthreads();
        for (int i = tid; i < 2304; i += 256) {
            int pr = i >= 1152;
            int ii = pr ? i - 1152 : i;
            const float* src = (pr ? d_wdpl : d_wdph) + g * 4608 + ii * 4;
            float* db = pr ? sWL : sWH;
            cpa16((uint32_t)__cvta_generic_to_shared(db + ii * 4), src, true);
        }
        cpcommit();
        cpwait();
        __syncthreads();

        const float* gbase = d_nbr_t + (size_t)(b * 8 + g) * HW * 8;

        float vm[8];
        dcn_gather(gbase, x, y, 0, 0, ody[0], odx[0], omk[0], vm);

#pragma unroll 1
        for (int k = 0; k < 9; k++) {
#pragma unroll
            for (int c = 0; c < 8; c++) {
                myBH[c * 40 + lane] = rna(vm[c]);
            }
            __syncwarp();

            // issue next tap's gather LDGs before this tap's LDS+MMA
            float vmn[8];
            if (k < 8) {
                int kn = k + 1;
                dcn_gather(gbase, x, y, kn / 3, kn - (kn / 3) * 3,
                           ody[kn], odx[kn], omk[kn], vmn);
            }

            uint32_t b0[4], b1[4];
#pragma unroll
            for (int nt = 0; nt < 4; nt++) {
                int bi = tq * 40 + nt * 8 + gr;
                b0[nt] = __float_as_uint(myBH[bi]);
                b1[nt] = __float_as_uint(myBH[bi + 160]);
            }
#pragma unroll
            for (int mt = 0; mt < 4; mt++) {
                int wi = ((k * 4 + mt) * 32 + lane) * 4;
                uint4 Ah = *(const uint4*)(sWH + wi);
                uint4 Al = *(const uint4*)(sWL + wi);
#pragma unroll
                for (int nt = 0; nt < 4; nt++) {
                    mma8t(acc[mt][nt], Ah, b0[nt], b1[nt]);
                    mma8t(acc[mt][nt], Al, b0[nt], b1[nt]);
                }
            }
            __syncwarp();
#pragma unroll
            for (int c = 0; c < 8; c++) vm[c] = vmn[c];
        }
    }

#pragma unroll
    for (int mt = 0; mt < 4; mt++)
#pragma unroll
        for (int nt = 0; nt < 4; nt++) {
            int xo = warp * 32 + nt * 8 + 2 * tq;
            int pb = y * 256 + xo;
#pragma unroll
            for (int r = 0; r < 4; r++) {
                int oc = 16 * mt + gr + (r >= 2 ? 8 : 0);
                int pp = pb + (r & 1);
                out[(b * 64 + oc) * HW + pp] = acc[mt][nt][r] + dcnb[oc];
            }
        }
}

// ---------------- launch ----------------
extern "C" void kernel_launch(void* const* d_in, const int* in_sizes, int n_in,
                              void* d_out, int out_size) {
    const float* nbr = (const float*)d_in[0];
    const float* ref = (const float*)d_in[1];
    const float* flow = (const float*)d_in[2];
    const float* conv1_w = (const float*)d_in[3];
    const float* conv1_b = (const float*)d_in[4];
    const float* om_w = (const float*)d_in[5];
    const float* om_b = (const float*)d_in[6];
    const float* dcn_w = (const float*)d_in[7];
    const float* dcn_b = (const float*)d_in[8];
    float* out = (float*)d_out;

    static bool attr_done = false;
    if (!attr_done) {
        cudaFuncSetAttribute(conv1_mma, cudaFuncAttributeMaxDynamicSharedMemorySize, 177152);
        cudaFuncSetAttribute(om_mma, cudaFuncAttributeMaxDynamicSharedMemorySize, 201728);
        cudaFuncSetAttribute(dcn_mma, cudaFuncAttributeMaxDynamicSharedMemorySize, 49152);
        attr_done = true;
    }

    int prep_total = PN0 + PN1 + PN2 + PN3 + PN4;
    prep_all<<<(prep_total + 255) / 256, 256>>>(ref, flow, conv1_w, om_w, dcn_w);
    transpose_kernel<<<(BAT * DG * HW + 255) / 256, 256>>>(nbr);
    warp_kernel<<<(BAT * HW + 255) / 256, 256>>>(flow);
    conv1_mma<<<dim3(256, BAT), 512, 177152>>>(conv1_b);
    om_mma<<<dim3(2, 256, BAT * 2), 512, 201728>>>(om_b, flow);
    dcn_mma<<<dim3(256, BAT), 256, 49152>>>(dcn_b, out);
}

// round 15
// speedup vs baseline: 2.9828x; 1.0270x over previous
#include <cuda_runtime.h>
#include <cuda_bf16.h>
#include <stdint.h>
#include <math.h>

#define WID 256
#define HGT 256
#define HW  65536
#define BAT 2
#define NF  64
#define DG  8
#define CST 424
#define RST 136
#define SINB 3392
// conv1 full-row tile constants
#define C1CST 808
#define C1RST 264
#define C1SINB 6464

// fp32 scratch (dcn path)
__device__ float d_nbr_t[BAT * DG * HW * 8];
__device__ float d_om[BAT * 216 * HW];
__device__ float d_wdph[36864];
__device__ float d_wdpl[36864];
// bf16 packed-pair activations (uint32 = 2 channels) hi/lo
__device__ unsigned int d_nwph[BAT * 32 * HW];
__device__ unsigned int d_nwpl[BAT * 32 * HW];
__device__ unsigned int d_refph[BAT * 32 * HW];
__device__ unsigned int d_refpl[BAT * 32 * HW];
__device__ unsigned int d_feaph[BAT * 32 * HW];
__device__ unsigned int d_feapl[BAT * 32 * HW];
__device__ unsigned int d_flwph[BAT * HW];
__device__ unsigned int d_flwpl[BAT * HW];
// bf16 packed weights (A-fragment layout)
__device__ unsigned int d_w1bh[36864];
__device__ unsigned int d_w1bl[36864];
__device__ unsigned int d_wobh[92160];
__device__ unsigned int d_wobl[92160];

__device__ __forceinline__ float rna(float x) {
    uint32_t u; asm("cvt.rna.tf32.f32 %0, %1;" : "=r"(u) : "f"(x));
    return __uint_as_float(u);
}
__device__ __forceinline__ float bf16f(float x) {
    return __bfloat162float(__float2bfloat16_rn(x));
}
__device__ __forceinline__ uint32_t pkbf(float a, float b) {
    uint32_t lo = (uint32_t)__bfloat16_as_ushort(__float2bfloat16_rn(a));
    uint32_t hi = (uint32_t)__bfloat16_as_ushort(__float2bfloat16_rn(b));
    return lo | (hi << 16);
}
__device__ __forceinline__ void mma16(float* c, const uint4& a, uint32_t b0, uint32_t b1) {
    asm volatile("mma.sync.aligned.m16n8k16.row.col.f32.bf16.bf16.f32 "
                 "{%0,%1,%2,%3},{%4,%5,%6,%7},{%8,%9},{%0,%1,%2,%3};"
                 : "+f"(c[0]), "+f"(c[1]), "+f"(c[2]), "+f"(c[3])
                 : "r"(a.x), "r"(a.y), "r"(a.z), "r"(a.w), "r"(b0), "r"(b1));
}
__device__ __forceinline__ void mma8t(float* c, const uint4& a, uint32_t b0, uint32_t b1) {
    asm volatile("mma.sync.aligned.m16n8k8.row.col.f32.tf32.tf32.f32 "
                 "{%0,%1,%2,%3},{%4,%5,%6,%7},{%8,%9},{%0,%1,%2,%3};"
                 : "+f"(c[0]), "+f"(c[1]), "+f"(c[2]), "+f"(c[3])
                 : "r"(a.x), "r"(a.y), "r"(a.z), "r"(a.w), "r"(b0), "r"(b1));
}
__device__ __forceinline__ void cpa16(uint32_t d, const void* s, bool ok) {
    int sz = ok ? 16 : 0;
    asm volatile("cp.async.cg.shared.global [%0], [%1], 16, %2;" :: "r"(d), "l"(s), "r"(sz) : "memory");
}
__device__ __forceinline__ void cpa4(uint32_t d, const void* s, bool ok) {
    int sz = ok ? 4 : 0;
    asm volatile("cp.async.ca.shared.global [%0], [%1], 4, %2;" :: "r"(d), "l"(s), "r"(sz) : "memory");
}
__device__ __forceinline__ void cpcommit() { asm volatile("cp.async.commit_group;" ::: "memory"); }
__device__ __forceinline__ void cpwait() { asm volatile("cp.async.wait_group 0;" ::: "memory"); }

// ---------------- fused prep ----------------
#define PN0 1048576
#define PN1 32768
#define PN2 36864
#define PN3 92160
#define PN4 9216
__global__ void prep_all(const float* __restrict__ ref, const float* __restrict__ flow,
                         const float* __restrict__ w1, const float* __restrict__ wom,
                         const float* __restrict__ wd) {
    int idx = blockIdx.x * blockDim.x + threadIdx.x;
    if (idx < PN0) {
        int row = idx / 16384;
        int p4 = idx - row * 16384;
        int b = row >> 5, c2 = row & 31;
        int pix = p4 * 4;
        float4 va = *(const float4*)(ref + (size_t)(b * 64 + 2 * c2) * HW + pix);
        float4 vb = *(const float4*)(ref + (size_t)(b * 64 + 2 * c2 + 1) * HW + pix);
        const float* ap = &va.x; const float* bp = &vb.x;
        uint4 wh, wl;
        uint32_t* whp = &wh.x; uint32_t* wlp = &wl.x;
#pragma unroll
        for (int j = 0; j < 4; j++) {
            float a = ap[j], c = bp[j];
            float ah = bf16f(a), ch = bf16f(c);
            whp[j] = pkbf(a, c);
            wlp[j] = pkbf(a - ah, c - ch);
        }
        ((uint4*)d_refph)[idx] = wh;
        ((uint4*)d_refpl)[idx] = wl;
        return;
    }
    idx -= PN0;
    if (idx < PN1) {
        int b = idx / 16384;
        int pix = (idx - b * 16384) * 4;
        float4 fx4 = *(const float4*)(flow + (size_t)(b * 2) * HW + pix);
        float4 fy4 = *(const float4*)(flow + (size_t)(b * 2 + 1) * HW + pix);
        const float* xp = &fx4.x; const float* yp = &fy4.x;
        uint4 wh, wl;
        uint32_t* whp = &wh.x; uint32_t* wlp = &wl.x;
#pragma unroll
        for (int j = 0; j < 4; j++) {
            float a = xp[j], c = yp[j];
            float ah = bf16f(a), ch = bf16f(c);
            whp[j] = pkbf(a, c);
            wlp[j] = pkbf(a - ah, c - ch);
        }
        ((uint4*)d_flwph)[idx] = wh;
        ((uint4*)d_flwpl)[idx] = wl;
        return;
    }
    idx -= PN1;
    if (idx < PN2) {
        int vi = idx & 3;
        int lane = (idx >> 2) & 31;
        int m = (idx >> 7) & 3;
        int tap = (idx >> 9) % 9;
        int chunk = idx / 4608;
        int gr = lane >> 2, tq = lane & 3;
        int oc = 16 * m + gr + (vi & 1) * 8;
        int kb = 16 * chunk + 2 * tq + ((vi >> 1) ? 8 : 0);
        float v0 = w1[(oc * 128 + kb) * 9 + tap];
        float v1 = w1[(oc * 128 + kb + 1) * 9 + tap];
        float h0 = bf16f(v0), h1 = bf16f(v1);
        d_w1bh[idx] = pkbf(v0, v1);
        d_w1bl[idx] = pkbf(v0 - h0, v1 - h1);
        return;
    }
    idx -= PN2;
    if (idx < PN3) {
        int cs = idx / 9216;
        int w = idx - cs * 9216;
        int slice = cs / 5, chunk = cs - slice * 5;
        int tap = w / 1024;
        int r2 = w - tap * 1024;
        int m = r2 >> 7;
        int lane = (r2 >> 2) & 31;
        int vi = r2 & 3;
        int gr = lane >> 2, tq = lane & 3;
        int oc = 128 * slice + 16 * m + gr + (vi & 1) * 8;
        int kb = 16 * chunk + 2 * tq + ((vi >> 1) ? 8 : 0);
        float v0 = 0.f, v1 = 0.f;
        if (oc < 216 && kb < 66) v0 = wom[(oc * 66 + kb) * 9 + tap];
        if (oc < 216 && kb + 1 < 66) v1 = wom[(oc * 66 + kb + 1) * 9 + tap];
        float h0 = bf16f(v0), h1 = bf16f(v1);
        d_wobh[idx] = pkbf(v0, v1);
        d_wobl[idx] = pkbf(v0 - h0, v1 - h1);
        return;
    }
    idx -= PN3;
    if (idx < PN4) {
        int g = idx / 1152, r = idx % 1152;
        int tap = r / 128, r2 = r & 127;
        int mt = r2 >> 5, lane = r2 & 31;
        int gr = lane >> 2, tq = lane & 3;
        float4 h, l; float* hp = &h.x; float* lp = &l.x;
#pragma unroll
        for (int vi = 0; vi < 4; vi++) {
            int oc = 16 * mt + gr + (vi & 1) * 8;
            int kc = tq + (vi >> 1) * 4;
            float v = wd[(oc * 64 + g * 8 + kc) * 9 + tap];
            float hv = rna(v); hp[vi] = hv; lp[vi] = rna(v - hv);
        }
        ((float4*)d_wdph)[idx] = h;
        ((float4*)d_wdpl)[idx] = l;
    }
}

// ---------------- transpose for dcn + warp ----------------
__global__ void transpose_kernel(const float* __restrict__ nbr) {
    int idx = blockIdx.x * blockDim.x + threadIdx.x;
    if (idx >= BAT * DG * HW) return;
    int bg = idx >> 16, p = idx & 65535;
    int b = bg >> 3, g = bg & 7;
    float v[8];
#pragma unroll
    for (int c = 0; c < 8; c++) v[c] = nbr[((b * NF + g * 8 + c) * HW) + p];
    float4* dst = (float4*)&d_nbr_t[(size_t)idx * 8];
    dst[0] = make_float4(v[0], v[1], v[2], v[3]);
    dst[1] = make_float4(v[4], v[5], v[6], v[7]);
}

// ---------------- warp (bilinear) -> packed bf16 hi/lo ----------------
__global__ void warp_kernel(const float* __restrict__ flow) {
    int idx = blockIdx.x * blockDim.x + threadIdx.x;
    if (idx >= BAT * HW) return;
    int b = idx >> 16, p = idx & 65535;
    int y = p >> 8, x = p & 255;
    float fx = flow[(b * 2 + 0) * HW + p];
    float fy = flow[(b * 2 + 1) * HW + p];
    float px = (float)x + fx, py = (float)y + fy;
    float x0f = floorf(px), y0f = floorf(py);
    int ix0 = (int)x0f, iy0 = (int)y0f;
    float wx = px - x0f, wy = py - y0f;
    bool vx0 = (unsigned)ix0 < WID, vx1 = (unsigned)(ix0 + 1) < WID;
    bool vy0 = (unsigned)iy0 < HGT, vy1 = (unsigned)(iy0 + 1) < HGT;
    float w00 = (vy0 && vx0) ? (1.f - wy) * (1.f - wx) : 0.f;
    float w01 = (vy0 && vx1) ? (1.f - wy) * wx : 0.f;
    float w10 = (vy1 && vx0) ? wy * (1.f - wx) : 0.f;
    float w11 = (vy1 && vx1) ? wy * wx : 0.f;
    int cx0 = min(max(ix0, 0), WID - 1), cx1 = min(max(ix0 + 1, 0), WID - 1);
    int cy0 = min(max(iy0, 0), HGT - 1), cy1 = min(max(iy0 + 1, 0), HGT - 1);
    size_t i00 = (size_t)(cy0 * WID + cx0) * 8;
    size_t i01 = (size_t)(cy0 * WID + cx1) * 8;
    size_t i10 = (size_t)(cy1 * WID + cx0) * 8;
    size_t i11 = (size_t)(cy1 * WID + cx1) * 8;

#pragma unroll 1
    for (int g = 0; g < 8; g++) {
        const float* gb = d_nbr_t + (size_t)(b * 8 + g) * HW * 8;
        float v[8];
#pragma unroll
        for (int half = 0; half < 2; half++) {
            float4 a00 = *(const float4*)(gb + i00 + 4 * half);
            float4 a01 = *(const float4*)(gb + i01 + 4 * half);
            float4 a10 = *(const float4*)(gb + i10 + 4 * half);
            float4 a11 = *(const float4*)(gb + i11 + 4 * half);
            v[4 * half + 0] = w00 * a00.x + w01 * a01.x + w10 * a10.x + w11 * a11.x;
            v[4 * half + 1] = w00 * a00.y + w01 * a01.y + w10 * a10.y + w11 * a11.y;
            v[4 * half + 2] = w00 * a00.z + w01 * a01.z + w10 * a10.z + w11 * a11.z;
            v[4 * half + 3] = w00 * a00.w + w01 * a01.w + w10 * a10.w + w11 * a11.w;
        }
#pragma unroll
        for (int cl = 0; cl < 4; cl++) {
            float a = v[2 * cl], c = v[2 * cl + 1];
            float ah = bf16f(a), ch = bf16f(c);
            size_t o = (size_t)(b * 32 + g * 4 + cl) * HW + p;
            d_nwph[o] = pkbf(a, c);
            d_nwpl[o] = pkbf(a - ah, c - ch);
        }
    }
}

// ---------------- conv1: bf16 k16, full-row, 2 m-blocks/warp ----------------
__global__ __launch_bounds__(512, 1)
void conv1_mma(const float* __restrict__ bias) {
    extern __shared__ unsigned int sm[];
    unsigned int* sInH = sm;
    unsigned int* sInL = sm + 12928;
    unsigned int* sWH  = sm + 25856;
    unsigned int* sWL  = sm + 35072;

    int tid = threadIdx.x;
    int warp = tid >> 5, lane = tid & 31;
    int g = warp & 7, h = warp >> 3;
    int gr = lane >> 2, tq = lane & 3;
    int y = blockIdx.x, b = blockIdx.y;

    float acc[4][2][4];
#pragma unroll
    for (int j = 0; j < 4; j++)
#pragma unroll
        for (int mi = 0; mi < 2; mi++)
#pragma unroll
            for (int k = 0; k < 4; k++) acc[j][mi][k] = 0.f;

    auto stage = [&](int chunk, int buf) {
        for (int i = tid; i < 3072; i += 512) {
            int pr = i >= 1536;
            int ii = pr ? i - 1536 : i;
            int c2l = ii / 192, rr = ii - c2l * 192;
            int r = rr >> 6, k = rr & 63;
            int row = chunk * 8 + c2l;
            int gy = y + r - 1;
            bool ok = (unsigned)gy < HGT;
            int gyc = ok ? gy : 0;
            const unsigned int* arr = (row < 32) ? (pr ? d_nwpl : d_nwph) : (pr ? d_refpl : d_refph);
            int rl = (row < 32) ? row : row - 32;
            const unsigned int* src = arr + (size_t)(b * 32 + rl) * HW + gyc * 256 + 4 * k;
            unsigned int* db = (pr ? sInL : sInH) + buf * C1SINB;
            cpa16((uint32_t)__cvta_generic_to_shared(db + c2l * C1CST + r * C1RST + 4 + 4 * k), src, ok);
        }
        for (int i = tid; i < 96; i += 512) {
            int pr = i >= 48;
            int ii = pr ? i - 48 : i;
            int c2l = ii / 6, rr = ii - c2l * 6;
            int r = rr >> 1, side = rr & 1;
            int row = chunk * 8 + c2l;
            int gy = y + r - 1;
            int gx = side ? 256 : -1;
            bool ok = ((unsigned)gy < HGT) && ((unsigned)gx < WID);
            int gyc = ((unsigned)gy < HGT) ? gy : 0;
            int gxc = ((unsigned)gx < WID) ? gx : 0;
            const unsigned int* arr = (row < 32) ? (pr ? d_nwpl : d_nwph) : (pr ? d_refpl : d_refph);
            int rl = (row < 32) ? row : row - 32;
            const unsigned int* src = arr + (size_t)(b * 32 + rl) * HW + gyc * 256 + gxc;
            unsigned int* db = (pr ? sInL : sInH) + buf * C1SINB;
            cpa4((uint32_t)__cvta_generic_to_shared(db + c2l * C1CST + r * C1RST + (side ? 260 : 3)), src, ok);
        }
        for (int i = tid; i < 2304; i += 512) {
            int pr = i >= 1152;
            int ii = pr ? i - 1152 : i;
            const unsigned int* src = (pr ? d_w1bl : d_w1bh) + chunk * 4608 + ii * 4;
            unsigned int* db = (pr ? sWL : sWH) + buf * 4608;
            cpa16((uint32_t)__cvta_generic_to_shared(db + ii * 4), src, true);
        }
        cpcommit();
    };

    stage(0, 0);
    int bbase = tq * C1CST + 32 * g + gr + 3;
    for (int it = 0; it < 8; it++) {
        int buf = it & 1;
        cpwait();
        __syncthreads();
        if (it + 1 < 8) stage(it + 1, buf ^ 1);

        const unsigned int* siH = sInH + buf * C1SINB;
        const unsigned int* siL = sInL + buf * C1SINB;
        const unsigned int* swH = sWH + buf * 4608;
        const unsigned int* swL = sWL + buf * 4608;
#pragma unroll
        for (int dy = 0; dy < 3; dy++) {
#pragma unroll
            for (int dx = 0; dx < 3; dx++) {
                int tap = dy * 3 + dx;
                int wi = ((tap * 4 + 2 * h) * 32 + lane) * 4;
                uint4 Ah0 = *(const uint4*)(swH + wi);
                uint4 Ah1 = *(const uint4*)(swH + wi + 128);
                uint4 Al0 = *(const uint4*)(swL + wi);
                uint4 Al1 = *(const uint4*)(swL + wi + 128);
                int fb = bbase + dy * C1RST + dx;
#pragma unroll
                for (int j = 0; j < 4; j++) {
                    int fi = fb + 8 * j;
                    uint32_t bh0 = siH[fi];
                    uint32_t bh1 = siH[fi + 4 * C1CST];
                    uint32_t bl0 = siL[fi];
                    uint32_t bl1 = siL[fi + 4 * C1CST];
                    mma16(acc[j][0], Ah0, bh0, bh1);
                    mma16(acc[j][0], Ah0, bl0, bl1);
                    mma16(acc[j][0], Al0, bh0, bh1);
                    mma16(acc[j][1], Ah1, bh0, bh1);
                    mma16(acc[j][1], Ah1, bl0, bl1);
                    mma16(acc[j][1], Al1, bh0, bh1);
                }
            }
        }
        __syncthreads();
    }

#pragma unroll
    for (int j = 0; j < 4; j++) {
        int x = 32 * g + 8 * j + 2 * tq;
        int pA = y * 256 + x;
#pragma unroll
        for (int mi = 0; mi < 2; mi++) {
            int m = 2 * h + mi;
#pragma unroll
            for (int kk = 0; kk < 4; kk++) {
                int oc = 16 * m + gr + (kk >= 2 ? 8 : 0);
                int p = pA + (kk & 1);
                float v = acc[j][mi][kk] + bias[oc];
                v = fmaxf(v, 0.f);
                float vp = __shfl_xor_sync(0xffffffffu, v, 4);
                if ((lane & 4) == 0) {
                    float vh = bf16f(v), vph = bf16f(vp);
                    int c2 = 8 * m + (kk >= 2 ? 4 : 0) + (gr >> 1);
                    size_t o = (size_t)(b * 32 + c2) * HW + p;
                    d_feaph[o] = pkbf(v, vp);
                    d_feapl[o] = pkbf(v - vh, vp - vph);
                }
            }
        }
    }
}

// ---------------- om via bf16 k16 MMA (3-term): 66->216, fused epilogue -----
// slice 1 only covers oc 128..215 -> warps h==3 (m-blocks 6,7 = oc 224..255)
// are fully out of range: skip their staging and compute entirely.
__global__ __launch_bounds__(512, 1)
void om_mma(const float* __restrict__ bias, const float* __restrict__ flow) {
    extern __shared__ unsigned int sm[];
    unsigned int* sInH = sm;
    unsigned int* sInL = sm + 6784;
    unsigned int* sWH  = sm + 13568;
    unsigned int* sWL  = sm + 32000;

    int tid = threadIdx.x;
    int warp = tid >> 5, lane = tid & 31;
    int g = warp & 3, h = warp >> 2;
    int gr = lane >> 2, tq = lane & 3;
    int bz = blockIdx.z;
    int b = bz >> 1, slice = bz & 1;
    int y = blockIdx.y, x0 = blockIdx.x * 128;
    bool active = !(slice == 1 && h == 3);

    float acc[4][2][4];
#pragma unroll
    for (int j = 0; j < 4; j++)
#pragma unroll
        for (int mi = 0; mi < 2; mi++)
#pragma unroll
            for (int k = 0; k < 4; k++) acc[j][mi][k] = 0.f;

    auto stage = [&](int chunk, int buf) {
        for (int i = tid; i < 1536; i += 512) {
            int pr = i >= 768;
            int ii = pr ? i - 768 : i;
            int c2l = ii / 96, rr = ii - c2l * 96;
            int r = rr >> 5, k = rr & 31;
            int row = chunk * 8 + c2l;
            int gy = y + r - 1;
            bool ok = ((unsigned)gy < HGT) && (row <= 32);
            int gyc = ((unsigned)gy < HGT) ? gy : 0;
            const unsigned int* arr;
            size_t base;
            if (row < 32) { arr = pr ? d_feapl : d_feaph; base = (size_t)(b * 32 + row) * HW; }
            else { arr = pr ? d_flwpl : d_flwph; base = (size_t)b * HW; }
            const unsigned int* src = arr + base + gyc * 256 + x0 + 4 * k;
            unsigned int* db = (pr ? sInL : sInH) + buf * SINB;
            cpa16((uint32_t)__cvta_generic_to_shared(db + c2l * CST + r * RST + 4 + 4 * k), src, ok);
        }
        for (int i = tid; i < 96; i += 512) {
            int pr = i >= 48;
            int ii = pr ? i - 48 : i;
            int c2l = ii / 6, rr = ii - c2l * 6;
            int r = rr >> 1, side = rr & 1;
            int row = chunk * 8 + c2l;
            int gy = y + r - 1;
            int gx = side ? x0 + 128 : x0 - 1;
            bool ok = ((unsigned)gy < HGT) && ((unsigned)gx < WID) && (row <= 32);
            int gyc = ((unsigned)gy < HGT) ? gy : 0;
            int gxc = ((unsigned)gx < WID) ? gx : 0;
            const unsigned int* arr;
            size_t base;
            if (row < 32) { arr = pr ? d_feapl : d_feaph; base = (size_t)(b * 32 + row) * HW; }
            else { arr = pr ? d_flwpl : d_flwph; base = (size_t)b * HW; }
            const unsigned int* src = arr + base + gyc * 256 + gxc;
            unsigned int* db = (pr ? sInL : sInH) + buf * SINB;
            cpa4((uint32_t)__cvta_generic_to_shared(db + c2l * CST + r * RST + (side ? 132 : 3)), src, ok);
        }
        for (int i = tid; i < 4608; i += 512) {
            int pr = i >= 2304;
            int ii = pr ? i - 2304 : i;
            if (slice == 1 && ((ii >> 5) & 7) >= 6) continue;
            const unsigned int* src = (pr ? d_wobl : d_wobh) + (slice * 5 + chunk) * 9216 + ii * 4;
            unsigned int* db = (pr ? sWL : sWH) + buf * 9216;
            cpa16((uint32_t)__cvta_generic_to_shared(db + ii * 4), src, true);
        }
        cpcommit();
    };

    stage(0, 0);
    int bbase = tq * CST + 32 * g + gr + 3;
    for (int it = 0; it < 5; it++) {
        int buf = it & 1;
        cpwait();
        __syncthreads();
        if (it + 1 < 5) stage(it + 1, buf ^ 1);

        if (active) {
            const unsigned int* siH = sInH + buf * SINB;
            const unsigned int* siL = sInL + buf * SINB;
            const unsigned int* swH = sWH + buf * 9216;
            const unsigned int* swL = sWL + buf * 9216;
#pragma unroll
            for (int dy = 0; dy < 3; dy++) {
#pragma unroll
                for (int dx = 0; dx < 3; dx++) {
                    int tap = dy * 3 + dx;
                    int wi = ((tap * 8 + 2 * h) * 32 + lane) * 4;
                    uint4 Ah0 = *(const uint4*)(swH + wi);
                    uint4 Ah1 = *(const uint4*)(swH + wi + 128);
                    uint4 Al0 = *(const uint4*)(swL + wi);
                    uint4 Al1 = *(const uint4*)(swL + wi + 128);
                    int fb = bbase + dy * RST + dx;
#pragma unroll
                    for (int j = 0; j < 4; j++) {
                        int fi = fb + 8 * j;
                        uint32_t bh0 = siH[fi];
                        uint32_t bh1 = siH[fi + 4 * CST];
                        uint32_t bl0 = siL[fi];
                        uint32_t bl1 = siL[fi + 4 * CST];
                        mma16(acc[j][0], Ah0, bh0, bh1);
                        mma16(acc[j][0], Ah0, bl0, bl1);
                        mma16(acc[j][0], Al0, bh0, bh1);
                        mma16(acc[j][1], Ah1, bh0, bh1);
                        mma16(acc[j][1], Ah1, bl0, bl1);
                        mma16(acc[j][1], Al1, bh0, bh1);
                    }
                }
            }
        }
        __syncthreads();
    }

    if (active) {
        int ocb = 128 * slice;
#pragma unroll
        for (int j = 0; j < 4; j++) {
            int x = x0 + 32 * g + 8 * j + 2 * tq;
            int pA = y * 256 + x;
#pragma unroll
            for (int mi = 0; mi < 2; mi++) {
                int chA = ocb + 16 * (2 * h + mi) + gr;
#pragma unroll
                for (int k = 0; k < 4; k++) {
                    int ch = chA + (k >= 2 ? 8 : 0);
                    if (ch >= 216) continue;
                    int p = pA + (k & 1);
                    float v = acc[j][mi][k] + bias[ch];
                    if (ch < 144) {
                        v += (gr & 1) ? flow[(b * 2 + 0) * HW + p]
                                      : flow[(b * 2 + 1) * HW + p];
                    } else {
                        v = 1.f / (1.f + expf(-v));
                    }
                    d_om[(size_t)(b * 216 + ch) * HW + p] = v;
                }
            }
        }
    }
}

// ---------------- dcn via tf32 MMA, software-pipelined gathers ----------------
__device__ __forceinline__ void dcn_gather(const float* __restrict__ gbase,
                                           int x, int y, int ky, int kx,
                                           float dy, float dx, float m, float* vm) {
    float spy = (float)(y - 1 + ky) + dy;
    float spx = (float)(x - 1 + kx) + dx;
    float y0f = floorf(spy), x0f = floorf(spx);
    int iy0 = (int)y0f, ix0 = (int)x0f;
    float wy = spy - y0f, wx = spx - x0f;
    float v[8];
#pragma unroll
    for (int c = 0; c < 8; c++) v[c] = 0.f;
    float wts[4] = {(1.f - wy) * (1.f - wx), (1.f - wy) * wx, wy * (1.f - wx), wy * wx};
    int ys[4] = {iy0, iy0, iy0 + 1, iy0 + 1};
    int xs[4] = {ix0, ix0 + 1, ix0, ix0 + 1};
#pragma unroll
    for (int t = 0; t < 4; t++) {
        int yi = ys[t], xi = xs[t];
        if ((unsigned)yi < HGT && (unsigned)xi < WID) {
            const float4* q = (const float4*)(gbase + (size_t)(yi * WID + xi) * 8);
            float4 a = q[0];
            float4 bb = q[1];
            float wt = wts[t];
            v[0] += wt * a.x;  v[1] += wt * a.y;  v[2] += wt * a.z;  v[3] += wt * a.w;
            v[4] += wt * bb.x; v[5] += wt * bb.y; v[6] += wt * bb.z; v[7] += wt * bb.w;
        }
    }
#pragma unroll
    for (int c = 0; c < 8; c++) vm[c] = v[c] * m;
}

__global__ __launch_bounds__(256, 2)
void dcn_mma(const float* __restrict__ dcnb, float* __restrict__ out) {
    extern __shared__ float smf[];
    float* sWH = smf;
    float* sWL = smf + 4608;
    float* sBH = smf + 9216;

    int tid = threadIdx.x;
    int warp = tid >> 5, lane = tid & 31;
    int gr = lane >> 2, tq = lane & 3;
    int y = blockIdx.x, b = blockIdx.y;
    int x = warp * 32 + lane;
    int p = y * 256 + x;

    float acc[4][4][4];
#pragma unroll
    for (int mt = 0; mt < 4; mt++)
#pragma unroll
        for (int nt = 0; nt < 4; nt++)
#pragma unroll
            for (int r = 0; r < 4; r++) acc[mt][nt][r] = 0.f;

    float* myBH = sBH + warp * 320;

    for (int g = 0; g < 8; g++) {
        const float* omb = d_om + (size_t)b * 216 * HW;
        float ody[9], odx[9], omk[9];
#pragma unroll
        for (int k = 0; k < 9; k++) {
            int ch = g * 9 + k;
            ody[k] = omb[(ch * 2) * HW + p];
            odx[k] = omb[(ch * 2 + 1) * HW + p];
            omk[k] = omb[(144 + ch) * HW + p];
        }

        __syncthreads();
        for (int i = tid; i < 2304; i += 256) {
            int pr = i >= 1152;
            int ii = pr ? i - 1152 : i;
            const float* src = (pr ? d_wdpl : d_wdph) + g * 4608 + ii * 4;
            float* db = pr ? sWL : sWH;
            cpa16((uint32_t)__cvta_generic_to_shared(db + ii * 4), src, true);
        }
        cpcommit();
        cpwait();
        __syncthreads();

        const float* gbase = d_nbr_t + (size_t)(b * 8 + g) * HW * 8;

        float vm[8];
        dcn_gather(gbase, x, y, 0, 0, ody[0], odx[0], omk[0], vm);

#pragma unroll 1
        for (int k = 0; k < 9; k++) {
#pragma unroll
            for (int c = 0; c < 8; c++) {
                myBH[c * 40 + lane] = rna(vm[c]);
            }
            __syncwarp();

            float vmn[8];
            if (k < 8) {
                int kn = k + 1;
                dcn_gather(gbase, x, y, kn / 3, kn - (kn / 3) * 3,
                           ody[kn], odx[kn], omk[kn], vmn);
            }

            uint32_t b0[4], b1[4];
#pragma unroll
            for (int nt = 0; nt < 4; nt++) {
                int bi = tq * 40 + nt * 8 + gr;
                b0[nt] = __float_as_uint(myBH[bi]);
                b1[nt] = __float_as_uint(myBH[bi + 160]);
            }
#pragma unroll
            for (int mt = 0; mt < 4; mt++) {
                int wi = ((k * 4 + mt) * 32 + lane) * 4;
                uint4 Ah = *(const uint4*)(sWH + wi);
                uint4 Al = *(const uint4*)(sWL + wi);
#pragma unroll
                for (int nt = 0; nt < 4; nt++) {
                    mma8t(acc[mt][nt], Ah, b0[nt], b1[nt]);
                    mma8t(acc[mt][nt], Al, b0[nt], b1[nt]);
                }
            }
            __syncwarp();
#pragma unroll
            for (int c = 0; c < 8; c++) vm[c] = vmn[c];
        }
    }

#pragma unroll
    for (int mt = 0; mt < 4; mt++)
#pragma unroll
        for (int nt = 0; nt < 4; nt++) {
            int xo = warp * 32 + nt * 8 + 2 * tq;
            int pb = y * 256 + xo;
#pragma unroll
            for (int r = 0; r < 4; r++) {
                int oc = 16 * mt + gr + (r >= 2 ? 8 : 0);
                int pp = pb + (r & 1);
                out[(b * 64 + oc) * HW + pp] = acc[mt][nt][r] + dcnb[oc];
            }
        }
}

// ---------------- launch ----------------
extern "C" void kernel_launch(void* const* d_in, const int* in_sizes, int n_in,
                              void* d_out, int out_size) {
    const float* nbr = (const float*)d_in[0];
    const float* ref = (const float*)d_in[1];
    const float* flow = (const float*)d_in[2];
    const float* conv1_w = (const float*)d_in[3];
    const float* conv1_b = (const float*)d_in[4];
    const float* om_w = (const float*)d_in[5];
    const float* om_b = (const float*)d_in[6];
    const float* dcn_w = (const float*)d_in[7];
    const float* dcn_b = (const float*)d_in[8];
    float* out = (float*)d_out;

    static bool attr_done = false;
    if (!attr_done) {
        cudaFuncSetAttribute(conv1_mma, cudaFuncAttributeMaxDynamicSharedMemorySize, 177152);
        cudaFuncSetAttribute(om_mma, cudaFuncAttributeMaxDynamicSharedMemorySize, 201728);
        cudaFuncSetAttribute(dcn_mma, cudaFuncAttributeMaxDynamicSharedMemorySize, 49152);
        attr_done = true;
    }

    int prep_total = PN0 + PN1 + PN2 + PN3 + PN4;
    prep_all<<<(prep_total + 255) / 256, 256>>>(ref, flow, conv1_w, om_w, dcn_w);
    transpose_kernel<<<(BAT * DG * HW + 255) / 256, 256>>>(nbr);
    warp_kernel<<<(BAT * HW + 255) / 256, 256>>>(flow);
    conv1_mma<<<dim3(256, BAT), 512, 177152>>>(conv1_b);
    om_mma<<<dim3(2, 256, BAT * 2), 512, 201728>>>(om_b, flow);
    dcn_mma<<<dim3(256, BAT), 256, 49152>>>(dcn_b, out);
}